// round 2
// baseline (speedup 1.0000x reference)
#include <cuda_runtime.h>
#include <math.h>

constexpr int Bb   = 64;      // batch
constexpr int Tt   = 12;      // encoder steps
constexpr int Nn   = 1024;    // nodes
constexpr int Ee   = 10;      // embedding dim
constexpr int Hor  = 12;      // decoder horizon
constexpr int CD   = 66;      // unified per-batch feature width [x|go, 0|ycov, h(64)]
constexpr int FP   = 208;     // padded feature width (3*66=198 -> 208)
constexpr int ROWS = Nn * Bb; // 65536
constexpr int NN2  = Nn * Nn;

// ---------------- scratch (device globals; no allocations allowed) ----------
__device__ __align__(128) float g_SS_enc[2 * NN2];     // [S ; S2] encoder
__device__ __align__(128) float g_SS_dec[2 * NN2];     // [S ; S2] decoder
__device__ __align__(128) float g_Xin[Nn * Bb * CD];   // [n, b*66+c]
__device__ __align__(128) float g_F[(size_t)ROWS * FP];// [(n*64+b), 208]
__device__ __align__(128) float g_R[(size_t)ROWS * 64];// r gate (post-sigmoid)
__device__ __align__(128) float g_h[(size_t)ROWS * 64];// state [n*64+b, h]
__device__ __align__(128) float g_go[ROWS];
__device__ __align__(128) float g_demb[Nn * Bb * Ee];  // [1024, 640]
__device__ __align__(128) float g_dembT[Bb * Ee * Nn]; // [640, 1024]
__device__ __align__(128) float g_embpad[Nn * 16];
__device__ __align__(128) float g_embpadT[16 * Nn];
__device__ __align__(128) float g_Wg_enc[FP * 128];
__device__ __align__(128) float g_Wu_enc[FP * 64];
__device__ __align__(128) float g_Wg_dec[FP * 128];
__device__ __align__(128) float g_Wu_dec[FP * 64];

__device__ __forceinline__ float sigmoidf_(float x) { return 1.0f / (1.0f + expf(-x)); }

// ---------------- SGEMM: C = A(MxK) @ B(KxN), row-major, double-buffered ----
// BM=128, BK=16, 256 threads, microtile 8 x (BN/16).
// MODE 0: plain row-major store into C
// MODE 1: diffusion scatter into g_F: row m -> (kk=m>>10, n=m&1023),
//         col -> (b=col/66, c=col%66); F[(n*64+b)*208 + (kk+1)*66 + c]
// MODE 3: gate MLP fused epilogue (BN=128): z=sigmoid(+bias[0:64]) -> z*h into
//         g_Xin/g_F state slots; r=sigmoid(+bias[64:128]) -> g_R
// MODE 4: update MLP fused epilogue (BN=64): hc=tanh(+bias);
//         g_h = r*g_h + (1-r)*hc
// Requires M%128==0, N%BN==0, K%16==0.
template <int BN, int MODE>
__global__ void __launch_bounds__(256) sgemm(
    const float* __restrict__ A, const float* __restrict__ B,
    float* __restrict__ C, int M, int N, int K,
    const float* __restrict__ bias)
{
    constexpr int BM = 128, BK = 16, TN = BN / 16;
    __shared__ __align__(16) float As[2][BK][BM];
    __shared__ __align__(16) float Bs[2][BK][BN];

    const int tid = threadIdx.x;
    const int tx = tid & 15;
    const int ty = tid >> 4;
    const int m0 = blockIdx.y * BM;
    const int n0 = blockIdx.x * BN;

    const int arow = tid >> 2;          // 0..63 (+64 second)
    const int acol = (tid & 3) * 4;     // 0,4,8,12
    const int brow = tid >> 4;          // 0..15
    const int bcol = (tid & 15) * 4;    // 0..60

    const float* Ap = A + (size_t)(m0 + arow) * K + acol;
    const float* Ap2 = Ap + (size_t)64 * K;
    const float* Bp = B + (size_t)brow * N + n0 + bcol;

    float acc[8][TN];
#pragma unroll
    for (int i = 0; i < 8; i++)
#pragma unroll
        for (int j = 0; j < TN; j++) acc[i][j] = 0.0f;

    // prologue: tile 0 -> buf 0
    float4 a0 = *reinterpret_cast<const float4*>(Ap);
    float4 a1 = *reinterpret_cast<const float4*>(Ap2);
    float4 b0 = *reinterpret_cast<const float4*>(Bp);
    float4 b1;
    if (BN == 128) b1 = *reinterpret_cast<const float4*>(Bp + 64);

    As[0][acol + 0][arow] = a0.x; As[0][acol + 1][arow] = a0.y;
    As[0][acol + 2][arow] = a0.z; As[0][acol + 3][arow] = a0.w;
    As[0][acol + 0][arow + 64] = a1.x; As[0][acol + 1][arow + 64] = a1.y;
    As[0][acol + 2][arow + 64] = a1.z; As[0][acol + 3][arow + 64] = a1.w;
    *reinterpret_cast<float4*>(&Bs[0][brow][bcol]) = b0;
    if (BN == 128) *reinterpret_cast<float4*>(&Bs[0][brow][bcol + 64]) = b1;
    __syncthreads();

    const int KT = K / BK;
    int cur = 0;
    for (int kt = 0; kt < KT; kt++) {
        if (kt + 1 < KT) {
            const float* An = Ap + (kt + 1) * BK;
            a0 = *reinterpret_cast<const float4*>(An);
            a1 = *reinterpret_cast<const float4*>(An + (size_t)64 * K);
            const float* Bn = Bp + (size_t)(kt + 1) * BK * N;
            b0 = *reinterpret_cast<const float4*>(Bn);
            if (BN == 128) b1 = *reinterpret_cast<const float4*>(Bn + 64);
        }
#pragma unroll
        for (int k = 0; k < BK; k++) {
            float af[8], bf[TN];
            *reinterpret_cast<float4*>(&af[0]) =
                *reinterpret_cast<const float4*>(&As[cur][k][ty * 8]);
            *reinterpret_cast<float4*>(&af[4]) =
                *reinterpret_cast<const float4*>(&As[cur][k][ty * 8 + 4]);
#pragma unroll
            for (int j = 0; j < TN; j += 4)
                *reinterpret_cast<float4*>(&bf[j]) =
                    *reinterpret_cast<const float4*>(&Bs[cur][k][tx * TN + j]);
#pragma unroll
            for (int i = 0; i < 8; i++)
#pragma unroll
                for (int j = 0; j < TN; j++)
                    acc[i][j] = fmaf(af[i], bf[j], acc[i][j]);
        }
        if (kt + 1 < KT) {
            int nxt = cur ^ 1;
            As[nxt][acol + 0][arow] = a0.x; As[nxt][acol + 1][arow] = a0.y;
            As[nxt][acol + 2][arow] = a0.z; As[nxt][acol + 3][arow] = a0.w;
            As[nxt][acol + 0][arow + 64] = a1.x; As[nxt][acol + 1][arow + 64] = a1.y;
            As[nxt][acol + 2][arow + 64] = a1.z; As[nxt][acol + 3][arow + 64] = a1.w;
            *reinterpret_cast<float4*>(&Bs[nxt][brow][bcol]) = b0;
            if (BN == 128) *reinterpret_cast<float4*>(&Bs[nxt][brow][bcol + 64]) = b1;
            __syncthreads();
            cur = nxt;
        }
    }

    if (MODE == 0) {
#pragma unroll
        for (int i = 0; i < 8; i++) {
            float* Crow = C + (size_t)(m0 + ty * 8 + i) * N + n0 + tx * TN;
#pragma unroll
            for (int j = 0; j < TN; j += 4) {
                float4 v = make_float4(acc[i][j], acc[i][j + 1], acc[i][j + 2], acc[i][j + 3]);
                *reinterpret_cast<float4*>(Crow + j) = v;
            }
        }
    } else if (MODE == 1) {
#pragma unroll
        for (int i = 0; i < 8; i++) {
            int m = m0 + ty * 8 + i;
            int kk = m >> 10;
            int n = m & 1023;
#pragma unroll
            for (int j = 0; j < TN; j++) {
                int col = n0 + tx * TN + j;
                int b = col / CD;
                int c = col - b * CD;
                g_F[(size_t)((n << 6) + b) * FP + (kk + 1) * CD + c] = acc[i][j];
            }
        }
    } else if (MODE == 3) {
#pragma unroll
        for (int i = 0; i < 8; i++) {
            int id = m0 + ty * 8 + i;
            int n = id >> 6, b = id & 63;
#pragma unroll
            for (int j = 0; j < TN; j++) {
                int col = tx * TN + j;   // n0 == 0
                float v = sigmoidf_(acc[i][j] + bias[col]);
                if (col < 64) {
                    float zh = v * g_h[(size_t)id * 64 + col];
                    g_Xin[(size_t)n * (Bb * CD) + b * CD + 2 + col] = zh;
                    g_F[(size_t)id * FP + 2 + col] = zh;
                } else {
                    g_R[(size_t)id * 64 + (col - 64)] = v;
                }
            }
        }
    } else if (MODE == 4) {
#pragma unroll
        for (int i = 0; i < 8; i++) {
            int id = m0 + ty * 8 + i;
#pragma unroll
            for (int j = 0; j < TN; j++) {
                int col = tx * TN + j;   // n0 == 0
                float hc = tanhf(acc[i][j] + bias[col]);
                size_t o = (size_t)id * 64 + col;
                float r = g_R[o];
                float h = g_h[o];
                g_h[o] = r * h + (1.0f - r) * hc;
            }
        }
    }
}

// ---------------- small helper kernels --------------------------------------
__global__ void k_zero(float* p, size_t n) {
    size_t i = (size_t)blockIdx.x * blockDim.x + threadIdx.x;
    if (i < n) p[i] = 0.0f;
}

__global__ void k_pad_emb(const float* __restrict__ emb) {
    int idx = blockIdx.x * blockDim.x + threadIdx.x;
    if (idx >= Nn * 16) return;
    int n = idx >> 4, j = idx & 15;
    g_embpad[idx] = (j < Ee) ? emb[n * Ee + j] : 0.0f;
}

__global__ void k_transpose(const float* __restrict__ in, float* __restrict__ out,
                            int R, int C) {
    int idx = blockIdx.x * blockDim.x + threadIdx.x;
    if (idx >= R * C) return;
    int r = idx / C, c = idx - r * C;
    out[c * R + r] = in[idx];
}

// pad/remap weights to FP(208)-row layout with unified 66-wide feature blocks
template <bool ENC>
__global__ void k_pad_w(const float* __restrict__ src, float* __restrict__ dst,
                        int ncols) {
    int idx = blockIdx.x * blockDim.x + threadIdx.x;
    if (idx >= FP * ncols) return;
    int r = idx / ncols, j = idx - r * ncols;
    float v = 0.0f;
    if (r < 198) {
        int k = r / CD, c = r - k * CD;
        if (ENC) {
            if (c == 0) v = src[(k * 65) * ncols + j];
            else if (c >= 2) v = src[(k * 65 + c - 1) * ncols + j];
        } else {
            v = src[r * ncols + j];
        }
    }
    dst[idx] = v;
}

// softmax(relu(row)) over 1024 cols, one block (256 thr) per row, in-place
__global__ void k_relu_softmax(float* __restrict__ S) {
    int row = blockIdx.x;
    float* p = S + (size_t)row * Nn;
    int t = threadIdx.x;
    float v[4];
#pragma unroll
    for (int i = 0; i < 4; i++) {
        float x = p[t + i * 256];
        v[i] = x > 0.0f ? x : 0.0f;
    }
    __shared__ float red[256];
    float m = fmaxf(fmaxf(v[0], v[1]), fmaxf(v[2], v[3]));
    red[t] = m;
    __syncthreads();
    for (int s = 128; s > 0; s >>= 1) {
        if (t < s) red[t] = fmaxf(red[t], red[t + s]);
        __syncthreads();
    }
    m = red[0];
    __syncthreads();
    float e[4], sum = 0.0f;
#pragma unroll
    for (int i = 0; i < 4; i++) {
        e[i] = expf(v[i] - m);
        sum += e[i];
    }
    red[t] = sum;
    __syncthreads();
    for (int s = 128; s > 0; s >>= 1) {
        if (t < s) red[t] += red[t + s];
        __syncthreads();
    }
    float inv = 1.0f / red[0];
#pragma unroll
    for (int i = 0; i < 4; i++) p[t + i * 256] = e[i] * inv;
}

// P := 2*P - I  (in place, [1024,1024])
__global__ void k_cheb(float* __restrict__ P) {
    int idx = blockIdx.x * blockDim.x + threadIdx.x;
    if (idx >= NN2) return;
    int r = idx >> 10, c = idx & 1023;
    P[idx] = 2.0f * P[idx] - (r == c ? 1.0f : 0.0f);
}

// encoder xin = [x_t, 0, h] -> Xin [n, b*66+c] and F cols 0..65
__global__ void k_build_xin_enc(const float* __restrict__ x, int t) {
    int idx = blockIdx.x * blockDim.x + threadIdx.x;
    if (idx >= ROWS * 64) return;
    int id = idx >> 6, i = idx & 63;
    int n = id >> 6, b = id & 63;
    float hv = g_h[idx];
    g_Xin[(size_t)n * (Bb * CD) + b * CD + 2 + i] = hv;
    g_F[(size_t)id * FP + 2 + i] = hv;
    if (i == 0) {
        float xv = x[((size_t)b * Tt + t) * Nn + n];
        g_Xin[(size_t)n * (Bb * CD) + b * CD + 0] = xv;
        g_Xin[(size_t)n * (Bb * CD) + b * CD + 1] = 0.0f;
        g_F[(size_t)id * FP] = xv;   // F col 1 stays zero from initial zeroing
    }
}

// decoder xin = [go, ycov_t, h]
__global__ void k_build_xin_dec(const float* __restrict__ ycov, int t) {
    int idx = blockIdx.x * blockDim.x + threadIdx.x;
    if (idx >= ROWS * 64) return;
    int id = idx >> 6, i = idx & 63;
    int n = id >> 6, b = id & 63;
    float hv = g_h[idx];
    g_Xin[(size_t)n * (Bb * CD) + b * CD + 2 + i] = hv;
    g_F[(size_t)id * FP + 2 + i] = hv;
    if (i == 0) {
        float gv = g_go[id];
        float yv = ycov[((size_t)b * Hor + t) * Nn + n];
        g_Xin[(size_t)n * (Bb * CD) + b * CD + 0] = gv;
        g_Xin[(size_t)n * (Bb * CD) + b * CD + 1] = yv;
        g_F[(size_t)id * FP + 0] = gv;
        g_F[(size_t)id * FP + 1] = yv;
    }
}

// dec_emb = h @ FC_E  -> g_demb [1024, 64*10]
__global__ void k_demb(const float* __restrict__ fce) {
    int idx = blockIdx.x * blockDim.x + threadIdx.x;
    if (idx >= ROWS * Ee) return;
    int id = idx / Ee, e = idx - id * Ee;
    const float* hr = g_h + (size_t)id * 64;
    float s = 0.0f;
#pragma unroll
    for (int h = 0; h < 64; h++) s = fmaf(hr[h], fce[h * Ee + e], s);
    g_demb[idx] = s;
}

__global__ void k_init_go(const float* __restrict__ x) {
    int id = blockIdx.x * blockDim.x + threadIdx.x;
    if (id >= ROWS) return;
    int n = id >> 6, b = id & 63;
    g_go[id] = x[((size_t)b * Tt + (Tt - 1)) * Nn + n];
}

// go = h @ proj_w + pb ; write output[b, t, n]
__global__ void k_proj_out(const float* __restrict__ pw, const float* __restrict__ pb,
                           float* __restrict__ out, int t) {
    int id = blockIdx.x * blockDim.x + threadIdx.x;
    if (id >= ROWS) return;
    int n = id >> 6, b = id & 63;
    const float* hr = g_h + (size_t)id * 64;
    float s = pb[0];
#pragma unroll
    for (int i = 0; i < 64; i++) s = fmaf(hr[i], pw[i], s);
    g_go[id] = s;
    out[((size_t)b * Hor + t) * Nn + n] = s;
}

// ---------------- orchestration ---------------------------------------------
extern "C" void kernel_launch(void* const* d_in, const int* in_sizes, int n_in,
                              void* d_out, int out_size) {
    const float* x    = (const float*)d_in[0];
    const float* ycov = (const float*)d_in[1];
    const float* emb  = (const float*)d_in[2];
    const float* fce  = (const float*)d_in[3];
    const float* egw  = (const float*)d_in[4];
    const float* egb  = (const float*)d_in[5];
    const float* euw  = (const float*)d_in[6];
    const float* eub  = (const float*)d_in[7];
    const float* dgw  = (const float*)d_in[8];
    const float* dgb  = (const float*)d_in[9];
    const float* duw  = (const float*)d_in[10];
    const float* dub  = (const float*)d_in[11];
    const float* pw   = (const float*)d_in[12];
    const float* pb   = (const float*)d_in[13];
    float* out = (float*)d_out;

    float *pSSe, *pSSd, *pXin, *pF, *ph;
    float *pDemb, *pDembT, *pEp, *pEpT, *pWge, *pWue, *pWgd, *pWud;
    cudaGetSymbolAddress((void**)&pSSe, g_SS_enc);
    cudaGetSymbolAddress((void**)&pSSd, g_SS_dec);
    cudaGetSymbolAddress((void**)&pXin, g_Xin);
    cudaGetSymbolAddress((void**)&pF, g_F);
    cudaGetSymbolAddress((void**)&ph, g_h);
    cudaGetSymbolAddress((void**)&pDemb, g_demb);
    cudaGetSymbolAddress((void**)&pDembT, g_dembT);
    cudaGetSymbolAddress((void**)&pEp, g_embpad);
    cudaGetSymbolAddress((void**)&pEpT, g_embpadT);
    cudaGetSymbolAddress((void**)&pWge, g_Wg_enc);
    cudaGetSymbolAddress((void**)&pWue, g_Wu_enc);
    cudaGetSymbolAddress((void**)&pWgd, g_Wg_dec);
    cudaGetSymbolAddress((void**)&pWud, g_Wu_dec);

    // ---- setup (ordered so launch index 5 == the 1024^3 SGEMM for ncu -s 5)
    k_pad_emb<<<64, 256>>>(emb);                                             // 0
    k_transpose<<<64, 256>>>(pEp, pEpT, Nn, 16);                             // 1
    sgemm<128, 0><<<dim3(8, 8), 256>>>(pEp, pEpT, pSSe, Nn, Nn, 16, nullptr);// 2
    k_relu_softmax<<<Nn, 256>>>(pSSe);                                       // 3
    k_zero<<<(int)(((size_t)ROWS * FP + 255) / 256), 256>>>(pF, (size_t)ROWS * FP); // 4
    sgemm<128, 0><<<dim3(8, 8), 256>>>(pSSe, pSSe, pSSe + NN2, Nn, Nn, Nn, nullptr); // 5 (profiled)
    k_cheb<<<NN2 / 256, 256>>>(pSSe + NN2);
    k_zero<<<ROWS * 64 / 256, 256>>>(ph, (size_t)ROWS * 64);
    k_pad_w<true><<<(FP * 128 + 255) / 256, 256>>>(egw, pWge, 128);
    k_pad_w<true><<<(FP * 64 + 255) / 256, 256>>>(euw, pWue, 64);
    k_pad_w<false><<<(FP * 128 + 255) / 256, 256>>>(dgw, pWgd, 128);
    k_pad_w<false><<<(FP * 64 + 255) / 256, 256>>>(duw, pWud, 64);

    // ---- encoder
    for (int t = 0; t < Tt; t++) {
        k_build_xin_enc<<<16384, 256>>>(x, t);
        sgemm<128, 1><<<dim3(33, 16), 256>>>(pSSe, pXin, nullptr, 2048, Bb * CD, Nn, nullptr);
        sgemm<128, 3><<<dim3(1, 512), 256>>>(pF, pWge, nullptr, ROWS, 128, FP, egb);
        sgemm<128, 1><<<dim3(33, 16), 256>>>(pSSe, pXin, nullptr, 2048, Bb * CD, Nn, nullptr);
        sgemm<64, 4><<<dim3(1, 512), 256>>>(pF, pWue, nullptr, ROWS, 64, FP, eub);
    }

    // ---- decoder supports from dec_emb gram (sum over batch)
    k_demb<<<ROWS * Ee / 256, 256>>>(fce);
    k_transpose<<<ROWS * Ee / 256, 256>>>(pDemb, pDembT, Nn, Bb * Ee);
    sgemm<128, 0><<<dim3(8, 8), 256>>>(pDemb, pDembT, pSSd, Nn, Nn, Bb * Ee, nullptr);
    k_relu_softmax<<<Nn, 256>>>(pSSd);
    sgemm<128, 0><<<dim3(8, 8), 256>>>(pSSd, pSSd, pSSd + NN2, Nn, Nn, Nn, nullptr);
    k_cheb<<<NN2 / 256, 256>>>(pSSd + NN2);
    k_init_go<<<256, 256>>>(x);

    // ---- decoder
    for (int t = 0; t < Hor; t++) {
        k_build_xin_dec<<<16384, 256>>>(ycov, t);
        sgemm<128, 1><<<dim3(33, 16), 256>>>(pSSd, pXin, nullptr, 2048, Bb * CD, Nn, nullptr);
        sgemm<128, 3><<<dim3(1, 512), 256>>>(pF, pWgd, nullptr, ROWS, 128, FP, dgb);
        sgemm<128, 1><<<dim3(33, 16), 256>>>(pSSd, pXin, nullptr, 2048, Bb * CD, Nn, nullptr);
        sgemm<64, 4><<<dim3(1, 512), 256>>>(pF, pWud, nullptr, ROWS, 64, FP, dub);
        k_proj_out<<<256, 256>>>(pw, pb, out, t);
    }
}

// round 4
// speedup vs baseline: 1.3419x; 1.3419x over previous
#include <cuda_runtime.h>
#include <cuda_bf16.h>
#include <cstdint>
#include <math.h>

constexpr int Bb=64, Tt=12, Nn=1024, Ee=10, Hor=12;
constexpr int ROWS = Nn*Bb;          // 65536
constexpr int NN2  = Nn*Nn;
constexpr int FPK  = 256;            // padded K width of F (3*66=198 -> 256)
constexpr int XTC  = 66*Bb;          // 4224 = Xin^T row count (cols of Xin)

// ---------------- device-global scratch ----------------
__device__ __align__(1024) float g_S_enc[2*NN2];
__device__ __align__(1024) float g_S_dec[2*NN2];
__device__ __align__(1024) float g_R [(size_t)ROWS*64];
__device__ __align__(1024) float g_h [(size_t)ROWS*64];
__device__ __align__(1024) float g_go[ROWS];
__device__ __align__(1024) float g_demb [Nn*Bb*Ee];
__device__ __align__(1024) float g_dembT[Bb*Ee*Nn];
__device__ __align__(1024) float g_embpad [Nn*16];
__device__ __align__(1024) float g_embpadT[16*Nn];

__device__ __align__(1024) __nv_bfloat16 g_Se_hi[2*NN2], g_Se_lo[2*NN2];
__device__ __align__(1024) __nv_bfloat16 g_Sd_hi[2*NN2], g_Sd_lo[2*NN2];
__device__ __align__(1024) __nv_bfloat16 g_XT_hi[(size_t)XTC*Nn], g_XT_lo[(size_t)XTC*Nn];
__device__ __align__(1024) __nv_bfloat16 g_F_hi[(size_t)ROWS*FPK], g_F_lo[(size_t)ROWS*FPK];
__device__ __align__(1024) __nv_bfloat16 g_Wge_hi[128*FPK], g_Wge_lo[128*FPK];
__device__ __align__(1024) __nv_bfloat16 g_Wue_hi[64*FPK],  g_Wue_lo[64*FPK];
__device__ __align__(1024) __nv_bfloat16 g_Wgd_hi[128*FPK], g_Wgd_lo[128*FPK];
__device__ __align__(1024) __nv_bfloat16 g_Wud_hi[64*FPK],  g_Wud_lo[64*FPK];

__device__ __forceinline__ float sigmoidf_(float x){ return 1.0f/(1.0f+expf(-x)); }

__device__ __forceinline__ uint32_t smem_u32(const void* p){
    uint32_t a;
    asm("{ .reg .u64 t; cvta.to.shared.u64 t, %1; cvt.u32.u64 %0, t; }" : "=r"(a) : "l"(p));
    return a;
}
__device__ __forceinline__ void cp_async16(uint32_t dst, const void* src){
    asm volatile("cp.async.cg.shared.global [%0], [%1], 16;" :: "r"(dst), "l"(src));
}
__device__ __forceinline__ void cp_commit(){ asm volatile("cp.async.commit_group;"); }
template <int N>
__device__ __forceinline__ void cp_wait(){ asm volatile("cp.async.wait_group %0;" :: "n"(N)); }

__device__ __forceinline__ void ldsm_x4(uint32_t* r, uint32_t addr){
    asm volatile("ldmatrix.sync.aligned.m8n8.x4.shared.b16 {%0,%1,%2,%3}, [%4];"
        : "=r"(r[0]), "=r"(r[1]), "=r"(r[2]), "=r"(r[3]) : "r"(addr));
}
__device__ __forceinline__ void mma16816(float* c, const uint32_t* a, const uint32_t* b){
    asm volatile("mma.sync.aligned.m16n8k16.row.col.f32.bf16.bf16.f32 "
        "{%0,%1,%2,%3}, {%4,%5,%6,%7}, {%8,%9}, {%0,%1,%2,%3};"
        : "+f"(c[0]), "+f"(c[1]), "+f"(c[2]), "+f"(c[3])
        : "r"(a[0]), "r"(a[1]), "r"(a[2]), "r"(a[3]), "r"(b[0]), "r"(b[1]));
}

// ---------------- bf16 split-K HMMA GEMM ----------------
// D[M rows, N=BN per block] = sum over 3 segments Aseg(M x segK) @ Bseg^T,
// fp32 accumulate. A rows = output rows (lda elems); B rows = output COLUMNS,
// K-major (ldb elems). BM=128, BK=64, 256 threads (8 warps, 4m x 2n).
// EPI 0: diffusion -> bf16 hi/lo scatter into g_F
// EPI 1: gate: z=sig(+bias), c<64 -> z*h into g_XT/g_F; c>=64 -> g_R
// EPI 2: update: hc=tanh(+bias); g_h = r*h + (1-r)*hc
template <int BN, int EPI>
__global__ void __launch_bounds__(256) mma_gemm(
    const __nv_bfloat16* __restrict__ A0, const __nv_bfloat16* __restrict__ A1,
    const __nv_bfloat16* __restrict__ A2,
    const __nv_bfloat16* __restrict__ B0, const __nv_bfloat16* __restrict__ B1,
    const __nv_bfloat16* __restrict__ B2,
    int lda, int ldb, int segK, const float* __restrict__ bias)
{
    constexpr int BM = 128, LDS = 72;      // 64 + 8 pad (bf16 elems)
    constexpr int NT = BN / 16;            // n8-tiles per warp (8 or 4)
    extern __shared__ __align__(16) char sm[];
    const uint32_t smA0 = smem_u32(sm);
    const uint32_t smB0 = smA0 + 2u*BM*LDS*2u;
    const uint32_t smAs[2] = { smA0, smA0 + (uint32_t)BM*LDS*2u };
    const uint32_t smBs[2] = { smB0, smB0 + (uint32_t)BN*LDS*2u };

    const int tid = threadIdx.x, lane = tid & 31, wid = tid >> 5;
    const int wm = wid >> 1, wn = wid & 1;
    const int m0 = blockIdx.y * BM, n0 = blockIdx.x * BN;

    const __nv_bfloat16* Asg[3] = {A0, A1, A2};
    const __nv_bfloat16* Bsg[3] = {B0, B1, B2};
    const int nt_seg = segK >> 6;
    const int KT = 3 * nt_seg;

    float acc[2][NT][4];
#pragma unroll
    for (int i = 0; i < 2; i++)
#pragma unroll
        for (int j = 0; j < NT; j++)
#pragma unroll
            for (int e = 0; e < 4; e++) acc[i][j][e] = 0.0f;

    // ldmatrix base offsets (per-thread)
    const uint32_t aOff = (((uint32_t)(wm*32 + (lane & 15))) * LDS + ((lane >> 4) << 3)) * 2u;
    const uint32_t bOff = (((uint32_t)(wn*(BN/2) + (lane & 7) + ((lane >> 4) << 3))) * LDS
                           + (((lane >> 3) & 1) << 3)) * 2u;

    // cp.async tile loader
    auto load_tile = [&](int kt, int buf) {
        int seg = kt / nt_seg;
        int j = kt - seg * nt_seg;
        const char* Ag = (const char*)(Asg[seg] + (size_t)m0 * lda + j * 64);
        const char* Bg = (const char*)(Bsg[seg] + (size_t)n0 * ldb + j * 64);
#pragma unroll
        for (int it = 0; it < 4; it++) {
            int id = (it << 8) + tid;
            int r = id >> 3, c = id & 7;
            cp_async16(smAs[buf] + (uint32_t)r*144u + (uint32_t)c*16u,
                       Ag + (size_t)r * ((size_t)lda*2) + c*16);
        }
#pragma unroll
        for (int it = 0; it < BN/32; it++) {
            int id = (it << 8) + tid;
            int r = id >> 3, c = id & 7;
            cp_async16(smBs[buf] + (uint32_t)r*144u + (uint32_t)c*16u,
                       Bg + (size_t)r * ((size_t)ldb*2) + c*16);
        }
        cp_commit();
    };

    load_tile(0, 0);

    for (int kt = 0; kt < KT; kt++) {
        const int cur = kt & 1;
        if (kt + 1 < KT) { load_tile(kt + 1, cur ^ 1); cp_wait<1>(); }
        else              { cp_wait<0>(); }
        __syncthreads();

        const uint32_t aBase = smAs[cur] + aOff;
        const uint32_t bBase = smBs[cur] + bOff;
#pragma unroll
        for (int ks = 0; ks < 4; ks++) {
            uint32_t a[2][4];
            ldsm_x4(a[0], aBase + (uint32_t)ks*32u);
            ldsm_x4(a[1], aBase + 16u*LDS*2u + (uint32_t)ks*32u);
            uint32_t b[NT/2][4];
#pragma unroll
            for (int p = 0; p < NT/2; p++)
                ldsm_x4(b[p], bBase + (uint32_t)p*16u*LDS*2u + (uint32_t)ks*32u);
#pragma unroll
            for (int mt = 0; mt < 2; mt++)
#pragma unroll
                for (int nt = 0; nt < NT; nt++)
                    mma16816(acc[mt][nt], a[mt], &b[nt >> 1][(nt & 1) * 2]);
        }
        __syncthreads();
    }

    // ---------------- epilogue ----------------
    const int rbase = m0 + wm*32 + (lane >> 2);
    const int cbase = n0 + wn*(BN/2) + ((lane & 3) << 1);
#pragma unroll
    for (int mt = 0; mt < 2; mt++) {
#pragma unroll
        for (int nt = 0; nt < NT; nt++) {
#pragma unroll
            for (int e = 0; e < 4; e++) {
                const int row = rbase + mt*16 + ((e >> 1) << 3);
                const int col = cbase + nt*8 + (e & 1);
                const float v = acc[mt][nt][e];
                if (EPI == 0) {
                    const int kk = row >> 10, n = row & 1023;
                    const int b = col / 66, c = col - b * 66;
                    __nv_bfloat16 hi = __float2bfloat16(v);
                    __nv_bfloat16 lo = __float2bfloat16(v - __bfloat162float(hi));
                    const size_t off = (size_t)((n << 6) + b) * FPK + (kk + 1) * 66 + c;
                    g_F_hi[off] = hi; g_F_lo[off] = lo;
                } else if (EPI == 1) {
                    const int id = row, n = row >> 6, b = row & 63;
                    const float s = sigmoidf_(v + bias[col]);
                    if (col < 64) {
                        const float zh = s * g_h[(size_t)id * 64 + col];
                        __nv_bfloat16 hi = __float2bfloat16(zh);
                        __nv_bfloat16 lo = __float2bfloat16(zh - __bfloat162float(hi));
                        const size_t xo = ((size_t)(b * 66 + 2 + col) << 10) + n;
                        g_XT_hi[xo] = hi; g_XT_lo[xo] = lo;
                        const size_t fo = ((size_t)id << 8) + 2 + col;
                        g_F_hi[fo] = hi; g_F_lo[fo] = lo;
                    } else {
                        g_R[(size_t)id * 64 + (col - 64)] = s;
                    }
                } else {
                    const int id = row;
                    const float hc = tanhf(v + bias[col]);
                    const size_t o = (size_t)id * 64 + col;
                    const float r = g_R[o], h = g_h[o];
                    g_h[o] = r * h + (1.0f - r) * hc;
                }
            }
        }
    }
}

// ---------------- fp32 SGEMM (setup only; round-1 proven) ----------------
__global__ void __launch_bounds__(256) sgemm32(
    const float* __restrict__ A, const float* __restrict__ B,
    float* __restrict__ C, int M, int N, int K)
{
    constexpr int BM = 128, BN = 64, BK = 16;
    __shared__ __align__(16) float As_[BK][BM];
    __shared__ __align__(16) float Bs_[BK][BN];
    const int tid = threadIdx.x;
    const int tx = tid & 15, ty = tid >> 4;
    const int m0 = blockIdx.y * BM, n0 = blockIdx.x * BN;
    float acc[8][4];
#pragma unroll
    for (int i = 0; i < 8; i++)
#pragma unroll
        for (int jj = 0; jj < 4; jj++) acc[i][jj] = 0.0f;
    const int arow0 = tid >> 2, acol0 = (tid & 3) * 4;
    const int brow = tid >> 4, bcol = (tid & 15) * 4;
    for (int kt = 0; kt < K; kt += BK) {
#pragma unroll
        for (int i = 0; i < 2; i++) {
            int r = arow0 + i * 64;
            float4 v = *reinterpret_cast<const float4*>(A + (size_t)(m0 + r) * K + kt + acol0);
            As_[acol0+0][r]=v.x; As_[acol0+1][r]=v.y; As_[acol0+2][r]=v.z; As_[acol0+3][r]=v.w;
        }
        float4 bv = *reinterpret_cast<const float4*>(B + (size_t)(kt + brow) * N + n0 + bcol);
        *reinterpret_cast<float4*>(&Bs_[brow][bcol]) = bv;
        __syncthreads();
#pragma unroll
        for (int k = 0; k < BK; k++) {
            float4 a0 = *reinterpret_cast<const float4*>(&As_[k][ty*8]);
            float4 a1 = *reinterpret_cast<const float4*>(&As_[k][ty*8+4]);
            float4 b0 = *reinterpret_cast<const float4*>(&Bs_[k][tx*4]);
            float am[8]={a0.x,a0.y,a0.z,a0.w,a1.x,a1.y,a1.z,a1.w};
            float bn[4]={b0.x,b0.y,b0.z,b0.w};
#pragma unroll
            for (int i = 0; i < 8; i++)
#pragma unroll
                for (int jj = 0; jj < 4; jj++) acc[i][jj] = fmaf(am[i], bn[jj], acc[i][jj]);
        }
        __syncthreads();
    }
#pragma unroll
    for (int i = 0; i < 8; i++) {
        float4 v = make_float4(acc[i][0], acc[i][1], acc[i][2], acc[i][3]);
        *reinterpret_cast<float4*>(C + (size_t)(m0 + ty*8 + i) * N + n0 + tx*4) = v;
    }
}

// ---------------- elementwise helpers ----------------
__global__ void k_zero_f32(float* p, size_t n) {
    size_t i = (size_t)blockIdx.x * blockDim.x + threadIdx.x;
    if (i < n) p[i] = 0.0f;
}
__global__ void k_zero_b16(__nv_bfloat16* p, size_t n) {
    size_t i = (size_t)blockIdx.x * blockDim.x + threadIdx.x;
    if (i < n) p[i] = __float2bfloat16(0.0f);
}
__global__ void k_split(const float* __restrict__ s, __nv_bfloat16* __restrict__ hi,
                        __nv_bfloat16* __restrict__ lo, size_t n) {
    size_t i = (size_t)blockIdx.x * blockDim.x + threadIdx.x;
    if (i >= n) return;
    float v = s[i];
    __nv_bfloat16 h = __float2bfloat16(v);
    hi[i] = h;
    lo[i] = __float2bfloat16(v - __bfloat162float(h));
}
__global__ void k_pad_emb(const float* __restrict__ emb) {
    int idx = blockIdx.x * blockDim.x + threadIdx.x;
    if (idx >= Nn * 16) return;
    int n = idx >> 4, j = idx & 15;
    g_embpad[idx] = (j < Ee) ? emb[n * Ee + j] : 0.0f;
}
__global__ void k_transpose(const float* __restrict__ in, float* __restrict__ out,
                            int R, int C) {
    int idx = blockIdx.x * blockDim.x + threadIdx.x;
    if (idx >= R * C) return;
    int r = idx / C, c = idx - r * C;
    out[c * R + r] = in[idx];
}
template <bool ENC>
__global__ void k_pad_w_t(const float* __restrict__ src, __nv_bfloat16* __restrict__ hi,
                          __nv_bfloat16* __restrict__ lo, int nout) {
    int idx = blockIdx.x * blockDim.x + threadIdx.x;
    if (idx >= nout * FPK) return;
    int n = idx >> 8, f = idx & 255;
    float v = 0.0f;
    if (f < 198) {
        int k = f / 66, c = f - k * 66;
        if (ENC) {
            if (c == 0) v = src[(k * 65) * nout + n];
            else if (c >= 2) v = src[(k * 65 + c - 1) * nout + n];
        } else {
            v = src[f * nout + n];
        }
    }
    __nv_bfloat16 h = __float2bfloat16(v);
    hi[idx] = h;
    lo[idx] = __float2bfloat16(v - __bfloat162float(h));
}
__global__ void k_relu_softmax(float* __restrict__ S) {
    int row = blockIdx.x;
    float* p = S + (size_t)row * Nn;
    int t = threadIdx.x;
    float v[4];
#pragma unroll
    for (int i = 0; i < 4; i++) { float x = p[t + i*256]; v[i] = x > 0.0f ? x : 0.0f; }
    __shared__ float red[256];
    float m = fmaxf(fmaxf(v[0], v[1]), fmaxf(v[2], v[3]));
    red[t] = m; __syncthreads();
    for (int s = 128; s > 0; s >>= 1) { if (t < s) red[t] = fmaxf(red[t], red[t+s]); __syncthreads(); }
    m = red[0]; __syncthreads();
    float e[4], sum = 0.0f;
#pragma unroll
    for (int i = 0; i < 4; i++) { e[i] = expf(v[i] - m); sum += e[i]; }
    red[t] = sum; __syncthreads();
    for (int s = 128; s > 0; s >>= 1) { if (t < s) red[t] += red[t+s]; __syncthreads(); }
    float inv = 1.0f / red[0];
#pragma unroll
    for (int i = 0; i < 4; i++) p[t + i*256] = e[i] * inv;
}
__global__ void k_cheb(float* __restrict__ P) {
    int idx = blockIdx.x * blockDim.x + threadIdx.x;
    if (idx >= NN2) return;
    int r = idx >> 10, c = idx & 1023;
    P[idx] = 2.0f * P[idx] - (r == c ? 1.0f : 0.0f);
}
__global__ void k_build_xin_enc(const float* __restrict__ x, int t) {
    int idx = blockIdx.x * blockDim.x + threadIdx.x;
    if (idx >= ROWS * 64) return;
    int id = idx >> 6, i = idx & 63, n = id >> 6, b = id & 63;
    float v = g_h[idx];
    __nv_bfloat16 h1 = __float2bfloat16(v);
    __nv_bfloat16 l1 = __float2bfloat16(v - __bfloat162float(h1));
    size_t xo = ((size_t)(b * 66 + 2 + i) << 10) + n;
    g_XT_hi[xo] = h1; g_XT_lo[xo] = l1;
    size_t fo = ((size_t)id << 8) + 2 + i;
    g_F_hi[fo] = h1; g_F_lo[fo] = l1;
    if (i == 0) {
        float xv = x[((size_t)b * Tt + t) * Nn + n];
        __nv_bfloat16 xh = __float2bfloat16(xv);
        __nv_bfloat16 xl = __float2bfloat16(xv - __bfloat162float(xh));
        __nv_bfloat16 z = __float2bfloat16(0.0f);
        xo = ((size_t)(b * 66) << 10) + n;        g_XT_hi[xo] = xh; g_XT_lo[xo] = xl;
        xo = ((size_t)(b * 66 + 1) << 10) + n;    g_XT_hi[xo] = z;  g_XT_lo[xo] = z;
        fo = (size_t)id << 8;
        g_F_hi[fo] = xh; g_F_lo[fo] = xl;
        g_F_hi[fo + 1] = z; g_F_lo[fo + 1] = z;
    }
}
__global__ void k_build_xin_dec(const float* __restrict__ ycov, int t) {
    int idx = blockIdx.x * blockDim.x + threadIdx.x;
    if (idx >= ROWS * 64) return;
    int id = idx >> 6, i = idx & 63, n = id >> 6, b = id & 63;
    float v = g_h[idx];
    __nv_bfloat16 h1 = __float2bfloat16(v);
    __nv_bfloat16 l1 = __float2bfloat16(v - __bfloat162float(h1));
    size_t xo = ((size_t)(b * 66 + 2 + i) << 10) + n;
    g_XT_hi[xo] = h1; g_XT_lo[xo] = l1;
    size_t fo = ((size_t)id << 8) + 2 + i;
    g_F_hi[fo] = h1; g_F_lo[fo] = l1;
    if (i == 0) {
        float gv = g_go[id];
        float yv = ycov[((size_t)b * Hor + t) * Nn + n];
        __nv_bfloat16 gh = __float2bfloat16(gv);
        __nv_bfloat16 gl = __float2bfloat16(gv - __bfloat162float(gh));
        __nv_bfloat16 yh = __float2bfloat16(yv);
        __nv_bfloat16 yl = __float2bfloat16(yv - __bfloat162float(yh));
        xo = ((size_t)(b * 66) << 10) + n;        g_XT_hi[xo] = gh; g_XT_lo[xo] = gl;
        xo = ((size_t)(b * 66 + 1) << 10) + n;    g_XT_hi[xo] = yh; g_XT_lo[xo] = yl;
        fo = (size_t)id << 8;
        g_F_hi[fo] = gh; g_F_lo[fo] = gl;
        g_F_hi[fo + 1] = yh; g_F_lo[fo + 1] = yl;
    }
}
__global__ void k_demb(const float* __restrict__ fce) {
    int idx = blockIdx.x * blockDim.x + threadIdx.x;
    if (idx >= ROWS * Ee) return;
    int id = idx / Ee, e = idx - id * Ee;
    const float* hr = g_h + (size_t)id * 64;
    float s = 0.0f;
#pragma unroll
    for (int h = 0; h < 64; h++) s = fmaf(hr[h], fce[h * Ee + e], s);
    g_demb[idx] = s;
}
__global__ void k_init_go(const float* __restrict__ x) {
    int id = blockIdx.x * blockDim.x + threadIdx.x;
    if (id >= ROWS) return;
    int n = id >> 6, b = id & 63;
    g_go[id] = x[((size_t)b * Tt + (Tt - 1)) * Nn + n];
}
__global__ void k_proj_out(const float* __restrict__ pw, const float* __restrict__ pb,
                           float* __restrict__ out, int t) {
    int id = blockIdx.x * blockDim.x + threadIdx.x;
    if (id >= ROWS) return;
    int n = id >> 6, b = id & 63;
    const float* hr = g_h + (size_t)id * 64;
    float s = pb[0];
#pragma unroll
    for (int i = 0; i < 64; i++) s = fmaf(hr[i], pw[i], s);
    g_go[id] = s;
    out[((size_t)b * Hor + t) * Nn + n] = s;
}

// ---------------- orchestration ----------------
extern "C" void kernel_launch(void* const* d_in, const int* in_sizes, int n_in,
                              void* d_out, int out_size) {
    const float* x    = (const float*)d_in[0];
    const float* ycov = (const float*)d_in[1];
    const float* emb  = (const float*)d_in[2];
    const float* fce  = (const float*)d_in[3];
    const float* egw  = (const float*)d_in[4];
    const float* egb  = (const float*)d_in[5];
    const float* euw  = (const float*)d_in[6];
    const float* eub  = (const float*)d_in[7];
    const float* dgw  = (const float*)d_in[8];
    const float* dgb  = (const float*)d_in[9];
    const float* duw  = (const float*)d_in[10];
    const float* dub  = (const float*)d_in[11];
    const float* pw   = (const float*)d_in[12];
    const float* pb   = (const float*)d_in[13];
    float* out = (float*)d_out;

    float *pSe, *pSd, *ph, *pDemb, *pDembT, *pEp, *pEpT;
    __nv_bfloat16 *pSeh, *pSel, *pSdh, *pSdl, *pXh, *pXl, *pFh, *pFl;
    __nv_bfloat16 *pWgeh, *pWgel, *pWueh, *pWuel, *pWgdh, *pWgdl, *pWudh, *pWudl;
    cudaGetSymbolAddress((void**)&pSe, g_S_enc);
    cudaGetSymbolAddress((void**)&pSd, g_S_dec);
    cudaGetSymbolAddress((void**)&ph, g_h);
    cudaGetSymbolAddress((void**)&pDemb, g_demb);
    cudaGetSymbolAddress((void**)&pDembT, g_dembT);
    cudaGetSymbolAddress((void**)&pEp, g_embpad);
    cudaGetSymbolAddress((void**)&pEpT, g_embpadT);
    cudaGetSymbolAddress((void**)&pSeh, g_Se_hi); cudaGetSymbolAddress((void**)&pSel, g_Se_lo);
    cudaGetSymbolAddress((void**)&pSdh, g_Sd_hi); cudaGetSymbolAddress((void**)&pSdl, g_Sd_lo);
    cudaGetSymbolAddress((void**)&pXh, g_XT_hi);  cudaGetSymbolAddress((void**)&pXl, g_XT_lo);
    cudaGetSymbolAddress((void**)&pFh, g_F_hi);   cudaGetSymbolAddress((void**)&pFl, g_F_lo);
    cudaGetSymbolAddress((void**)&pWgeh, g_Wge_hi); cudaGetSymbolAddress((void**)&pWgel, g_Wge_lo);
    cudaGetSymbolAddress((void**)&pWueh, g_Wue_hi); cudaGetSymbolAddress((void**)&pWuel, g_Wue_lo);
    cudaGetSymbolAddress((void**)&pWgdh, g_Wgd_hi); cudaGetSymbolAddress((void**)&pWgdl, g_Wgd_lo);
    cudaGetSymbolAddress((void**)&pWudh, g_Wud_hi); cudaGetSymbolAddress((void**)&pWudl, g_Wud_lo);

    constexpr int SMEM_BN128 = 2 * (128 * 72 + 128 * 72) * 2;  // 73728
    constexpr int SMEM_BN64  = 2 * (128 * 72 + 64 * 72) * 2;   // 55296
    cudaFuncSetAttribute(mma_gemm<128,0>, cudaFuncAttributeMaxDynamicSharedMemorySize, SMEM_BN128);
    cudaFuncSetAttribute(mma_gemm<128,1>, cudaFuncAttributeMaxDynamicSharedMemorySize, SMEM_BN128);
    cudaFuncSetAttribute(mma_gemm<64,2>,  cudaFuncAttributeMaxDynamicSharedMemorySize, SMEM_BN64);

    // ---- setup, ordered so launch index 5 is a representative diffusion GEMM
    k_zero_f32<<<ROWS * 64 / 256, 256>>>(ph, (size_t)ROWS * 64);                        // 0
    k_zero_b16<<<(int)((size_t)ROWS * FPK / 256), 256>>>(pFh, (size_t)ROWS * FPK);      // 1
    k_zero_b16<<<(int)((size_t)ROWS * FPK / 256), 256>>>(pFl, (size_t)ROWS * FPK);      // 2
    k_build_xin_enc<<<16384, 256>>>(x, 0);                                              // 3
    k_pad_emb<<<64, 256>>>(emb);                                                        // 4
    // ncu target: real-shape diffusion (S buffers deterministic; output overwritten)
    mma_gemm<128,0><<<dim3(33, 16), 256, SMEM_BN128>>>(pSeh, pSel, pSeh, pXh, pXh, pXl,
                                                       Nn, Nn, 1024, nullptr);          // 5
    k_transpose<<<64, 256>>>(pEp, pEpT, Nn, 16);
    sgemm32<<<dim3(16, 8), 256>>>(pEp, pEpT, pSe, Nn, Nn, 16);
    k_relu_softmax<<<Nn, 256>>>(pSe);
    sgemm32<<<dim3(16, 8), 256>>>(pSe, pSe, pSe + NN2, Nn, Nn, Nn);
    k_cheb<<<NN2 / 256, 256>>>(pSe + NN2);
    k_split<<<2 * NN2 / 256, 256>>>(pSe, pSeh, pSel, (size_t)2 * NN2);
    k_pad_w_t<true><<<(128 * FPK + 255) / 256, 256>>>(egw, pWgeh, pWgel, 128);
    k_pad_w_t<true><<<(64 * FPK + 255) / 256, 256>>>(euw, pWueh, pWuel, 64);
    k_pad_w_t<false><<<(128 * FPK + 255) / 256, 256>>>(dgw, pWgdh, pWgdl, 128);
    k_pad_w_t<false><<<(64 * FPK + 255) / 256, 256>>>(duw, pWudh, pWudl, 64);

    // ---- encoder
    for (int t = 0; t < Tt; t++) {
        k_build_xin_enc<<<16384, 256>>>(x, t);
        mma_gemm<128,0><<<dim3(33, 16), 256, SMEM_BN128>>>(pSeh, pSel, pSeh, pXh, pXh, pXl,
                                                           Nn, Nn, 1024, nullptr);
        mma_gemm<128,1><<<dim3(1, 512), 256, SMEM_BN128>>>(pFh, pFl, pFh, pWgeh, pWgeh, pWgel,
                                                           FPK, FPK, 256, egb);
        mma_gemm<128,0><<<dim3(33, 16), 256, SMEM_BN128>>>(pSeh, pSel, pSeh, pXh, pXh, pXl,
                                                           Nn, Nn, 1024, nullptr);
        mma_gemm<64,2><<<dim3(1, 512), 256, SMEM_BN64>>>(pFh, pFl, pFh, pWueh, pWueh, pWuel,
                                                         FPK, FPK, 256, eub);
    }

    // ---- decoder supports
    k_demb<<<ROWS * Ee / 256, 256>>>(fce);
    k_transpose<<<ROWS * Ee / 256, 256>>>(pDemb, pDembT, Nn, Bb * Ee);
    sgemm32<<<dim3(16, 8), 256>>>(pDemb, pDembT, pSd, Nn, Nn, Bb * Ee);
    k_relu_softmax<<<Nn, 256>>>(pSd);
    sgemm32<<<dim3(16, 8), 256>>>(pSd, pSd, pSd + NN2, Nn, Nn, Nn);
    k_cheb<<<NN2 / 256, 256>>>(pSd + NN2);
    k_split<<<2 * NN2 / 256, 256>>>(pSd, pSdh, pSdl, (size_t)2 * NN2);
    k_init_go<<<256, 256>>>(x);

    // ---- decoder
    for (int t = 0; t < Hor; t++) {
        k_build_xin_dec<<<16384, 256>>>(ycov, t);
        mma_gemm<128,0><<<dim3(33, 16), 256, SMEM_BN128>>>(pSdh, pSdl, pSdh, pXh, pXh, pXl,
                                                           Nn, Nn, 1024, nullptr);
        mma_gemm<128,1><<<dim3(1, 512), 256, SMEM_BN128>>>(pFh, pFl, pFh, pWgdh, pWgdh, pWgdl,
                                                           FPK, FPK, 256, dgb);
        mma_gemm<128,0><<<dim3(33, 16), 256, SMEM_BN128>>>(pSdh, pSdl, pSdh, pXh, pXh, pXl,
                                                           Nn, Nn, 1024, nullptr);
        mma_gemm<64,2><<<dim3(1, 512), 256, SMEM_BN64>>>(pFh, pFl, pFh, pWudh, pWudh, pWudl,
                                                         FPK, FPK, 256, dub);
        k_proj_out<<<256, 256>>>(pw, pb, out, t);
    }
}

// round 5
// speedup vs baseline: 1.3521x; 1.0076x over previous
#include <cuda_runtime.h>
#include <cuda_bf16.h>
#include <cstdint>
#include <math.h>

constexpr int Bb=64, Tt=12, Nn=1024, Ee=10, Hor=12;
constexpr int ROWS = Nn*Bb;          // 65536
constexpr int NN2  = Nn*Nn;
constexpr int FPK  = 256;            // padded K width of F (3*66=198 -> 256)
constexpr int XTC  = 66*Bb;          // 4224 = Xin^T row count (cols of Xin)

// ---------------- device-global scratch ----------------
__device__ __align__(1024) float g_S_enc[2*NN2];
__device__ __align__(1024) float g_S_dec[2*NN2];
__device__ __align__(1024) float g_R [(size_t)ROWS*64];
__device__ __align__(1024) float g_h [(size_t)ROWS*64];
__device__ __align__(1024) float g_go[ROWS];
__device__ __align__(1024) float g_demb [Nn*Bb*Ee];
__device__ __align__(1024) float g_dembT[Bb*Ee*Nn];
__device__ __align__(1024) float g_embpad [Nn*16];
__device__ __align__(1024) float g_embpadT[16*Nn];

__device__ __align__(1024) __nv_bfloat16 g_Se_hi[2*NN2], g_Se_lo[2*NN2];
__device__ __align__(1024) __nv_bfloat16 g_Sd_hi[2*NN2], g_Sd_lo[2*NN2];
__device__ __align__(1024) __nv_bfloat16 g_XT_hi[(size_t)XTC*Nn], g_XT_lo[(size_t)XTC*Nn];
__device__ __align__(1024) __nv_bfloat16 g_F_hi[(size_t)ROWS*FPK], g_F_lo[(size_t)ROWS*FPK];
__device__ __align__(1024) __nv_bfloat16 g_Wge_hi[128*FPK], g_Wge_lo[128*FPK];
__device__ __align__(1024) __nv_bfloat16 g_Wue_hi[64*FPK],  g_Wue_lo[64*FPK];
__device__ __align__(1024) __nv_bfloat16 g_Wgd_hi[128*FPK], g_Wgd_lo[128*FPK];
__device__ __align__(1024) __nv_bfloat16 g_Wud_hi[64*FPK],  g_Wud_lo[64*FPK];

__device__ __forceinline__ float sigmoidf_(float x){ return 1.0f/(1.0f+expf(-x)); }

__device__ __forceinline__ uint32_t smem_u32(const void* p){
    uint32_t a;
    asm("{ .reg .u64 t; cvta.to.shared.u64 t, %1; cvt.u32.u64 %0, t; }" : "=r"(a) : "l"(p));
    return a;
}
__device__ __forceinline__ void cp_async16(uint32_t dst, const void* src){
    asm volatile("cp.async.cg.shared.global [%0], [%1], 16;" :: "r"(dst), "l"(src));
}
__device__ __forceinline__ void cp_commit(){ asm volatile("cp.async.commit_group;"); }
template <int N>
__device__ __forceinline__ void cp_wait(){ asm volatile("cp.async.wait_group %0;" :: "n"(N)); }

__device__ __forceinline__ void ldsm_x4(uint32_t* r, uint32_t addr){
    asm volatile("ldmatrix.sync.aligned.m8n8.x4.shared.b16 {%0,%1,%2,%3}, [%4];"
        : "=r"(r[0]), "=r"(r[1]), "=r"(r[2]), "=r"(r[3]) : "r"(addr));
}
__device__ __forceinline__ void mma16816(float* c, const uint32_t* a, const uint32_t* b){
    asm volatile("mma.sync.aligned.m16n8k16.row.col.f32.bf16.bf16.f32 "
        "{%0,%1,%2,%3}, {%4,%5,%6,%7}, {%8,%9}, {%0,%1,%2,%3};"
        : "+f"(c[0]), "+f"(c[1]), "+f"(c[2]), "+f"(c[3])
        : "r"(a[0]), "r"(a[1]), "r"(a[2]), "r"(a[3]), "r"(b[0]), "r"(b[1]));
}

// ---------------- bf16 split-K HMMA GEMM (3-stage cp.async pipeline) --------
// D[M rows, N=BN per block] = sum over 3 segments Aseg(M x segK) @ Bseg^T,
// fp32 accumulate. A rows = output rows (lda elems); B rows = output COLUMNS,
// K-major (ldb elems). BM=128, BK=64, 256 threads (8 warps, 4m x 2n).
// EPI 0: diffusion -> bf16 hi/lo scatter into g_F
// EPI 1: gate: z=sig(+bias), c<64 -> z*h into g_XT/g_F; c>=64 -> g_R
// EPI 2: update: hc=tanh(+bias); hn = r*h + (1-r)*hc -> g_h AND bf16 hi/lo
//        into g_XT/g_F state slots (fused "build_xin" for the next step)
template <int BN, int EPI>
__global__ void __launch_bounds__(256) mma_gemm(
    const __nv_bfloat16* __restrict__ A0, const __nv_bfloat16* __restrict__ A1,
    const __nv_bfloat16* __restrict__ A2,
    const __nv_bfloat16* __restrict__ B0, const __nv_bfloat16* __restrict__ B1,
    const __nv_bfloat16* __restrict__ B2,
    int lda, int ldb, int segK, const float* __restrict__ bias)
{
    constexpr int BM = 128, LDS = 72;      // 64 + 8 pad (bf16 elems)
    constexpr int NT = BN / 16;            // n8-tiles per warp (8 or 4)
    constexpr uint32_t STG_BYTES = (uint32_t)(BM + BN) * LDS * 2u;
    extern __shared__ __align__(16) char sm[];
    const uint32_t sm0 = smem_u32(sm);

    const int tid = threadIdx.x, lane = tid & 31, wid = tid >> 5;
    const int wm = wid >> 1, wn = wid & 1;
    const int m0 = blockIdx.y * BM, n0 = blockIdx.x * BN;

    const __nv_bfloat16* Asg[3] = {A0, A1, A2};
    const __nv_bfloat16* Bsg[3] = {B0, B1, B2};
    const int nt_seg = segK >> 6;
    const int KT = 3 * nt_seg;

    float acc[2][NT][4];
#pragma unroll
    for (int i = 0; i < 2; i++)
#pragma unroll
        for (int j = 0; j < NT; j++)
#pragma unroll
            for (int e = 0; e < 4; e++) acc[i][j][e] = 0.0f;

    // ldmatrix base offsets (per-thread, within a stage)
    const uint32_t aOff = (((uint32_t)(wm*32 + (lane & 15))) * LDS + ((lane >> 4) << 3)) * 2u;
    const uint32_t bOff = (uint32_t)BM * LDS * 2u
        + (((uint32_t)(wn*(BN/2) + (lane & 7) + ((lane >> 4) << 3))) * LDS
           + (((lane >> 3) & 1) << 3)) * 2u;

    auto load_tile = [&](int kt, int stg) {
        const uint32_t sA = sm0 + (uint32_t)stg * STG_BYTES;
        const uint32_t sB = sA + (uint32_t)BM * LDS * 2u;
        int seg = kt / nt_seg;
        int j = kt - seg * nt_seg;
        const char* Ag = (const char*)(Asg[seg] + (size_t)m0 * lda + j * 64);
        const char* Bg = (const char*)(Bsg[seg] + (size_t)n0 * ldb + j * 64);
#pragma unroll
        for (int it = 0; it < 4; it++) {
            int id = (it << 8) + tid;
            int r = id >> 3, c = id & 7;
            cp_async16(sA + (uint32_t)r*144u + (uint32_t)c*16u,
                       Ag + (size_t)r * ((size_t)lda*2) + c*16);
        }
#pragma unroll
        for (int it = 0; it < BN/32; it++) {
            int id = (it << 8) + tid;
            int r = id >> 3, c = id & 7;
            cp_async16(sB + (uint32_t)r*144u + (uint32_t)c*16u,
                       Bg + (size_t)r * ((size_t)ldb*2) + c*16);
        }
        cp_commit();
    };

    load_tile(0, 0);
    if (KT > 1) load_tile(1, 1);

    int stg = 0;
    for (int kt = 0; kt < KT; kt++) {
        if (kt + 1 < KT) cp_wait<1>(); else cp_wait<0>();
        __syncthreads();
        if (kt + 2 < KT) load_tile(kt + 2, (kt + 2) % 3);

        const uint32_t sbase = sm0 + (uint32_t)stg * STG_BYTES;
        const uint32_t aBase = sbase + aOff;
        const uint32_t bBase = sbase + bOff;
#pragma unroll
        for (int ks = 0; ks < 4; ks++) {
            uint32_t a[2][4];
            ldsm_x4(a[0], aBase + (uint32_t)ks*32u);
            ldsm_x4(a[1], aBase + 16u*LDS*2u + (uint32_t)ks*32u);
            uint32_t b[NT/2][4];
#pragma unroll
            for (int p = 0; p < NT/2; p++)
                ldsm_x4(b[p], bBase + (uint32_t)p*16u*LDS*2u + (uint32_t)ks*32u);
#pragma unroll
            for (int mt = 0; mt < 2; mt++)
#pragma unroll
                for (int nt = 0; nt < NT; nt++)
                    mma16816(acc[mt][nt], a[mt], &b[nt >> 1][(nt & 1) * 2]);
        }
        if (++stg == 3) stg = 0;
    }

    // ---------------- epilogue ----------------
    const int rbase = m0 + wm*32 + (lane >> 2);
    const int cbase = n0 + wn*(BN/2) + ((lane & 3) << 1);
#pragma unroll
    for (int mt = 0; mt < 2; mt++) {
#pragma unroll
        for (int nt = 0; nt < NT; nt++) {
#pragma unroll
            for (int e = 0; e < 4; e++) {
                const int row = rbase + mt*16 + ((e >> 1) << 3);
                const int col = cbase + nt*8 + (e & 1);
                const float v = acc[mt][nt][e];
                if (EPI == 0) {
                    const int kk = row >> 10, n = row & 1023;
                    const int b = col / 66, c = col - b * 66;
                    __nv_bfloat16 hi = __float2bfloat16(v);
                    __nv_bfloat16 lo = __float2bfloat16(v - __bfloat162float(hi));
                    const size_t off = (size_t)((n << 6) + b) * FPK + (kk + 1) * 66 + c;
                    g_F_hi[off] = hi; g_F_lo[off] = lo;
                } else if (EPI == 1) {
                    const int id = row, n = row >> 6, b = row & 63;
                    const float s = sigmoidf_(v + bias[col]);
                    if (col < 64) {
                        const float zh = s * g_h[(size_t)id * 64 + col];
                        __nv_bfloat16 hi = __float2bfloat16(zh);
                        __nv_bfloat16 lo = __float2bfloat16(zh - __bfloat162float(hi));
                        const size_t xo = ((size_t)(b * 66 + 2 + col) << 10) + n;
                        g_XT_hi[xo] = hi; g_XT_lo[xo] = lo;
                        const size_t fo = ((size_t)id << 8) + 2 + col;
                        g_F_hi[fo] = hi; g_F_lo[fo] = lo;
                    } else {
                        g_R[(size_t)id * 64 + (col - 64)] = s;
                    }
                } else {
                    const int id = row, n = row >> 6, b = row & 63;
                    const float hc = tanhf(v + bias[col]);
                    const size_t o = (size_t)id * 64 + col;
                    const float r = g_R[o], h = g_h[o];
                    const float hn = r * h + (1.0f - r) * hc;
                    g_h[o] = hn;
                    // fused build_xin for the next step
                    __nv_bfloat16 hi = __float2bfloat16(hn);
                    __nv_bfloat16 lo = __float2bfloat16(hn - __bfloat162float(hi));
                    const size_t xo = ((size_t)(b * 66 + 2 + col) << 10) + n;
                    g_XT_hi[xo] = hi; g_XT_lo[xo] = lo;
                    const size_t fo = ((size_t)id << 8) + 2 + col;
                    g_F_hi[fo] = hi; g_F_lo[fo] = lo;
                }
            }
        }
    }
}

// ---------------- fp32 SGEMM (setup only) ----------------
__global__ void __launch_bounds__(256) sgemm32(
    const float* __restrict__ A, const float* __restrict__ B,
    float* __restrict__ C, int M, int N, int K)
{
    constexpr int BM = 128, BN = 64, BK = 16;
    __shared__ __align__(16) float As_[BK][BM];
    __shared__ __align__(16) float Bs_[BK][BN];
    const int tid = threadIdx.x;
    const int tx = tid & 15, ty = tid >> 4;
    const int m0 = blockIdx.y * BM, n0 = blockIdx.x * BN;
    float acc[8][4];
#pragma unroll
    for (int i = 0; i < 8; i++)
#pragma unroll
        for (int jj = 0; jj < 4; jj++) acc[i][jj] = 0.0f;
    const int arow0 = tid >> 2, acol0 = (tid & 3) * 4;
    const int brow = tid >> 4, bcol = (tid & 15) * 4;
    for (int kt = 0; kt < K; kt += BK) {
#pragma unroll
        for (int i = 0; i < 2; i++) {
            int r = arow0 + i * 64;
            float4 v = *reinterpret_cast<const float4*>(A + (size_t)(m0 + r) * K + kt + acol0);
            As_[acol0+0][r]=v.x; As_[acol0+1][r]=v.y; As_[acol0+2][r]=v.z; As_[acol0+3][r]=v.w;
        }
        float4 bv = *reinterpret_cast<const float4*>(B + (size_t)(kt + brow) * N + n0 + bcol);
        *reinterpret_cast<float4*>(&Bs_[brow][bcol]) = bv;
        __syncthreads();
#pragma unroll
        for (int k = 0; k < BK; k++) {
            float4 a0 = *reinterpret_cast<const float4*>(&As_[k][ty*8]);
            float4 a1 = *reinterpret_cast<const float4*>(&As_[k][ty*8+4]);
            float4 b0 = *reinterpret_cast<const float4*>(&Bs_[k][tx*4]);
            float am[8]={a0.x,a0.y,a0.z,a0.w,a1.x,a1.y,a1.z,a1.w};
            float bn[4]={b0.x,b0.y,b0.z,b0.w};
#pragma unroll
            for (int i = 0; i < 8; i++)
#pragma unroll
                for (int jj = 0; jj < 4; jj++) acc[i][jj] = fmaf(am[i], bn[jj], acc[i][jj]);
        }
        __syncthreads();
    }
#pragma unroll
    for (int i = 0; i < 8; i++) {
        float4 v = make_float4(acc[i][0], acc[i][1], acc[i][2], acc[i][3]);
        *reinterpret_cast<float4*>(C + (size_t)(m0 + ty*8 + i) * N + n0 + tx*4) = v;
    }
}

// ---------------- elementwise helpers ----------------
__global__ void k_zero_f32(float* p, size_t n) {
    size_t i = (size_t)blockIdx.x * blockDim.x + threadIdx.x;
    if (i < n) p[i] = 0.0f;
}
__global__ void k_zero_b16(__nv_bfloat16* p, size_t n) {
    size_t i = (size_t)blockIdx.x * blockDim.x + threadIdx.x;
    if (i < n) p[i] = __float2bfloat16(0.0f);
}
__global__ void k_split(const float* __restrict__ s, __nv_bfloat16* __restrict__ hi,
                        __nv_bfloat16* __restrict__ lo, size_t n) {
    size_t i = (size_t)blockIdx.x * blockDim.x + threadIdx.x;
    if (i >= n) return;
    float v = s[i];
    __nv_bfloat16 h = __float2bfloat16(v);
    hi[i] = h;
    lo[i] = __float2bfloat16(v - __bfloat162float(h));
}
__global__ void k_pad_emb(const float* __restrict__ emb) {
    int idx = blockIdx.x * blockDim.x + threadIdx.x;
    if (idx >= Nn * 16) return;
    int n = idx >> 4, j = idx & 15;
    g_embpad[idx] = (j < Ee) ? emb[n * Ee + j] : 0.0f;
}
__global__ void k_transpose(const float* __restrict__ in, float* __restrict__ out,
                            int R, int C) {
    int idx = blockIdx.x * blockDim.x + threadIdx.x;
    if (idx >= R * C) return;
    int r = idx / C, c = idx - r * C;
    out[c * R + r] = in[idx];
}
template <bool ENC>
__global__ void k_pad_w_t(const float* __restrict__ src, __nv_bfloat16* __restrict__ hi,
                          __nv_bfloat16* __restrict__ lo, int nout) {
    int idx = blockIdx.x * blockDim.x + threadIdx.x;
    if (idx >= nout * FPK) return;
    int n = idx >> 8, f = idx & 255;
    float v = 0.0f;
    if (f < 198) {
        int k = f / 66, c = f - k * 66;
        if (ENC) {
            if (c == 0) v = src[(k * 65) * nout + n];
            else if (c >= 2) v = src[(k * 65 + c - 1) * nout + n];
        } else {
            v = src[f * nout + n];
        }
    }
    __nv_bfloat16 h = __float2bfloat16(v);
    hi[idx] = h;
    lo[idx] = __float2bfloat16(v - __bfloat162float(h));
}
__global__ void k_relu_softmax(float* __restrict__ S) {
    int row = blockIdx.x;
    float* p = S + (size_t)row * Nn;
    int t = threadIdx.x;
    float v[4];
#pragma unroll
    for (int i = 0; i < 4; i++) { float x = p[t + i*256]; v[i] = x > 0.0f ? x : 0.0f; }
    __shared__ float red[256];
    float m = fmaxf(fmaxf(v[0], v[1]), fmaxf(v[2], v[3]));
    red[t] = m; __syncthreads();
    for (int s = 128; s > 0; s >>= 1) { if (t < s) red[t] = fmaxf(red[t], red[t+s]); __syncthreads(); }
    m = red[0]; __syncthreads();
    float e[4], sum = 0.0f;
#pragma unroll
    for (int i = 0; i < 4; i++) { e[i] = expf(v[i] - m); sum += e[i]; }
    red[t] = sum; __syncthreads();
    for (int s = 128; s > 0; s >>= 1) { if (t < s) red[t] += red[t+s]; __syncthreads(); }
    float inv = 1.0f / red[0];
#pragma unroll
    for (int i = 0; i < 4; i++) p[t + i*256] = e[i] * inv;
}
__global__ void k_cheb(float* __restrict__ P) {
    int idx = blockIdx.x * blockDim.x + threadIdx.x;
    if (idx >= NN2) return;
    int r = idx >> 10, c = idx & 1023;
    P[idx] = 2.0f * P[idx] - (r == c ? 1.0f : 0.0f);
}
// per-step inputs: encoder writes x_t into XT col (b*66) and F col 0
__global__ void k_set_x_enc(const float* __restrict__ x, int t) {
    int id = blockIdx.x * blockDim.x + threadIdx.x;
    if (id >= ROWS) return;
    int n = id >> 6, b = id & 63;
    float xv = x[((size_t)b * Tt + t) * Nn + n];
    __nv_bfloat16 xh = __float2bfloat16(xv);
    __nv_bfloat16 xl = __float2bfloat16(xv - __bfloat162float(xh));
    size_t xo = ((size_t)(b * 66) << 10) + n;
    g_XT_hi[xo] = xh; g_XT_lo[xo] = xl;
    size_t fo = (size_t)id << 8;
    g_F_hi[fo] = xh; g_F_lo[fo] = xl;
}
// decoder: go + ycov into cols 0,1
__global__ void k_set_xy_dec(const float* __restrict__ ycov, int t) {
    int id = blockIdx.x * blockDim.x + threadIdx.x;
    if (id >= ROWS) return;
    int n = id >> 6, b = id & 63;
    float gv = g_go[id];
    float yv = ycov[((size_t)b * Hor + t) * Nn + n];
    __nv_bfloat16 gh = __float2bfloat16(gv);
    __nv_bfloat16 gl = __float2bfloat16(gv - __bfloat162float(gh));
    __nv_bfloat16 yh = __float2bfloat16(yv);
    __nv_bfloat16 yl = __float2bfloat16(yv - __bfloat162float(yh));
    size_t xo = ((size_t)(b * 66) << 10) + n;
    g_XT_hi[xo] = gh; g_XT_lo[xo] = gl;
    xo = ((size_t)(b * 66 + 1) << 10) + n;
    g_XT_hi[xo] = yh; g_XT_lo[xo] = yl;
    size_t fo = (size_t)id << 8;
    g_F_hi[fo] = gh; g_F_lo[fo] = gl;
    g_F_hi[fo + 1] = yh; g_F_lo[fo + 1] = yl;
}
__global__ void k_demb(const float* __restrict__ fce) {
    int idx = blockIdx.x * blockDim.x + threadIdx.x;
    if (idx >= ROWS * Ee) return;
    int id = idx / Ee, e = idx - id * Ee;
    const float* hr = g_h + (size_t)id * 64;
    float s = 0.0f;
#pragma unroll
    for (int h = 0; h < 64; h++) s = fmaf(hr[h], fce[h * Ee + e], s);
    g_demb[idx] = s;
}
__global__ void k_init_go(const float* __restrict__ x) {
    int id = blockIdx.x * blockDim.x + threadIdx.x;
    if (id >= ROWS) return;
    int n = id >> 6, b = id & 63;
    g_go[id] = x[((size_t)b * Tt + (Tt - 1)) * Nn + n];
}
__global__ void k_proj_out(const float* __restrict__ pw, const float* __restrict__ pb,
                           float* __restrict__ out, int t) {
    int id = blockIdx.x * blockDim.x + threadIdx.x;
    if (id >= ROWS) return;
    int n = id >> 6, b = id & 63;
    const float* hr = g_h + (size_t)id * 64;
    float s = pb[0];
#pragma unroll
    for (int i = 0; i < 64; i++) s = fmaf(hr[i], pw[i], s);
    g_go[id] = s;
    out[((size_t)b * Hor + t) * Nn + n] = s;
}

// ---------------- orchestration ----------------
extern "C" void kernel_launch(void* const* d_in, const int* in_sizes, int n_in,
                              void* d_out, int out_size) {
    const float* x    = (const float*)d_in[0];
    const float* ycov = (const float*)d_in[1];
    const float* emb  = (const float*)d_in[2];
    const float* fce  = (const float*)d_in[3];
    const float* egw  = (const float*)d_in[4];
    const float* egb  = (const float*)d_in[5];
    const float* euw  = (const float*)d_in[6];
    const float* eub  = (const float*)d_in[7];
    const float* dgw  = (const float*)d_in[8];
    const float* dgb  = (const float*)d_in[9];
    const float* duw  = (const float*)d_in[10];
    const float* dub  = (const float*)d_in[11];
    const float* pw   = (const float*)d_in[12];
    const float* pb   = (const float*)d_in[13];
    float* out = (float*)d_out;

    float *pSe, *pSd, *ph, *pDemb, *pDembT, *pEp, *pEpT;
    __nv_bfloat16 *pSeh, *pSel, *pSdh, *pSdl, *pXh, *pXl, *pFh, *pFl;
    __nv_bfloat16 *pWgeh, *pWgel, *pWueh, *pWuel, *pWgdh, *pWgdl, *pWudh, *pWudl;
    cudaGetSymbolAddress((void**)&pSe, g_S_enc);
    cudaGetSymbolAddress((void**)&pSd, g_S_dec);
    cudaGetSymbolAddress((void**)&ph, g_h);
    cudaGetSymbolAddress((void**)&pDemb, g_demb);
    cudaGetSymbolAddress((void**)&pDembT, g_dembT);
    cudaGetSymbolAddress((void**)&pEp, g_embpad);
    cudaGetSymbolAddress((void**)&pEpT, g_embpadT);
    cudaGetSymbolAddress((void**)&pSeh, g_Se_hi); cudaGetSymbolAddress((void**)&pSel, g_Se_lo);
    cudaGetSymbolAddress((void**)&pSdh, g_Sd_hi); cudaGetSymbolAddress((void**)&pSdl, g_Sd_lo);
    cudaGetSymbolAddress((void**)&pXh, g_XT_hi);  cudaGetSymbolAddress((void**)&pXl, g_XT_lo);
    cudaGetSymbolAddress((void**)&pFh, g_F_hi);   cudaGetSymbolAddress((void**)&pFl, g_F_lo);
    cudaGetSymbolAddress((void**)&pWgeh, g_Wge_hi); cudaGetSymbolAddress((void**)&pWgel, g_Wge_lo);
    cudaGetSymbolAddress((void**)&pWueh, g_Wue_hi); cudaGetSymbolAddress((void**)&pWuel, g_Wue_lo);
    cudaGetSymbolAddress((void**)&pWgdh, g_Wgd_hi); cudaGetSymbolAddress((void**)&pWgdl, g_Wgd_lo);
    cudaGetSymbolAddress((void**)&pWudh, g_Wud_hi); cudaGetSymbolAddress((void**)&pWudl, g_Wud_lo);

    constexpr int SMEM_BN128 = 3 * (128 + 128) * 72 * 2;  // 110592
    constexpr int SMEM_BN64  = 3 * (128 + 64) * 72 * 2;   // 82944
    cudaFuncSetAttribute(mma_gemm<128,0>, cudaFuncAttributeMaxDynamicSharedMemorySize, SMEM_BN128);
    cudaFuncSetAttribute(mma_gemm<128,1>, cudaFuncAttributeMaxDynamicSharedMemorySize, SMEM_BN128);
    cudaFuncSetAttribute(mma_gemm<64,2>,  cudaFuncAttributeMaxDynamicSharedMemorySize, SMEM_BN64);

    // ---- setup, ordered so launch index 5 is a representative diffusion GEMM
    k_zero_f32<<<ROWS * 64 / 256, 256>>>(ph, (size_t)ROWS * 64);                        // 0
    k_zero_b16<<<(int)((size_t)ROWS * FPK / 256), 256>>>(pFh, (size_t)ROWS * FPK);      // 1
    k_zero_b16<<<(int)((size_t)ROWS * FPK / 256), 256>>>(pFl, (size_t)ROWS * FPK);      // 2
    k_zero_b16<<<(int)(((size_t)XTC * Nn + 255) / 256), 256>>>(pXh, (size_t)XTC * Nn);  // 3
    k_zero_b16<<<(int)(((size_t)XTC * Nn + 255) / 256), 256>>>(pXl, (size_t)XTC * Nn);  // 4
    // ncu target: real-shape diffusion (inputs deterministic; output overwritten)
    mma_gemm<128,0><<<dim3(33, 16), 256, SMEM_BN128>>>(pSeh, pSel, pSeh, pXh, pXh, pXl,
                                                       Nn, Nn, 1024, nullptr);          // 5
    k_pad_emb<<<64, 256>>>(emb);
    k_transpose<<<64, 256>>>(pEp, pEpT, Nn, 16);
    sgemm32<<<dim3(16, 8), 256>>>(pEp, pEpT, pSe, Nn, Nn, 16);
    k_relu_softmax<<<Nn, 256>>>(pSe);
    sgemm32<<<dim3(16, 8), 256>>>(pSe, pSe, pSe + NN2, Nn, Nn, Nn);
    k_cheb<<<NN2 / 256, 256>>>(pSe + NN2);
    k_split<<<2 * NN2 / 256, 256>>>(pSe, pSeh, pSel, (size_t)2 * NN2);
    k_pad_w_t<true><<<(128 * FPK + 255) / 256, 256>>>(egw, pWgeh, pWgel, 128);
    k_pad_w_t<true><<<(64 * FPK + 255) / 256, 256>>>(euw, pWueh, pWuel, 64);
    k_pad_w_t<false><<<(128 * FPK + 255) / 256, 256>>>(dgw, pWgdh, pWgdl, 128);
    k_pad_w_t<false><<<(64 * FPK + 255) / 256, 256>>>(duw, pWudh, pWudl, 64);

    // ---- encoder
    for (int t = 0; t < Tt; t++) {
        k_set_x_enc<<<256, 256>>>(x, t);
        mma_gemm<128,0><<<dim3(33, 16), 256, SMEM_BN128>>>(pSeh, pSel, pSeh, pXh, pXh, pXl,
                                                           Nn, Nn, 1024, nullptr);
        mma_gemm<128,1><<<dim3(1, 512), 256, SMEM_BN128>>>(pFh, pFl, pFh, pWgeh, pWgeh, pWgel,
                                                           FPK, FPK, 256, egb);
        mma_gemm<128,0><<<dim3(33, 16), 256, SMEM_BN128>>>(pSeh, pSel, pSeh, pXh, pXh, pXl,
                                                           Nn, Nn, 1024, nullptr);
        mma_gemm<64,2><<<dim3(1, 512), 256, SMEM_BN64>>>(pFh, pFl, pFh, pWueh, pWueh, pWuel,
                                                         FPK, FPK, 256, eub);
    }

    // ---- decoder supports
    k_demb<<<ROWS * Ee / 256, 256>>>(fce);
    k_transpose<<<ROWS * Ee / 256, 256>>>(pDemb, pDembT, Nn, Bb * Ee);
    sgemm32<<<dim3(16, 8), 256>>>(pDemb, pDembT, pSd, Nn, Nn, Bb * Ee);
    k_relu_softmax<<<Nn, 256>>>(pSd);
    sgemm32<<<dim3(16, 8), 256>>>(pSd, pSd, pSd + NN2, Nn, Nn, Nn);
    k_cheb<<<NN2 / 256, 256>>>(pSd + NN2);
    k_split<<<2 * NN2 / 256, 256>>>(pSd, pSdh, pSdl, (size_t)2 * NN2);
    k_init_go<<<256, 256>>>(x);

    // ---- decoder
    for (int t = 0; t < Hor; t++) {
        k_set_xy_dec<<<256, 256>>>(ycov, t);
        mma_gemm<128,0><<<dim3(33, 16), 256, SMEM_BN128>>>(pSdh, pSdl, pSdh, pXh, pXh, pXl,
                                                           Nn, Nn, 1024, nullptr);
        mma_gemm<128,1><<<dim3(1, 512), 256, SMEM_BN128>>>(pFh, pFl, pFh, pWgdh, pWgdh, pWgdl,
                                                           FPK, FPK, 256, dgb);
        mma_gemm<128,0><<<dim3(33, 16), 256, SMEM_BN128>>>(pSdh, pSdl, pSdh, pXh, pXh, pXl,
                                                           Nn, Nn, 1024, nullptr);
        mma_gemm<64,2><<<dim3(1, 512), 256, SMEM_BN64>>>(pFh, pFl, pFh, pWudh, pWudh, pWudl,
                                                         FPK, FPK, 256, dub);
        k_proj_out<<<256, 256>>>(pw, pb, out, t);
    }
}

// round 6
// speedup vs baseline: 1.8270x; 1.3512x over previous
#include <cuda_runtime.h>
#include <cuda_fp16.h>
#include <cstdint>
#include <math.h>

constexpr int Bb=64, Tt=12, Nn=1024, Ee=10, Hor=12;
constexpr int ROWS = Nn*Bb;          // 65536
constexpr int NN2  = Nn*Nn;
constexpr int FPK  = 256;            // padded K width of F (3*66=198 -> 256)
constexpr int XTC  = 66*Bb;          // 4224 = Xin^T row count (cols of Xin)

// ---------------- device-global scratch ----------------
__device__ __align__(1024) float g_S_enc[2*NN2];
__device__ __align__(1024) float g_S_dec[2*NN2];
__device__ __align__(1024) float g_R [(size_t)ROWS*64];
__device__ __align__(1024) float g_h [(size_t)ROWS*64];
__device__ __align__(1024) float g_go[ROWS];
__device__ __align__(1024) float g_demb [Nn*Bb*Ee];
__device__ __align__(1024) float g_dembT[Bb*Ee*Nn];
__device__ __align__(1024) float g_embpad [Nn*16];
__device__ __align__(1024) float g_embpadT[16*Nn];

__device__ __align__(1024) __half g_Se_hi[2*NN2], g_Se_lo[2*NN2];
__device__ __align__(1024) __half g_Sd_hi[2*NN2], g_Sd_lo[2*NN2];
__device__ __align__(1024) __half g_XT[(size_t)XTC*Nn];                 // single fp16
__device__ __align__(1024) __half g_F_hi[(size_t)ROWS*FPK], g_F_lo[(size_t)ROWS*FPK];
__device__ __align__(1024) __half g_Wge_hi[128*FPK], g_Wge_lo[128*FPK];
__device__ __align__(1024) __half g_Wue_hi[64*FPK],  g_Wue_lo[64*FPK];
__device__ __align__(1024) __half g_Wgd_hi[128*FPK], g_Wgd_lo[128*FPK];
__device__ __align__(1024) __half g_Wud_hi[64*FPK],  g_Wud_lo[64*FPK];

__device__ __forceinline__ float sigmoidf_(float x){ return 1.0f/(1.0f+expf(-x)); }
__device__ __forceinline__ void split_h(float v, __half& hi, __half& lo){
    hi = __float2half_rn(v);
    lo = __float2half_rn(v - __half2float(hi));
}

__device__ __forceinline__ uint32_t smem_u32(const void* p){
    uint32_t a;
    asm("{ .reg .u64 t; cvta.to.shared.u64 t, %1; cvt.u32.u64 %0, t; }" : "=r"(a) : "l"(p));
    return a;
}
__device__ __forceinline__ void cp_async16(uint32_t dst, const void* src){
    asm volatile("cp.async.cg.shared.global [%0], [%1], 16;" :: "r"(dst), "l"(src));
}
__device__ __forceinline__ void cp_commit(){ asm volatile("cp.async.commit_group;"); }
template <int N>
__device__ __forceinline__ void cp_wait(){ asm volatile("cp.async.wait_group %0;" :: "n"(N)); }

__device__ __forceinline__ void ldsm_x4(uint32_t* r, uint32_t addr){
    asm volatile("ldmatrix.sync.aligned.m8n8.x4.shared.b16 {%0,%1,%2,%3}, [%4];"
        : "=r"(r[0]), "=r"(r[1]), "=r"(r[2]), "=r"(r[3]) : "r"(addr));
}
__device__ __forceinline__ void mma16816(float* c, const uint32_t* a, const uint32_t* b){
    asm volatile("mma.sync.aligned.m16n8k16.row.col.f32.f16.f16.f32 "
        "{%0,%1,%2,%3}, {%4,%5,%6,%7}, {%8,%9}, {%0,%1,%2,%3};"
        : "+f"(c[0]), "+f"(c[1]), "+f"(c[2]), "+f"(c[3])
        : "r"(a[0]), "r"(a[1]), "r"(a[2]), "r"(a[3]), "r"(b[0]), "r"(b[1]));
}

// ---------------- fp16 split-K HMMA GEMM (3-stage cp.async pipeline) --------
// D[M rows, N=BN per block] = sum over NSEG segments Aseg(M x segK) @ Bseg^T,
// fp32 accumulate. A rows = output rows (lda elems); B rows = output COLUMNS,
// K-major (ldb elems). BM=128, BK=64, 256 threads (8 warps, 4m x 2n).
// EPI 0: diffusion -> fp16 hi/lo split-scatter into g_F
// EPI 1: gate: z=sig(+bias), c<64 -> z*h into g_XT (single) + g_F (hi/lo);
//        c>=64 -> g_R
// EPI 2: update: hc=tanh(+bias); hn = r*h + (1-r)*hc -> g_h, g_XT, g_F
template <int BN, int EPI, int NSEG>
__global__ void __launch_bounds__(256) mma_gemm(
    const __half* __restrict__ A0, const __half* __restrict__ A1,
    const __half* __restrict__ A2,
    const __half* __restrict__ B0, const __half* __restrict__ B1,
    const __half* __restrict__ B2,
    int lda, int ldb, int segK, const float* __restrict__ bias)
{
    constexpr int BM = 128, LDS = 72;      // 64 + 8 pad (half elems)
    constexpr int NT = BN / 16;            // n8-tiles per warp (8 or 4)
    constexpr uint32_t STG_BYTES = (uint32_t)(BM + BN) * LDS * 2u;
    extern __shared__ __align__(16) char sm[];
    const uint32_t sm0 = smem_u32(sm);

    const int tid = threadIdx.x, lane = tid & 31, wid = tid >> 5;
    const int wm = wid >> 1, wn = wid & 1;
    const int m0 = blockIdx.y * BM, n0 = blockIdx.x * BN;

    const __half* Asg[3] = {A0, A1, A2};
    const __half* Bsg[3] = {B0, B1, B2};
    const int nt_seg = segK >> 6;
    const int KT = NSEG * nt_seg;

    float acc[2][NT][4];
#pragma unroll
    for (int i = 0; i < 2; i++)
#pragma unroll
        for (int j = 0; j < NT; j++)
#pragma unroll
            for (int e = 0; e < 4; e++) acc[i][j][e] = 0.0f;

    const uint32_t aOff = (((uint32_t)(wm*32 + (lane & 15))) * LDS + ((lane >> 4) << 3)) * 2u;
    const uint32_t bOff = (uint32_t)BM * LDS * 2u
        + (((uint32_t)(wn*(BN/2) + (lane & 7) + ((lane >> 4) << 3))) * LDS
           + (((lane >> 3) & 1) << 3)) * 2u;

    auto load_tile = [&](int kt, int stg) {
        const uint32_t sA = sm0 + (uint32_t)stg * STG_BYTES;
        const uint32_t sB = sA + (uint32_t)BM * LDS * 2u;
        int seg = kt / nt_seg;
        int j = kt - seg * nt_seg;
        const char* Ag = (const char*)(Asg[seg] + (size_t)m0 * lda + j * 64);
        const char* Bg = (const char*)(Bsg[seg] + (size_t)n0 * ldb + j * 64);
#pragma unroll
        for (int it = 0; it < 4; it++) {
            int id = (it << 8) + tid;
            int r = id >> 3, c = id & 7;
            cp_async16(sA + (uint32_t)r*144u + (uint32_t)c*16u,
                       Ag + (size_t)r * ((size_t)lda*2) + c*16);
        }
#pragma unroll
        for (int it = 0; it < BN/32; it++) {
            int id = (it << 8) + tid;
            int r = id >> 3, c = id & 7;
            cp_async16(sB + (uint32_t)r*144u + (uint32_t)c*16u,
                       Bg + (size_t)r * ((size_t)ldb*2) + c*16);
        }
        cp_commit();
    };

    load_tile(0, 0);
    if (KT > 1) load_tile(1, 1);

    int stg = 0;
    for (int kt = 0; kt < KT; kt++) {
        if (kt + 1 < KT) cp_wait<1>(); else cp_wait<0>();
        __syncthreads();
        if (kt + 2 < KT) load_tile(kt + 2, (kt + 2) % 3);

        const uint32_t sbase = sm0 + (uint32_t)stg * STG_BYTES;
        const uint32_t aBase = sbase + aOff;
        const uint32_t bBase = sbase + bOff;
#pragma unroll
        for (int ks = 0; ks < 4; ks++) {
            uint32_t a[2][4];
            ldsm_x4(a[0], aBase + (uint32_t)ks*32u);
            ldsm_x4(a[1], aBase + 16u*LDS*2u + (uint32_t)ks*32u);
            uint32_t b[NT/2][4];
#pragma unroll
            for (int p = 0; p < NT/2; p++)
                ldsm_x4(b[p], bBase + (uint32_t)p*16u*LDS*2u + (uint32_t)ks*32u);
#pragma unroll
            for (int mt = 0; mt < 2; mt++)
#pragma unroll
                for (int nt = 0; nt < NT; nt++)
                    mma16816(acc[mt][nt], a[mt], &b[nt >> 1][(nt & 1) * 2]);
        }
        if (++stg == 3) stg = 0;
    }

    // ---------------- epilogue ----------------
    const int rbase = m0 + wm*32 + (lane >> 2);
    const int cbase = n0 + wn*(BN/2) + ((lane & 3) << 1);
#pragma unroll
    for (int mt = 0; mt < 2; mt++) {
#pragma unroll
        for (int nt = 0; nt < NT; nt++) {
#pragma unroll
            for (int e = 0; e < 4; e++) {
                const int row = rbase + mt*16 + ((e >> 1) << 3);
                const int col = cbase + nt*8 + (e & 1);
                const float v = acc[mt][nt][e];
                if (EPI == 0) {
                    const int kk = row >> 10, n = row & 1023;
                    const int b = col / 66, c = col - b * 66;
                    __half hi, lo; split_h(v, hi, lo);
                    const size_t off = (size_t)((n << 6) + b) * FPK + (kk + 1) * 66 + c;
                    g_F_hi[off] = hi; g_F_lo[off] = lo;
                } else if (EPI == 1) {
                    const int id = row, n = row >> 6, b = row & 63;
                    const float s = sigmoidf_(v + bias[col]);
                    if (col < 64) {
                        const float zh = s * g_h[(size_t)id * 64 + col];
                        __half hi, lo; split_h(zh, hi, lo);
                        g_XT[((size_t)(b * 66 + 2 + col) << 10) + n] = hi;
                        const size_t fo = ((size_t)id << 8) + 2 + col;
                        g_F_hi[fo] = hi; g_F_lo[fo] = lo;
                    } else {
                        g_R[(size_t)id * 64 + (col - 64)] = s;
                    }
                } else {
                    const int id = row, n = row >> 6, b = row & 63;
                    const float hc = tanhf(v + bias[col]);
                    const size_t o = (size_t)id * 64 + col;
                    const float r = g_R[o], h = g_h[o];
                    const float hn = r * h + (1.0f - r) * hc;
                    g_h[o] = hn;
                    __half hi, lo; split_h(hn, hi, lo);
                    g_XT[((size_t)(b * 66 + 2 + col) << 10) + n] = hi;
                    const size_t fo = ((size_t)id << 8) + 2 + col;
                    g_F_hi[fo] = hi; g_F_lo[fo] = lo;
                }
            }
        }
    }
}

// ---------------- fp32 SGEMM (setup only) ----------------
__global__ void __launch_bounds__(256) sgemm32(
    const float* __restrict__ A, const float* __restrict__ B,
    float* __restrict__ C, int M, int N, int K)
{
    constexpr int BM = 128, BN = 64, BK = 16;
    __shared__ __align__(16) float As_[BK][BM];
    __shared__ __align__(16) float Bs_[BK][BN];
    const int tid = threadIdx.x;
    const int tx = tid & 15, ty = tid >> 4;
    const int m0 = blockIdx.y * BM, n0 = blockIdx.x * BN;
    float acc[8][4];
#pragma unroll
    for (int i = 0; i < 8; i++)
#pragma unroll
        for (int jj = 0; jj < 4; jj++) acc[i][jj] = 0.0f;
    const int arow0 = tid >> 2, acol0 = (tid & 3) * 4;
    const int brow = tid >> 4, bcol = (tid & 15) * 4;
    for (int kt = 0; kt < K; kt += BK) {
#pragma unroll
        for (int i = 0; i < 2; i++) {
            int r = arow0 + i * 64;
            float4 v = *reinterpret_cast<const float4*>(A + (size_t)(m0 + r) * K + kt + acol0);
            As_[acol0+0][r]=v.x; As_[acol0+1][r]=v.y; As_[acol0+2][r]=v.z; As_[acol0+3][r]=v.w;
        }
        float4 bv = *reinterpret_cast<const float4*>(B + (size_t)(kt + brow) * N + n0 + bcol);
        *reinterpret_cast<float4*>(&Bs_[brow][bcol]) = bv;
        __syncthreads();
#pragma unroll
        for (int k = 0; k < BK; k++) {
            float4 a0 = *reinterpret_cast<const float4*>(&As_[k][ty*8]);
            float4 a1 = *reinterpret_cast<const float4*>(&As_[k][ty*8+4]);
            float4 b0 = *reinterpret_cast<const float4*>(&Bs_[k][tx*4]);
            float am[8]={a0.x,a0.y,a0.z,a0.w,a1.x,a1.y,a1.z,a1.w};
            float bn[4]={b0.x,b0.y,b0.z,b0.w};
#pragma unroll
            for (int i = 0; i < 8; i++)
#pragma unroll
                for (int jj = 0; jj < 4; jj++) acc[i][jj] = fmaf(am[i], bn[jj], acc[i][jj]);
        }
        __syncthreads();
    }
#pragma unroll
    for (int i = 0; i < 8; i++) {
        float4 v = make_float4(acc[i][0], acc[i][1], acc[i][2], acc[i][3]);
        *reinterpret_cast<float4*>(C + (size_t)(m0 + ty*8 + i) * N + n0 + tx*4) = v;
    }
}

// ---------------- elementwise helpers ----------------
__global__ void k_zero_f32(float* p, size_t n) {
    size_t i = (size_t)blockIdx.x * blockDim.x + threadIdx.x;
    if (i < n) p[i] = 0.0f;
}
__global__ void k_zero_h(__half* p, size_t n) {
    size_t i = (size_t)blockIdx.x * blockDim.x + threadIdx.x;
    if (i < n) p[i] = __float2half_rn(0.0f);
}
__global__ void k_split_h(const float* __restrict__ s, __half* __restrict__ hi,
                          __half* __restrict__ lo, size_t n) {
    size_t i = (size_t)blockIdx.x * blockDim.x + threadIdx.x;
    if (i >= n) return;
    __half h, l; split_h(s[i], h, l);
    hi[i] = h; lo[i] = l;
}
__global__ void k_pad_emb(const float* __restrict__ emb) {
    int idx = blockIdx.x * blockDim.x + threadIdx.x;
    if (idx >= Nn * 16) return;
    int n = idx >> 4, j = idx & 15;
    g_embpad[idx] = (j < Ee) ? emb[n * Ee + j] : 0.0f;
}
__global__ void k_transpose(const float* __restrict__ in, float* __restrict__ out,
                            int R, int C) {
    int idx = blockIdx.x * blockDim.x + threadIdx.x;
    if (idx >= R * C) return;
    int r = idx / C, c = idx - r * C;
    out[c * R + r] = in[idx];
}
template <bool ENC>
__global__ void k_pad_w_t(const float* __restrict__ src, __half* __restrict__ hi,
                          __half* __restrict__ lo, int nout) {
    int idx = blockIdx.x * blockDim.x + threadIdx.x;
    if (idx >= nout * FPK) return;
    int n = idx >> 8, f = idx & 255;
    float v = 0.0f;
    if (f < 198) {
        int k = f / 66, c = f - k * 66;
        if (ENC) {
            if (c == 0) v = src[(k * 65) * nout + n];
            else if (c >= 2) v = src[(k * 65 + c - 1) * nout + n];
        } else {
            v = src[f * nout + n];
        }
    }
    __half h, l; split_h(v, h, l);
    hi[idx] = h; lo[idx] = l;
}
__global__ void k_relu_softmax(float* __restrict__ S) {
    int row = blockIdx.x;
    float* p = S + (size_t)row * Nn;
    int t = threadIdx.x;
    float v[4];
#pragma unroll
    for (int i = 0; i < 4; i++) { float x = p[t + i*256]; v[i] = x > 0.0f ? x : 0.0f; }
    __shared__ float red[256];
    float m = fmaxf(fmaxf(v[0], v[1]), fmaxf(v[2], v[3]));
    red[t] = m; __syncthreads();
    for (int s = 128; s > 0; s >>= 1) { if (t < s) red[t] = fmaxf(red[t], red[t+s]); __syncthreads(); }
    m = red[0]; __syncthreads();
    float e[4], sum = 0.0f;
#pragma unroll
    for (int i = 0; i < 4; i++) { e[i] = expf(v[i] - m); sum += e[i]; }
    red[t] = sum; __syncthreads();
    for (int s = 128; s > 0; s >>= 1) { if (t < s) red[t] += red[t+s]; __syncthreads(); }
    float inv = 1.0f / red[0];
#pragma unroll
    for (int i = 0; i < 4; i++) p[t + i*256] = e[i] * inv;
}
__global__ void k_cheb(float* __restrict__ P) {
    int idx = blockIdx.x * blockDim.x + threadIdx.x;
    if (idx >= NN2) return;
    int r = idx >> 10, c = idx & 1023;
    P[idx] = 2.0f * P[idx] - (r == c ? 1.0f : 0.0f);
}
__global__ void k_set_x_enc(const float* __restrict__ x, int t) {
    int id = blockIdx.x * blockDim.x + threadIdx.x;
    if (id >= ROWS) return;
    int n = id >> 6, b = id & 63;
    float xv = x[((size_t)b * Tt + t) * Nn + n];
    __half xh, xl; split_h(xv, xh, xl);
    g_XT[((size_t)(b * 66) << 10) + n] = xh;
    size_t fo = (size_t)id << 8;
    g_F_hi[fo] = xh; g_F_lo[fo] = xl;
}
__global__ void k_set_xy_dec(const float* __restrict__ ycov, int t) {
    int id = blockIdx.x * blockDim.x + threadIdx.x;
    if (id >= ROWS) return;
    int n = id >> 6, b = id & 63;
    float gv = g_go[id];
    float yv = ycov[((size_t)b * Hor + t) * Nn + n];
    __half gh, gl, yh, yl;
    split_h(gv, gh, gl);
    split_h(yv, yh, yl);
    g_XT[((size_t)(b * 66) << 10) + n] = gh;
    g_XT[((size_t)(b * 66 + 1) << 10) + n] = yh;
    size_t fo = (size_t)id << 8;
    g_F_hi[fo] = gh;     g_F_lo[fo] = gl;
    g_F_hi[fo + 1] = yh; g_F_lo[fo + 1] = yl;
}
__global__ void k_demb(const float* __restrict__ fce) {
    int idx = blockIdx.x * blockDim.x + threadIdx.x;
    if (idx >= ROWS * Ee) return;
    int id = idx / Ee, e = idx - id * Ee;
    const float* hr = g_h + (size_t)id * 64;
    float s = 0.0f;
#pragma unroll
    for (int h = 0; h < 64; h++) s = fmaf(hr[h], fce[h * Ee + e], s);
    g_demb[idx] = s;
}
__global__ void k_init_go(const float* __restrict__ x) {
    int id = blockIdx.x * blockDim.x + threadIdx.x;
    if (id >= ROWS) return;
    int n = id >> 6, b = id & 63;
    g_go[id] = x[((size_t)b * Tt + (Tt - 1)) * Nn + n];
}
__global__ void k_proj_out(const float* __restrict__ pw, const float* __restrict__ pb,
                           float* __restrict__ out, int t) {
    int id = blockIdx.x * blockDim.x + threadIdx.x;
    if (id >= ROWS) return;
    int n = id >> 6, b = id & 63;
    const float* hr = g_h + (size_t)id * 64;
    float s = pb[0];
#pragma unroll
    for (int i = 0; i < 64; i++) s = fmaf(hr[i], pw[i], s);
    g_go[id] = s;
    out[((size_t)b * Hor + t) * Nn + n] = s;
}

// ---------------- orchestration ----------------
extern "C" void kernel_launch(void* const* d_in, const int* in_sizes, int n_in,
                              void* d_out, int out_size) {
    const float* x    = (const float*)d_in[0];
    const float* ycov = (const float*)d_in[1];
    const float* emb  = (const float*)d_in[2];
    const float* fce  = (const float*)d_in[3];
    const float* egw  = (const float*)d_in[4];
    const float* egb  = (const float*)d_in[5];
    const float* euw  = (const float*)d_in[6];
    const float* eub  = (const float*)d_in[7];
    const float* dgw  = (const float*)d_in[8];
    const float* dgb  = (const float*)d_in[9];
    const float* duw  = (const float*)d_in[10];
    const float* dub  = (const float*)d_in[11];
    const float* pw   = (const float*)d_in[12];
    const float* pb   = (const float*)d_in[13];
    float* out = (float*)d_out;

    float *pSe, *pSd, *ph, *pDemb, *pDembT, *pEp, *pEpT;
    __half *pSeh, *pSel, *pSdh, *pSdl, *pX, *pFh, *pFl;
    __half *pWgeh, *pWgel, *pWueh, *pWuel, *pWgdh, *pWgdl, *pWudh, *pWudl;
    cudaGetSymbolAddress((void**)&pSe, g_S_enc);
    cudaGetSymbolAddress((void**)&pSd, g_S_dec);
    cudaGetSymbolAddress((void**)&ph, g_h);
    cudaGetSymbolAddress((void**)&pDemb, g_demb);
    cudaGetSymbolAddress((void**)&pDembT, g_dembT);
    cudaGetSymbolAddress((void**)&pEp, g_embpad);
    cudaGetSymbolAddress((void**)&pEpT, g_embpadT);
    cudaGetSymbolAddress((void**)&pSeh, g_Se_hi); cudaGetSymbolAddress((void**)&pSel, g_Se_lo);
    cudaGetSymbolAddress((void**)&pSdh, g_Sd_hi); cudaGetSymbolAddress((void**)&pSdl, g_Sd_lo);
    cudaGetSymbolAddress((void**)&pX, g_XT);
    cudaGetSymbolAddress((void**)&pFh, g_F_hi);   cudaGetSymbolAddress((void**)&pFl, g_F_lo);
    cudaGetSymbolAddress((void**)&pWgeh, g_Wge_hi); cudaGetSymbolAddress((void**)&pWgel, g_Wge_lo);
    cudaGetSymbolAddress((void**)&pWueh, g_Wue_hi); cudaGetSymbolAddress((void**)&pWuel, g_Wue_lo);
    cudaGetSymbolAddress((void**)&pWgdh, g_Wgd_hi); cudaGetSymbolAddress((void**)&pWgdl, g_Wgd_lo);
    cudaGetSymbolAddress((void**)&pWudh, g_Wud_hi); cudaGetSymbolAddress((void**)&pWudl, g_Wud_lo);

    constexpr int SMEM_BN128 = 3 * (128 + 128) * 72 * 2;  // 110592
    constexpr int SMEM_BN64  = 3 * (128 + 64) * 72 * 2;   // 82944
    cudaFuncSetAttribute(mma_gemm<128,0,2>, cudaFuncAttributeMaxDynamicSharedMemorySize, SMEM_BN128);
    cudaFuncSetAttribute(mma_gemm<128,1,3>, cudaFuncAttributeMaxDynamicSharedMemorySize, SMEM_BN128);
    cudaFuncSetAttribute(mma_gemm<64,2,3>,  cudaFuncAttributeMaxDynamicSharedMemorySize, SMEM_BN64);

    // ---- setup; launch index 3 (0-based) == diffusion GEMM for ncu
    k_zero_h<<<(int)(((size_t)XTC * Nn + 255) / 256), 256>>>(pX, (size_t)XTC * Nn);     // 0
    k_zero_h<<<(int)((size_t)ROWS * FPK / 256), 256>>>(pFh, (size_t)ROWS * FPK);        // 1
    k_zero_h<<<(int)((size_t)ROWS * FPK / 256), 256>>>(pFl, (size_t)ROWS * FPK);        // 2
    // ncu target: real-shape diffusion (inputs deterministic; output overwritten)
    mma_gemm<128,0,2><<<dim3(33, 16), 256, SMEM_BN128>>>(pSeh, pSel, pSeh, pX, pX, pX,
                                                         Nn, Nn, 1024, nullptr);        // 3
    k_zero_f32<<<ROWS * 64 / 256, 256>>>(ph, (size_t)ROWS * 64);
    k_pad_emb<<<64, 256>>>(emb);
    k_transpose<<<64, 256>>>(pEp, pEpT, Nn, 16);
    sgemm32<<<dim3(16, 8), 256>>>(pEp, pEpT, pSe, Nn, Nn, 16);
    k_relu_softmax<<<Nn, 256>>>(pSe);
    sgemm32<<<dim3(16, 8), 256>>>(pSe, pSe, pSe + NN2, Nn, Nn, Nn);
    k_cheb<<<NN2 / 256, 256>>>(pSe + NN2);
    k_split_h<<<2 * NN2 / 256, 256>>>(pSe, pSeh, pSel, (size_t)2 * NN2);
    k_pad_w_t<true><<<(128 * FPK + 255) / 256, 256>>>(egw, pWgeh, pWgel, 128);
    k_pad_w_t<true><<<(64 * FPK + 255) / 256, 256>>>(euw, pWueh, pWuel, 64);
    k_pad_w_t<false><<<(128 * FPK + 255) / 256, 256>>>(dgw, pWgdh, pWgdl, 128);
    k_pad_w_t<false><<<(64 * FPK + 255) / 256, 256>>>(duw, pWudh, pWudl, 64);

    // ---- encoder
    for (int t = 0; t < Tt; t++) {
        k_set_x_enc<<<256, 256>>>(x, t);
        mma_gemm<128,0,2><<<dim3(33, 16), 256, SMEM_BN128>>>(pSeh, pSel, pSeh, pX, pX, pX,
                                                             Nn, Nn, 1024, nullptr);
        mma_gemm<128,1,3><<<dim3(1, 512), 256, SMEM_BN128>>>(pFh, pFl, pFh, pWgeh, pWgeh, pWgel,
                                                             FPK, FPK, 256, egb);
        mma_gemm<128,0,2><<<dim3(33, 16), 256, SMEM_BN128>>>(pSeh, pSel, pSeh, pX, pX, pX,
                                                             Nn, Nn, 1024, nullptr);
        mma_gemm<64,2,3><<<dim3(1, 512), 256, SMEM_BN64>>>(pFh, pFl, pFh, pWueh, pWueh, pWuel,
                                                           FPK, FPK, 256, eub);
    }

    // ---- decoder supports
    k_demb<<<ROWS * Ee / 256, 256>>>(fce);
    k_transpose<<<ROWS * Ee / 256, 256>>>(pDemb, pDembT, Nn, Bb * Ee);
    sgemm32<<<dim3(16, 8), 256>>>(pDemb, pDembT, pSd, Nn, Nn, Bb * Ee);
    k_relu_softmax<<<Nn, 256>>>(pSd);
    sgemm32<<<dim3(16, 8), 256>>>(pSd, pSd, pSd + NN2, Nn, Nn, Nn);
    k_cheb<<<NN2 / 256, 256>>>(pSd + NN2);
    k_split_h<<<2 * NN2 / 256, 256>>>(pSd, pSdh, pSdl, (size_t)2 * NN2);
    k_init_go<<<256, 256>>>(x);

    // ---- decoder
    for (int t = 0; t < Hor; t++) {
        k_set_xy_dec<<<256, 256>>>(ycov, t);
        mma_gemm<128,0,2><<<dim3(33, 16), 256, SMEM_BN128>>>(pSdh, pSdl, pSdh, pX, pX, pX,
                                                             Nn, Nn, 1024, nullptr);
        mma_gemm<128,1,3><<<dim3(1, 512), 256, SMEM_BN128>>>(pFh, pFl, pFh, pWgdh, pWgdh, pWgdl,
                                                             FPK, FPK, 256, dgb);
        mma_gemm<128,0,2><<<dim3(33, 16), 256, SMEM_BN128>>>(pSdh, pSdl, pSdh, pX, pX, pX,
                                                             Nn, Nn, 1024, nullptr);
        mma_gemm<64,2,3><<<dim3(1, 512), 256, SMEM_BN64>>>(pFh, pFl, pFh, pWudh, pWudh, pWudl,
                                                           FPK, FPK, 256, dub);
        k_proj_out<<<256, 256>>>(pw, pb, out, t);
    }
}

// round 7
// speedup vs baseline: 1.9996x; 1.0945x over previous
#include <cuda_runtime.h>
#include <cuda_fp16.h>
#include <cstdint>
#include <math.h>

constexpr int Bb=64, Tt=12, Nn=1024, Ee=10, Hor=12;
constexpr int ROWS = Nn*Bb;          // 65536
constexpr int NN2  = Nn*Nn;
constexpr int FPK  = 256;            // padded K width of F (3*66=198 -> 256)
constexpr int XTC  = 66*Bb;          // 4224 = Xin^T row count (cols of Xin)

// ---------------- device-global scratch ----------------
__device__ __align__(1024) float g_S_enc[2*NN2];
__device__ __align__(1024) float g_S_dec[2*NN2];
__device__ __align__(1024) float g_R [(size_t)ROWS*64];
__device__ __align__(1024) float g_h [(size_t)ROWS*64];
__device__ __align__(1024) float g_go[ROWS];
__device__ __align__(1024) float g_demb [Nn*Bb*Ee];
__device__ __align__(1024) float g_dembT[Bb*Ee*Nn];
__device__ __align__(1024) float g_embpad [Nn*16];
__device__ __align__(1024) float g_embpadT[16*Nn];

__device__ __align__(1024) __half g_Se_hi[2*NN2], g_Se_lo[2*NN2];
__device__ __align__(1024) __half g_Sd_hi[2*NN2], g_Sd_lo[2*NN2];
__device__ __align__(1024) __half g_XT[(size_t)XTC*Nn];                 // single fp16
__device__ __align__(1024) __half g_F_hi[(size_t)ROWS*FPK], g_F_lo[(size_t)ROWS*FPK];
__device__ __align__(1024) __half g_Wge_hi[128*FPK], g_Wge_lo[128*FPK];
__device__ __align__(1024) __half g_Wue_hi[64*FPK],  g_Wue_lo[64*FPK];
__device__ __align__(1024) __half g_Wgd_hi[128*FPK], g_Wgd_lo[128*FPK];
__device__ __align__(1024) __half g_Wud_hi[64*FPK],  g_Wud_lo[64*FPK];

__device__ __forceinline__ float sigmoidf_(float x){ return 1.0f/(1.0f+expf(-x)); }
__device__ __forceinline__ void split_h(float v, __half& hi, __half& lo){
    hi = __float2half_rn(v);
    lo = __float2half_rn(v - __half2float(hi));
}

__device__ __forceinline__ uint32_t smem_u32(const void* p){
    uint32_t a;
    asm("{ .reg .u64 t; cvta.to.shared.u64 t, %1; cvt.u32.u64 %0, t; }" : "=r"(a) : "l"(p));
    return a;
}
__device__ __forceinline__ void cp_async16(uint32_t dst, const void* src){
    asm volatile("cp.async.cg.shared.global [%0], [%1], 16;" :: "r"(dst), "l"(src));
}
__device__ __forceinline__ void cp_commit(){ asm volatile("cp.async.commit_group;"); }
template <int N>
__device__ __forceinline__ void cp_wait(){ asm volatile("cp.async.wait_group %0;" :: "n"(N)); }

__device__ __forceinline__ void ldsm_x4(uint32_t* r, uint32_t addr){
    asm volatile("ldmatrix.sync.aligned.m8n8.x4.shared.b16 {%0,%1,%2,%3}, [%4];"
        : "=r"(r[0]), "=r"(r[1]), "=r"(r[2]), "=r"(r[3]) : "r"(addr));
}
__device__ __forceinline__ void mma16816(float* c, const uint32_t* a, const uint32_t* b){
    asm volatile("mma.sync.aligned.m16n8k16.row.col.f32.f16.f16.f32 "
        "{%0,%1,%2,%3}, {%4,%5,%6,%7}, {%8,%9}, {%0,%1,%2,%3};"
        : "+f"(c[0]), "+f"(c[1]), "+f"(c[2]), "+f"(c[3])
        : "r"(a[0]), "r"(a[1]), "r"(a[2]), "r"(a[3]), "r"(b[0]), "r"(b[1]));
}

// ---------------- fp16 split-K HMMA GEMM (3-stage, 2 CTAs/SM) ---------------
// D[M rows, N=BN per block] = sum over NSEG segments Aseg(M x segK) @ Bseg^T,
// fp32 accumulate. A rows = output rows (lda elems); B rows = output COLUMNS,
// K-major (ldb elems). BM=128, BK=64, 256 threads (8 warps, 4m x 2n).
// __launch_bounds__(256, 2): cap regs at 128 so 2 CTAs/SM fit (was 138 -> 1 CTA).
// EPI 0: diffusion -> fp16 hi/lo split-scatter into g_F
// EPI 1: gate: z=sig(+bias), c<64 -> z*h into g_XT (single) + g_F (hi/lo);
//        c>=64 -> g_R
// EPI 2: update: hc=tanh(+bias); hn = r*h + (1-r)*hc -> g_h, g_XT, g_F
template <int BN, int EPI, int NSEG>
__global__ void __launch_bounds__(256, 2) mma_gemm(
    const __half* __restrict__ A0, const __half* __restrict__ A1,
    const __half* __restrict__ A2,
    const __half* __restrict__ B0, const __half* __restrict__ B1,
    const __half* __restrict__ B2,
    int lda, int ldb, int segK, const float* __restrict__ bias)
{
    constexpr int BM = 128, LDS = 72;      // 64 + 8 pad (half elems)
    constexpr int NT = BN / 16;            // n8-tiles per warp (8 or 4)
    constexpr uint32_t STG_BYTES = (uint32_t)(BM + BN) * LDS * 2u;
    extern __shared__ __align__(16) char sm[];
    const uint32_t sm0 = smem_u32(sm);

    const int tid = threadIdx.x, lane = tid & 31, wid = tid >> 5;
    const int wm = wid >> 1, wn = wid & 1;
    const int m0 = blockIdx.y * BM, n0 = blockIdx.x * BN;

    const __half* Asg[3] = {A0, A1, A2};
    const __half* Bsg[3] = {B0, B1, B2};
    const int nt_seg = segK >> 6;
    const int KT = NSEG * nt_seg;

    float acc[2][NT][4];
#pragma unroll
    for (int i = 0; i < 2; i++)
#pragma unroll
        for (int j = 0; j < NT; j++)
#pragma unroll
            for (int e = 0; e < 4; e++) acc[i][j][e] = 0.0f;

    const uint32_t aOff = (((uint32_t)(wm*32 + (lane & 15))) * LDS + ((lane >> 4) << 3)) * 2u;
    const uint32_t bOff = (uint32_t)BM * LDS * 2u
        + (((uint32_t)(wn*(BN/2) + (lane & 7) + ((lane >> 4) << 3))) * LDS
           + (((lane >> 3) & 1) << 3)) * 2u;

    auto load_tile = [&](int kt, int stg) {
        const uint32_t sA = sm0 + (uint32_t)stg * STG_BYTES;
        const uint32_t sB = sA + (uint32_t)BM * LDS * 2u;
        int seg = kt / nt_seg;
        int j = kt - seg * nt_seg;
        const char* Ag = (const char*)(Asg[seg] + (size_t)m0 * lda + j * 64);
        const char* Bg = (const char*)(Bsg[seg] + (size_t)n0 * ldb + j * 64);
#pragma unroll
        for (int it = 0; it < 4; it++) {
            int id = (it << 8) + tid;
            int r = id >> 3, c = id & 7;
            cp_async16(sA + (uint32_t)r*144u + (uint32_t)c*16u,
                       Ag + (size_t)r * ((size_t)lda*2) + c*16);
        }
#pragma unroll
        for (int it = 0; it < BN/32; it++) {
            int id = (it << 8) + tid;
            int r = id >> 3, c = id & 7;
            cp_async16(sB + (uint32_t)r*144u + (uint32_t)c*16u,
                       Bg + (size_t)r * ((size_t)ldb*2) + c*16);
        }
        cp_commit();
    };

    load_tile(0, 0);
    if (KT > 1) load_tile(1, 1);

    int stg = 0;
    for (int kt = 0; kt < KT; kt++) {
        if (kt + 1 < KT) cp_wait<1>(); else cp_wait<0>();
        __syncthreads();
        if (kt + 2 < KT) load_tile(kt + 2, (kt + 2) % 3);

        const uint32_t sbase = sm0 + (uint32_t)stg * STG_BYTES;
        const uint32_t aBase = sbase + aOff;
        const uint32_t bBase = sbase + bOff;
#pragma unroll
        for (int ks = 0; ks < 4; ks++) {
            uint32_t a[2][4];
            ldsm_x4(a[0], aBase + (uint32_t)ks*32u);
            ldsm_x4(a[1], aBase + 16u*LDS*2u + (uint32_t)ks*32u);
            uint32_t b[NT/2][4];
#pragma unroll
            for (int p = 0; p < NT/2; p++)
                ldsm_x4(b[p], bBase + (uint32_t)p*16u*LDS*2u + (uint32_t)ks*32u);
#pragma unroll
            for (int mt = 0; mt < 2; mt++)
#pragma unroll
                for (int nt = 0; nt < NT; nt++)
                    mma16816(acc[mt][nt], a[mt], &b[nt >> 1][(nt & 1) * 2]);
        }
        if (++stg == 3) stg = 0;
    }

    // ---------------- epilogue ----------------
    const int rbase = m0 + wm*32 + (lane >> 2);
    const int cbase = n0 + wn*(BN/2) + ((lane & 3) << 1);
#pragma unroll
    for (int mt = 0; mt < 2; mt++) {
#pragma unroll
        for (int nt = 0; nt < NT; nt++) {
#pragma unroll
            for (int e = 0; e < 4; e++) {
                const int row = rbase + mt*16 + ((e >> 1) << 3);
                const int col = cbase + nt*8 + (e & 1);
                const float v = acc[mt][nt][e];
                if (EPI == 0) {
                    const int kk = row >> 10, n = row & 1023;
                    const int b = col / 66, c = col - b * 66;
                    __half hi, lo; split_h(v, hi, lo);
                    const size_t off = (size_t)((n << 6) + b) * FPK + (kk + 1) * 66 + c;
                    g_F_hi[off] = hi; g_F_lo[off] = lo;
                } else if (EPI == 1) {
                    const int id = row, n = row >> 6, b = row & 63;
                    const float s = sigmoidf_(v + bias[col]);
                    if (col < 64) {
                        const float zh = s * g_h[(size_t)id * 64 + col];
                        __half hi, lo; split_h(zh, hi, lo);
                        g_XT[((size_t)(b * 66 + 2 + col) << 10) + n] = hi;
                        const size_t fo = ((size_t)id << 8) + 2 + col;
                        g_F_hi[fo] = hi; g_F_lo[fo] = lo;
                    } else {
                        g_R[(size_t)id * 64 + (col - 64)] = s;
                    }
                } else {
                    const int id = row, n = row >> 6, b = row & 63;
                    const float hc = tanhf(v + bias[col]);
                    const size_t o = (size_t)id * 64 + col;
                    const float r = g_R[o], h = g_h[o];
                    const float hn = r * h + (1.0f - r) * hc;
                    g_h[o] = hn;
                    __half hi, lo; split_h(hn, hi, lo);
                    g_XT[((size_t)(b * 66 + 2 + col) << 10) + n] = hi;
                    const size_t fo = ((size_t)id << 8) + 2 + col;
                    g_F_hi[fo] = hi; g_F_lo[fo] = lo;
                }
            }
        }
    }
}

// ---------------- fp32 SGEMM (setup only) ----------------
__global__ void __launch_bounds__(256) sgemm32(
    const float* __restrict__ A, const float* __restrict__ B,
    float* __restrict__ C, int M, int N, int K)
{
    constexpr int BM = 128, BN = 64, BK = 16;
    __shared__ __align__(16) float As_[BK][BM];
    __shared__ __align__(16) float Bs_[BK][BN];
    const int tid = threadIdx.x;
    const int tx = tid & 15, ty = tid >> 4;
    const int m0 = blockIdx.y * BM, n0 = blockIdx.x * BN;
    float acc[8][4];
#pragma unroll
    for (int i = 0; i < 8; i++)
#pragma unroll
        for (int jj = 0; jj < 4; jj++) acc[i][jj] = 0.0f;
    const int arow0 = tid >> 2, acol0 = (tid & 3) * 4;
    const int brow = tid >> 4, bcol = (tid & 15) * 4;
    for (int kt = 0; kt < K; kt += BK) {
#pragma unroll
        for (int i = 0; i < 2; i++) {
            int r = arow0 + i * 64;
            float4 v = *reinterpret_cast<const float4*>(A + (size_t)(m0 + r) * K + kt + acol0);
            As_[acol0+0][r]=v.x; As_[acol0+1][r]=v.y; As_[acol0+2][r]=v.z; As_[acol0+3][r]=v.w;
        }
        float4 bv = *reinterpret_cast<const float4*>(B + (size_t)(kt + brow) * N + n0 + bcol);
        *reinterpret_cast<float4*>(&Bs_[brow][bcol]) = bv;
        __syncthreads();
#pragma unroll
        for (int k = 0; k < BK; k++) {
            float4 a0 = *reinterpret_cast<const float4*>(&As_[k][ty*8]);
            float4 a1 = *reinterpret_cast<const float4*>(&As_[k][ty*8+4]);
            float4 b0 = *reinterpret_cast<const float4*>(&Bs_[k][tx*4]);
            float am[8]={a0.x,a0.y,a0.z,a0.w,a1.x,a1.y,a1.z,a1.w};
            float bn[4]={b0.x,b0.y,b0.z,b0.w};
#pragma unroll
            for (int i = 0; i < 8; i++)
#pragma unroll
                for (int jj = 0; jj < 4; jj++) acc[i][jj] = fmaf(am[i], bn[jj], acc[i][jj]);
        }
        __syncthreads();
    }
#pragma unroll
    for (int i = 0; i < 8; i++) {
        float4 v = make_float4(acc[i][0], acc[i][1], acc[i][2], acc[i][3]);
        *reinterpret_cast<float4*>(C + (size_t)(m0 + ty*8 + i) * N + n0 + tx*4) = v;
    }
}

// ---------------- elementwise helpers ----------------
__global__ void k_zero_f32(float* p, size_t n) {
    size_t i = (size_t)blockIdx.x * blockDim.x + threadIdx.x;
    if (i < n) p[i] = 0.0f;
}
__global__ void k_zero_h(__half* p, size_t n) {
    size_t i = (size_t)blockIdx.x * blockDim.x + threadIdx.x;
    if (i < n) p[i] = __float2half_rn(0.0f);
}
__global__ void k_split_h(const float* __restrict__ s, __half* __restrict__ hi,
                          __half* __restrict__ lo, size_t n) {
    size_t i = (size_t)blockIdx.x * blockDim.x + threadIdx.x;
    if (i >= n) return;
    __half h, l; split_h(s[i], h, l);
    hi[i] = h; lo[i] = l;
}
__global__ void k_pad_emb(const float* __restrict__ emb) {
    int idx = blockIdx.x * blockDim.x + threadIdx.x;
    if (idx >= Nn * 16) return;
    int n = idx >> 4, j = idx & 15;
    g_embpad[idx] = (j < Ee) ? emb[n * Ee + j] : 0.0f;
}
__global__ void k_transpose(const float* __restrict__ in, float* __restrict__ out,
                            int R, int C) {
    int idx = blockIdx.x * blockDim.x + threadIdx.x;
    if (idx >= R * C) return;
    int r = idx / C, c = idx - r * C;
    out[c * R + r] = in[idx];
}
template <bool ENC>
__global__ void k_pad_w_t(const float* __restrict__ src, __half* __restrict__ hi,
                          __half* __restrict__ lo, int nout) {
    int idx = blockIdx.x * blockDim.x + threadIdx.x;
    if (idx >= nout * FPK) return;
    int n = idx >> 8, f = idx & 255;
    float v = 0.0f;
    if (f < 198) {
        int k = f / 66, c = f - k * 66;
        if (ENC) {
            if (c == 0) v = src[(k * 65) * nout + n];
            else if (c >= 2) v = src[(k * 65 + c - 1) * nout + n];
        } else {
            v = src[f * nout + n];
        }
    }
    __half h, l; split_h(v, h, l);
    hi[idx] = h; lo[idx] = l;
}
__global__ void k_relu_softmax(float* __restrict__ S) {
    int row = blockIdx.x;
    float* p = S + (size_t)row * Nn;
    int t = threadIdx.x;
    float v[4];
#pragma unroll
    for (int i = 0; i < 4; i++) { float x = p[t + i*256]; v[i] = x > 0.0f ? x : 0.0f; }
    __shared__ float red[256];
    float m = fmaxf(fmaxf(v[0], v[1]), fmaxf(v[2], v[3]));
    red[t] = m; __syncthreads();
    for (int s = 128; s > 0; s >>= 1) { if (t < s) red[t] = fmaxf(red[t], red[t+s]); __syncthreads(); }
    m = red[0]; __syncthreads();
    float e[4], sum = 0.0f;
#pragma unroll
    for (int i = 0; i < 4; i++) { e[i] = expf(v[i] - m); sum += e[i]; }
    red[t] = sum; __syncthreads();
    for (int s = 128; s > 0; s >>= 1) { if (t < s) red[t] += red[t+s]; __syncthreads(); }
    float inv = 1.0f / red[0];
#pragma unroll
    for (int i = 0; i < 4; i++) p[t + i*256] = e[i] * inv;
}
__global__ void k_cheb(float* __restrict__ P) {
    int idx = blockIdx.x * blockDim.x + threadIdx.x;
    if (idx >= NN2) return;
    int r = idx >> 10, c = idx & 1023;
    P[idx] = 2.0f * P[idx] - (r == c ? 1.0f : 0.0f);
}
__global__ void k_set_x_enc(const float* __restrict__ x, int t) {
    int id = blockIdx.x * blockDim.x + threadIdx.x;
    if (id >= ROWS) return;
    int n = id >> 6, b = id & 63;
    float xv = x[((size_t)b * Tt + t) * Nn + n];
    __half xh, xl; split_h(xv, xh, xl);
    g_XT[((size_t)(b * 66) << 10) + n] = xh;
    size_t fo = (size_t)id << 8;
    g_F_hi[fo] = xh; g_F_lo[fo] = xl;
}
__global__ void k_set_xy_dec(const float* __restrict__ ycov, int t) {
    int id = blockIdx.x * blockDim.x + threadIdx.x;
    if (id >= ROWS) return;
    int n = id >> 6, b = id & 63;
    float gv = g_go[id];
    float yv = ycov[((size_t)b * Hor + t) * Nn + n];
    __half gh, gl, yh, yl;
    split_h(gv, gh, gl);
    split_h(yv, yh, yl);
    g_XT[((size_t)(b * 66) << 10) + n] = gh;
    g_XT[((size_t)(b * 66 + 1) << 10) + n] = yh;
    size_t fo = (size_t)id << 8;
    g_F_hi[fo] = gh;     g_F_lo[fo] = gl;
    g_F_hi[fo + 1] = yh; g_F_lo[fo + 1] = yl;
}
__global__ void k_demb(const float* __restrict__ fce) {
    int idx = blockIdx.x * blockDim.x + threadIdx.x;
    if (idx >= ROWS * Ee) return;
    int id = idx / Ee, e = idx - id * Ee;
    const float* hr = g_h + (size_t)id * 64;
    float s = 0.0f;
#pragma unroll
    for (int h = 0; h < 64; h++) s = fmaf(hr[h], fce[h * Ee + e], s);
    g_demb[idx] = s;
}
__global__ void k_init_go(const float* __restrict__ x) {
    int id = blockIdx.x * blockDim.x + threadIdx.x;
    if (id >= ROWS) return;
    int n = id >> 6, b = id & 63;
    g_go[id] = x[((size_t)b * Tt + (Tt - 1)) * Nn + n];
}
__global__ void k_proj_out(const float* __restrict__ pw, const float* __restrict__ pb,
                           float* __restrict__ out, int t) {
    int id = blockIdx.x * blockDim.x + threadIdx.x;
    if (id >= ROWS) return;
    int n = id >> 6, b = id & 63;
    const float* hr = g_h + (size_t)id * 64;
    float s = pb[0];
#pragma unroll
    for (int i = 0; i < 64; i++) s = fmaf(hr[i], pw[i], s);
    g_go[id] = s;
    out[((size_t)b * Hor + t) * Nn + n] = s;
}

// ---------------- orchestration ----------------
extern "C" void kernel_launch(void* const* d_in, const int* in_sizes, int n_in,
                              void* d_out, int out_size) {
    const float* x    = (const float*)d_in[0];
    const float* ycov = (const float*)d_in[1];
    const float* emb  = (const float*)d_in[2];
    const float* fce  = (const float*)d_in[3];
    const float* egw  = (const float*)d_in[4];
    const float* egb  = (const float*)d_in[5];
    const float* euw  = (const float*)d_in[6];
    const float* eub  = (const float*)d_in[7];
    const float* dgw  = (const float*)d_in[8];
    const float* dgb  = (const float*)d_in[9];
    const float* duw  = (const float*)d_in[10];
    const float* dub  = (const float*)d_in[11];
    const float* pw   = (const float*)d_in[12];
    const float* pb   = (const float*)d_in[13];
    float* out = (float*)d_out;

    float *pSe, *pSd, *ph, *pDemb, *pDembT, *pEp, *pEpT;
    __half *pSeh, *pSel, *pSdh, *pSdl, *pX, *pFh, *pFl;
    __half *pWgeh, *pWgel, *pWueh, *pWuel, *pWgdh, *pWgdl, *pWudh, *pWudl;
    cudaGetSymbolAddress((void**)&pSe, g_S_enc);
    cudaGetSymbolAddress((void**)&pSd, g_S_dec);
    cudaGetSymbolAddress((void**)&ph, g_h);
    cudaGetSymbolAddress((void**)&pDemb, g_demb);
    cudaGetSymbolAddress((void**)&pDembT, g_dembT);
    cudaGetSymbolAddress((void**)&pEp, g_embpad);
    cudaGetSymbolAddress((void**)&pEpT, g_embpadT);
    cudaGetSymbolAddress((void**)&pSeh, g_Se_hi); cudaGetSymbolAddress((void**)&pSel, g_Se_lo);
    cudaGetSymbolAddress((void**)&pSdh, g_Sd_hi); cudaGetSymbolAddress((void**)&pSdl, g_Sd_lo);
    cudaGetSymbolAddress((void**)&pX, g_XT);
    cudaGetSymbolAddress((void**)&pFh, g_F_hi);   cudaGetSymbolAddress((void**)&pFl, g_F_lo);
    cudaGetSymbolAddress((void**)&pWgeh, g_Wge_hi); cudaGetSymbolAddress((void**)&pWgel, g_Wge_lo);
    cudaGetSymbolAddress((void**)&pWueh, g_Wue_hi); cudaGetSymbolAddress((void**)&pWuel, g_Wue_lo);
    cudaGetSymbolAddress((void**)&pWgdh, g_Wgd_hi); cudaGetSymbolAddress((void**)&pWgdl, g_Wgd_lo);
    cudaGetSymbolAddress((void**)&pWudh, g_Wud_hi); cudaGetSymbolAddress((void**)&pWudl, g_Wud_lo);

    constexpr int SMEM_BN128 = 3 * (128 + 128) * 72 * 2;  // 110592
    constexpr int SMEM_BN64  = 3 * (128 + 64) * 72 * 2;   // 82944
    cudaFuncSetAttribute(mma_gemm<128,0,2>, cudaFuncAttributeMaxDynamicSharedMemorySize, SMEM_BN128);
    cudaFuncSetAttribute(mma_gemm<128,1,3>, cudaFuncAttributeMaxDynamicSharedMemorySize, SMEM_BN128);
    cudaFuncSetAttribute(mma_gemm<64,2,3>,  cudaFuncAttributeMaxDynamicSharedMemorySize, SMEM_BN64);

    // ---- setup; launch index 3 (0-based) == diffusion GEMM for ncu
    k_zero_h<<<(int)(((size_t)XTC * Nn + 255) / 256), 256>>>(pX, (size_t)XTC * Nn);     // 0
    k_zero_h<<<(int)((size_t)ROWS * FPK / 256), 256>>>(pFh, (size_t)ROWS * FPK);        // 1
    k_zero_h<<<(int)((size_t)ROWS * FPK / 256), 256>>>(pFl, (size_t)ROWS * FPK);        // 2
    // ncu target: real-shape diffusion (inputs deterministic; output overwritten)
    mma_gemm<128,0,2><<<dim3(33, 16), 256, SMEM_BN128>>>(pSeh, pSel, pSeh, pX, pX, pX,
                                                         Nn, Nn, 1024, nullptr);        // 3
    k_zero_f32<<<ROWS * 64 / 256, 256>>>(ph, (size_t)ROWS * 64);
    k_pad_emb<<<64, 256>>>(emb);
    k_transpose<<<64, 256>>>(pEp, pEpT, Nn, 16);
    sgemm32<<<dim3(16, 8), 256>>>(pEp, pEpT, pSe, Nn, Nn, 16);
    k_relu_softmax<<<Nn, 256>>>(pSe);
    sgemm32<<<dim3(16, 8), 256>>>(pSe, pSe, pSe + NN2, Nn, Nn, Nn);
    k_cheb<<<NN2 / 256, 256>>>(pSe + NN2);
    k_split_h<<<2 * NN2 / 256, 256>>>(pSe, pSeh, pSel, (size_t)2 * NN2);
    k_pad_w_t<true><<<(128 * FPK + 255) / 256, 256>>>(egw, pWgeh, pWgel, 128);
    k_pad_w_t<true><<<(64 * FPK + 255) / 256, 256>>>(euw, pWueh, pWuel, 64);
    k_pad_w_t<false><<<(128 * FPK + 255) / 256, 256>>>(dgw, pWgdh, pWgdl, 128);
    k_pad_w_t<false><<<(64 * FPK + 255) / 256, 256>>>(duw, pWudh, pWudl, 64);

    // ---- encoder
    for (int t = 0; t < Tt; t++) {
        k_set_x_enc<<<256, 256>>>(x, t);
        mma_gemm<128,0,2><<<dim3(33, 16), 256, SMEM_BN128>>>(pSeh, pSel, pSeh, pX, pX, pX,
                                                             Nn, Nn, 1024, nullptr);
        mma_gemm<128,1,3><<<dim3(1, 512), 256, SMEM_BN128>>>(pFh, pFl, pFh, pWgeh, pWgeh, pWgel,
                                                             FPK, FPK, 256, egb);
        mma_gemm<128,0,2><<<dim3(33, 16), 256, SMEM_BN128>>>(pSeh, pSel, pSeh, pX, pX, pX,
                                                             Nn, Nn, 1024, nullptr);
        mma_gemm<64,2,3><<<dim3(1, 512), 256, SMEM_BN64>>>(pFh, pFl, pFh, pWueh, pWueh, pWuel,
                                                           FPK, FPK, 256, eub);
    }

    // ---- decoder supports
    k_demb<<<ROWS * Ee / 256, 256>>>(fce);
    k_transpose<<<ROWS * Ee / 256, 256>>>(pDemb, pDembT, Nn, Bb * Ee);
    sgemm32<<<dim3(16, 8), 256>>>(pDemb, pDembT, pSd, Nn, Nn, Bb * Ee);
    k_relu_softmax<<<Nn, 256>>>(pSd);
    sgemm32<<<dim3(16, 8), 256>>>(pSd, pSd, pSd + NN2, Nn, Nn, Nn);
    k_cheb<<<NN2 / 256, 256>>>(pSd + NN2);
    k_split_h<<<2 * NN2 / 256, 256>>>(pSd, pSdh, pSdl, (size_t)2 * NN2);
    k_init_go<<<256, 256>>>(x);

    // ---- decoder
    for (int t = 0; t < Hor; t++) {
        k_set_xy_dec<<<256, 256>>>(ycov, t);
        mma_gemm<128,0,2><<<dim3(33, 16), 256, SMEM_BN128>>>(pSdh, pSdl, pSdh, pX, pX, pX,
                                                             Nn, Nn, 1024, nullptr);
        mma_gemm<128,1,3><<<dim3(1, 512), 256, SMEM_BN128>>>(pFh, pFl, pFh, pWgdh, pWgdh, pWgdl,
                                                             FPK, FPK, 256, dgb);
        mma_gemm<128,0,2><<<dim3(33, 16), 256, SMEM_BN128>>>(pSdh, pSdl, pSdh, pX, pX, pX,
                                                             Nn, Nn, 1024, nullptr);
        mma_gemm<64,2,3><<<dim3(1, 512), 256, SMEM_BN64>>>(pFh, pFl, pFh, pWudh, pWudh, pWudl,
                                                           FPK, FPK, 256, dub);
        k_proj_out<<<256, 256>>>(pw, pb, out, t);
    }
}

// round 9
// speedup vs baseline: 2.4793x; 1.2399x over previous
#include <cuda_runtime.h>
#include <cuda_fp16.h>
#include <cstdint>
#include <math.h>

constexpr int Bb=64, Tt=12, Nn=1024, Ee=10, Hor=12;
constexpr int ROWS = Nn*Bb;          // 65536
constexpr int NN2  = Nn*Nn;
constexpr int FPK  = 256;            // padded K width of F (3*66=198 -> 256)
constexpr int XTC  = 66*Bb;          // 4224 = Xin^T row count (cols of Xin)

// ---------------- device-global scratch ----------------
__device__ __align__(1024) float g_S_enc[2*NN2];
__device__ __align__(1024) float g_S_dec[2*NN2];
__device__ __align__(1024) float g_R [(size_t)ROWS*64];
__device__ __align__(1024) float g_h [(size_t)ROWS*64];
__device__ __align__(1024) float g_go[ROWS];
__device__ __align__(1024) float g_demb [Nn*Bb*Ee];
__device__ __align__(1024) float g_dembT[Bb*Ee*Nn];
__device__ __align__(1024) float g_embpad [Nn*16];
__device__ __align__(1024) float g_embpadT[16*Nn];

__device__ __align__(1024) __half g_Se_hi[2*NN2];
__device__ __align__(1024) __half g_Sd_hi[2*NN2];
__device__ __align__(1024) __half g_XT[(size_t)XTC*Nn];                 // single fp16
__device__ __align__(1024) __half g_F_hi[(size_t)ROWS*FPK], g_F_lo[(size_t)ROWS*FPK];
__device__ __align__(1024) __half g_Wge_hi[128*FPK], g_Wge_lo[128*FPK];
__device__ __align__(1024) __half g_Wue_hi[64*FPK],  g_Wue_lo[64*FPK];
__device__ __align__(1024) __half g_Wgd_hi[128*FPK], g_Wgd_lo[128*FPK];
__device__ __align__(1024) __half g_Wud_hi[64*FPK],  g_Wud_lo[64*FPK];

__device__ __forceinline__ float sigmoidf_(float x){ return 1.0f/(1.0f+expf(-x)); }
__device__ __forceinline__ void split_h(float v, __half& hi, __half& lo){
    hi = __float2half_rn(v);
    lo = __float2half_rn(v - __half2float(hi));
}

__device__ __forceinline__ uint32_t smem_u32(const void* p){
    uint32_t a;
    asm("{ .reg .u64 t; cvta.to.shared.u64 t, %1; cvt.u32.u64 %0, t; }" : "=r"(a) : "l"(p));
    return a;
}
__device__ __forceinline__ void cp_async16(uint32_t dst, const void* src){
    asm volatile("cp.async.cg.shared.global [%0], [%1], 16;" :: "r"(dst), "l"(src));
}
__device__ __forceinline__ void cp_commit(){ asm volatile("cp.async.commit_group;"); }
template <int N>
__device__ __forceinline__ void cp_wait(){ asm volatile("cp.async.wait_group %0;" :: "n"(N)); }

__device__ __forceinline__ void ldsm_x4(uint32_t* r, uint32_t addr){
    asm volatile("ldmatrix.sync.aligned.m8n8.x4.shared.b16 {%0,%1,%2,%3}, [%4];"
        : "=r"(r[0]), "=r"(r[1]), "=r"(r[2]), "=r"(r[3]) : "r"(addr));
}
__device__ __forceinline__ void mma16816(float* c, const uint32_t* a, const uint32_t* b){
    asm volatile("mma.sync.aligned.m16n8k16.row.col.f32.f16.f16.f32 "
        "{%0,%1,%2,%3}, {%4,%5,%6,%7}, {%8,%9}, {%0,%1,%2,%3};"
        : "+f"(c[0]), "+f"(c[1]), "+f"(c[2]), "+f"(c[3])
        : "r"(a[0]), "r"(a[1]), "r"(a[2]), "r"(a[3]), "r"(b[0]), "r"(b[1]));
}

// ---------------- fp16 split-K HMMA GEMM (3-stage, 2 CTAs/SM) ---------------
// D[M rows, N=BN per block] = sum over NSEG segments Aseg(M x segK) @ Bseg^T,
// fp32 accumulate. A rows = output rows (lda elems); B rows = output COLUMNS,
// K-major (ldb elems). BM=128, BK=64, 256 threads (8 warps, 4m x 2n).
// EPI 0: diffusion -> fp16 hi/lo split-scatter into g_F
// EPI 1: gate: z=sig(+bias), c<64 -> z*h into g_XT (single) + g_F (hi/lo);
//        c>=64 -> g_R
// EPI 2: update: hc=tanh(+bias); hn = r*h + (1-r)*hc -> g_h, g_XT, g_F
template <int BN, int EPI, int NSEG>
__global__ void __launch_bounds__(256, 2) mma_gemm(
    const __half* __restrict__ A0, const __half* __restrict__ A1,
    const __half* __restrict__ A2,
    const __half* __restrict__ B0, const __half* __restrict__ B1,
    const __half* __restrict__ B2,
    int lda, int ldb, int segK, const float* __restrict__ bias)
{
    constexpr int BM = 128, LDS = 72;      // 64 + 8 pad (half elems)
    constexpr int NT = BN / 16;            // n8-tiles per warp (8 or 4)
    constexpr uint32_t STG_BYTES = (uint32_t)(BM + BN) * LDS * 2u;
    extern __shared__ __align__(16) char sm[];
    const uint32_t sm0 = smem_u32(sm);

    const int tid = threadIdx.x, lane = tid & 31, wid = tid >> 5;
    const int wm = wid >> 1, wn = wid & 1;
    const int m0 = blockIdx.y * BM, n0 = blockIdx.x * BN;

    const __half* Asg[3] = {A0, A1, A2};
    const __half* Bsg[3] = {B0, B1, B2};
    const int nt_seg = segK >> 6;
    const int KT = NSEG * nt_seg;

    float acc[2][NT][4];
#pragma unroll
    for (int i = 0; i < 2; i++)
#pragma unroll
        for (int j = 0; j < NT; j++)
#pragma unroll
            for (int e = 0; e < 4; e++) acc[i][j][e] = 0.0f;

    const uint32_t aOff = (((uint32_t)(wm*32 + (lane & 15))) * LDS + ((lane >> 4) << 3)) * 2u;
    const uint32_t bOff = (uint32_t)BM * LDS * 2u
        + (((uint32_t)(wn*(BN/2) + (lane & 7) + ((lane >> 4) << 3))) * LDS
           + (((lane >> 3) & 1) << 3)) * 2u;

    auto load_tile = [&](int kt, int stg) {
        const uint32_t sA = sm0 + (uint32_t)stg * STG_BYTES;
        const uint32_t sB = sA + (uint32_t)BM * LDS * 2u;
        int seg = kt / nt_seg;
        int j = kt - seg * nt_seg;
        const char* Ag = (const char*)(Asg[seg] + (size_t)m0 * lda + j * 64);
        const char* Bg = (const char*)(Bsg[seg] + (size_t)n0 * ldb + j * 64);
#pragma unroll
        for (int it = 0; it < 4; it++) {
            int id = (it << 8) + tid;
            int r = id >> 3, c = id & 7;
            cp_async16(sA + (uint32_t)r*144u + (uint32_t)c*16u,
                       Ag + (size_t)r * ((size_t)lda*2) + c*16);
        }
#pragma unroll
        for (int it = 0; it < BN/32; it++) {
            int id = (it << 8) + tid;
            int r = id >> 3, c = id & 7;
            cp_async16(sB + (uint32_t)r*144u + (uint32_t)c*16u,
                       Bg + (size_t)r * ((size_t)ldb*2) + c*16);
        }
        cp_commit();
    };

    load_tile(0, 0);
    if (KT > 1) load_tile(1, 1);

    int stg = 0;
    for (int kt = 0; kt < KT; kt++) {
        if (kt + 1 < KT) cp_wait<1>(); else cp_wait<0>();
        __syncthreads();
        if (kt + 2 < KT) load_tile(kt + 2, (kt + 2) % 3);

        const uint32_t sbase = sm0 + (uint32_t)stg * STG_BYTES;
        const uint32_t aBase = sbase + aOff;
        const uint32_t bBase = sbase + bOff;
#pragma unroll
        for (int ks = 0; ks < 4; ks++) {
            uint32_t a[2][4];
            ldsm_x4(a[0], aBase + (uint32_t)ks*32u);
            ldsm_x4(a[1], aBase + 16u*LDS*2u + (uint32_t)ks*32u);
            uint32_t b[NT/2][4];
#pragma unroll
            for (int p = 0; p < NT/2; p++)
                ldsm_x4(b[p], bBase + (uint32_t)p*16u*LDS*2u + (uint32_t)ks*32u);
#pragma unroll
            for (int mt = 0; mt < 2; mt++)
#pragma unroll
                for (int nt = 0; nt < NT; nt++)
                    mma16816(acc[mt][nt], a[mt], &b[nt >> 1][(nt & 1) * 2]);
        }
        if (++stg == 3) stg = 0;
    }

    // ---------------- epilogue ----------------
    const int rbase = m0 + wm*32 + (lane >> 2);
    const int cbase = n0 + wn*(BN/2) + ((lane & 3) << 1);
#pragma unroll
    for (int mt = 0; mt < 2; mt++) {
#pragma unroll
        for (int nt = 0; nt < NT; nt++) {
#pragma unroll
            for (int e = 0; e < 4; e++) {
                const int row = rbase + mt*16 + ((e >> 1) << 3);
                const int col = cbase + nt*8 + (e & 1);
                const float v = acc[mt][nt][e];
                if (EPI == 0) {
                    const int kk = row >> 10, n = row & 1023;
                    const int b = col / 66, c = col - b * 66;
                    __half hi, lo; split_h(v, hi, lo);
                    const size_t off = (size_t)((n << 6) + b) * FPK + (kk + 1) * 66 + c;
                    g_F_hi[off] = hi; g_F_lo[off] = lo;
                } else if (EPI == 1) {
                    const int id = row, n = row >> 6, b = row & 63;
                    const float s = sigmoidf_(v + bias[col]);
                    if (col < 64) {
                        const float zh = s * g_h[(size_t)id * 64 + col];
                        __half hi, lo; split_h(zh, hi, lo);
                        g_XT[((size_t)(b * 66 + 2 + col) << 10) + n] = hi;
                        const size_t fo = ((size_t)id << 8) + 2 + col;
                        g_F_hi[fo] = hi; g_F_lo[fo] = lo;
                    } else {
                        g_R[(size_t)id * 64 + (col - 64)] = s;
                    }
                } else {
                    const int id = row, n = row >> 6, b = row & 63;
                    const float hc = tanhf(v + bias[col]);
                    const size_t o = (size_t)id * 64 + col;
                    const float r = g_R[o], h = g_h[o];
                    const float hn = r * h + (1.0f - r) * hc;
                    g_h[o] = hn;
                    __half hi, lo; split_h(hn, hi, lo);
                    g_XT[((size_t)(b * 66 + 2 + col) << 10) + n] = hi;
                    const size_t fo = ((size_t)id << 8) + 2 + col;
                    g_F_hi[fo] = hi; g_F_lo[fo] = lo;
                }
            }
        }
    }
}

// ---------------- fp32 SGEMM (setup only) ----------------
__global__ void __launch_bounds__(256) sgemm32(
    const float* __restrict__ A, const float* __restrict__ B,
    float* __restrict__ C, int M, int N, int K)
{
    constexpr int BM = 128, BN = 64, BK = 16;
    __shared__ __align__(16) float As_[BK][BM];
    __shared__ __align__(16) float Bs_[BK][BN];
    const int tid = threadIdx.x;
    const int tx = tid & 15, ty = tid >> 4;
    const int m0 = blockIdx.y * BM, n0 = blockIdx.x * BN;
    float acc[8][4];
#pragma unroll
    for (int i = 0; i < 8; i++)
#pragma unroll
        for (int jj = 0; jj < 4; jj++) acc[i][jj] = 0.0f;
    const int arow0 = tid >> 2, acol0 = (tid & 3) * 4;
    const int brow = tid >> 4, bcol = (tid & 15) * 4;
    for (int kt = 0; kt < K; kt += BK) {
#pragma unroll
        for (int i = 0; i < 2; i++) {
            int r = arow0 + i * 64;
            float4 v = *reinterpret_cast<const float4*>(A + (size_t)(m0 + r) * K + kt + acol0);
            As_[acol0+0][r]=v.x; As_[acol0+1][r]=v.y; As_[acol0+2][r]=v.z; As_[acol0+3][r]=v.w;
        }
        float4 bv = *reinterpret_cast<const float4*>(B + (size_t)(kt + brow) * N + n0 + bcol);
        *reinterpret_cast<float4*>(&Bs_[brow][bcol]) = bv;
        __syncthreads();
#pragma unroll
        for (int k = 0; k < BK; k++) {
            float4 a0 = *reinterpret_cast<const float4*>(&As_[k][ty*8]);
            float4 a1 = *reinterpret_cast<const float4*>(&As_[k][ty*8+4]);
            float4 b0 = *reinterpret_cast<const float4*>(&Bs_[k][tx*4]);
            float am[8]={a0.x,a0.y,a0.z,a0.w,a1.x,a1.y,a1.z,a1.w};
            float bn[4]={b0.x,b0.y,b0.z,b0.w};
#pragma unroll
            for (int i = 0; i < 8; i++)
#pragma unroll
                for (int jj = 0; jj < 4; jj++) acc[i][jj] = fmaf(am[i], bn[jj], acc[i][jj]);
        }
        __syncthreads();
    }
#pragma unroll
    for (int i = 0; i < 8; i++) {
        float4 v = make_float4(acc[i][0], acc[i][1], acc[i][2], acc[i][3]);
        *reinterpret_cast<float4*>(C + (size_t)(m0 + ty*8 + i) * N + n0 + tx*4) = v;
    }
}

// ---------------- elementwise helpers ----------------
__global__ void k_zero_f32(float* p, size_t n) {
    size_t i = (size_t)blockIdx.x * blockDim.x + threadIdx.x;
    if (i < n) p[i] = 0.0f;
}
__global__ void k_zero_h(__half* p, size_t n) {
    size_t i = (size_t)blockIdx.x * blockDim.x + threadIdx.x;
    if (i < n) p[i] = __float2half_rn(0.0f);
}
__global__ void k_tohalf(const float* __restrict__ s, __half* __restrict__ hi, size_t n) {
    size_t i = (size_t)blockIdx.x * blockDim.x + threadIdx.x;
    if (i >= n) return;
    hi[i] = __float2half_rn(s[i]);
}
__global__ void k_pad_emb(const float* __restrict__ emb) {
    int idx = blockIdx.x * blockDim.x + threadIdx.x;
    if (idx >= Nn * 16) return;
    int n = idx >> 4, j = idx & 15;
    g_embpad[idx] = (j < Ee) ? emb[n * Ee + j] : 0.0f;
}
__global__ void k_transpose(const float* __restrict__ in, float* __restrict__ out,
                            int R, int C) {
    int idx = blockIdx.x * blockDim.x + threadIdx.x;
    if (idx >= R * C) return;
    int r = idx / C, c = idx - r * C;
    out[c * R + r] = in[idx];
}
template <bool ENC>
__global__ void k_pad_w_t(const float* __restrict__ src, __half* __restrict__ hi,
                          __half* __restrict__ lo, int nout) {
    int idx = blockIdx.x * blockDim.x + threadIdx.x;
    if (idx >= nout * FPK) return;
    int n = idx >> 8, f = idx & 255;
    float v = 0.0f;
    if (f < 198) {
        int k = f / 66, c = f - k * 66;
        if (ENC) {
            if (c == 0) v = src[(k * 65) * nout + n];
            else if (c >= 2) v = src[(k * 65 + c - 1) * nout + n];
        } else {
            v = src[f * nout + n];
        }
    }
    __half h, l; split_h(v, h, l);
    hi[idx] = h; lo[idx] = l;
}
__global__ void k_relu_softmax(float* __restrict__ S) {
    int row = blockIdx.x;
    float* p = S + (size_t)row * Nn;
    int t = threadIdx.x;
    float v[4];
#pragma unroll
    for (int i = 0; i < 4; i++) { float x = p[t + i*256]; v[i] = x > 0.0f ? x : 0.0f; }
    __shared__ float red[256];
    float m = fmaxf(fmaxf(v[0], v[1]), fmaxf(v[2], v[3]));
    red[t] = m; __syncthreads();
    for (int s = 128; s > 0; s >>= 1) { if (t < s) red[t] = fmaxf(red[t], red[t+s]); __syncthreads(); }
    m = red[0]; __syncthreads();
    float e[4], sum = 0.0f;
#pragma unroll
    for (int i = 0; i < 4; i++) { e[i] = expf(v[i] - m); sum += e[i]; }
    red[t] = sum; __syncthreads();
    for (int s = 128; s > 0; s >>= 1) { if (t < s) red[t] += red[t+s]; __syncthreads(); }
    float inv = 1.0f / red[0];
#pragma unroll
    for (int i = 0; i < 4; i++) p[t + i*256] = e[i] * inv;
}
__global__ void k_cheb(float* __restrict__ P) {
    int idx = blockIdx.x * blockDim.x + threadIdx.x;
    if (idx >= NN2) return;
    int r = idx >> 10, c = idx & 1023;
    P[idx] = 2.0f * P[idx] - (r == c ? 1.0f : 0.0f);
}
__global__ void k_set_x_enc(const float* __restrict__ x, int t) {
    int id = blockIdx.x * blockDim.x + threadIdx.x;
    if (id >= ROWS) return;
    int n = id >> 6, b = id & 63;
    float xv = x[((size_t)b * Tt + t) * Nn + n];
    __half xh, xl; split_h(xv, xh, xl);
    g_XT[((size_t)(b * 66) << 10) + n] = xh;
    size_t fo = (size_t)id << 8;
    g_F_hi[fo] = xh; g_F_lo[fo] = xl;
}
__global__ void k_set_xy_dec(const float* __restrict__ ycov, int t) {
    int id = blockIdx.x * blockDim.x + threadIdx.x;
    if (id >= ROWS) return;
    int n = id >> 6, b = id & 63;
    float gv = g_go[id];
    float yv = ycov[((size_t)b * Hor + t) * Nn + n];
    __half gh, gl, yh, yl;
    split_h(gv, gh, gl);
    split_h(yv, yh, yl);
    g_XT[((size_t)(b * 66) << 10) + n] = gh;
    g_XT[((size_t)(b * 66 + 1) << 10) + n] = yh;
    size_t fo = (size_t)id << 8;
    g_F_hi[fo] = gh;     g_F_lo[fo] = gl;
    g_F_hi[fo + 1] = yh; g_F_lo[fo + 1] = yl;
}
__global__ void k_demb(const float* __restrict__ fce) {
    int idx = blockIdx.x * blockDim.x + threadIdx.x;
    if (idx >= ROWS * Ee) return;
    int id = idx / Ee, e = idx - id * Ee;
    const float* hr = g_h + (size_t)id * 64;
    float s = 0.0f;
#pragma unroll
    for (int h = 0; h < 64; h++) s = fmaf(hr[h], fce[h * Ee + e], s);
    g_demb[idx] = s;
}
__global__ void k_init_go(const float* __restrict__ x) {
    int id = blockIdx.x * blockDim.x + threadIdx.x;
    if (id >= ROWS) return;
    int n = id >> 6, b = id & 63;
    g_go[id] = x[((size_t)b * Tt + (Tt - 1)) * Nn + n];
}
__global__ void k_proj_out(const float* __restrict__ pw, const float* __restrict__ pb,
                           float* __restrict__ out, int t) {
    int id = blockIdx.x * blockDim.x + threadIdx.x;
    if (id >= ROWS) return;
    int n = id >> 6, b = id & 63;
    const float* hr = g_h + (size_t)id * 64;
    float s = pb[0];
#pragma unroll
    for (int i = 0; i < 64; i++) s = fmaf(hr[i], pw[i], s);
    g_go[id] = s;
    out[((size_t)b * Hor + t) * Nn + n] = s;
}

// ---------------- orchestration ----------------
extern "C" void kernel_launch(void* const* d_in, const int* in_sizes, int n_in,
                              void* d_out, int out_size) {
    const float* x    = (const float*)d_in[0];
    const float* ycov = (const float*)d_in[1];
    const float* emb  = (const float*)d_in[2];
    const float* fce  = (const float*)d_in[3];
    const float* egw  = (const float*)d_in[4];
    const float* egb  = (const float*)d_in[5];
    const float* euw  = (const float*)d_in[6];
    const float* eub  = (const float*)d_in[7];
    const float* dgw  = (const float*)d_in[8];
    const float* dgb  = (const float*)d_in[9];
    const float* duw  = (const float*)d_in[10];
    const float* dub  = (const float*)d_in[11];
    const float* pw   = (const float*)d_in[12];
    const float* pb   = (const float*)d_in[13];
    float* out = (float*)d_out;

    float *pSe, *pSd, *ph, *pDemb, *pDembT, *pEp, *pEpT;
    __half *pSeh, *pSdh, *pX, *pFh, *pFl;
    __half *pWgeh, *pWgel, *pWueh, *pWuel, *pWgdh, *pWgdl, *pWudh, *pWudl;
    cudaGetSymbolAddress((void**)&pSe, g_S_enc);
    cudaGetSymbolAddress((void**)&pSd, g_S_dec);
    cudaGetSymbolAddress((void**)&ph, g_h);
    cudaGetSymbolAddress((void**)&pDemb, g_demb);
    cudaGetSymbolAddress((void**)&pDembT, g_dembT);
    cudaGetSymbolAddress((void**)&pEp, g_embpad);
    cudaGetSymbolAddress((void**)&pEpT, g_embpadT);
    cudaGetSymbolAddress((void**)&pSeh, g_Se_hi);
    cudaGetSymbolAddress((void**)&pSdh, g_Sd_hi);
    cudaGetSymbolAddress((void**)&pX, g_XT);
    cudaGetSymbolAddress((void**)&pFh, g_F_hi);   cudaGetSymbolAddress((void**)&pFl, g_F_lo);
    cudaGetSymbolAddress((void**)&pWgeh, g_Wge_hi); cudaGetSymbolAddress((void**)&pWgel, g_Wge_lo);
    cudaGetSymbolAddress((void**)&pWueh, g_Wue_hi); cudaGetSymbolAddress((void**)&pWuel, g_Wue_lo);
    cudaGetSymbolAddress((void**)&pWgdh, g_Wgd_hi); cudaGetSymbolAddress((void**)&pWgdl, g_Wgd_lo);
    cudaGetSymbolAddress((void**)&pWudh, g_Wud_hi); cudaGetSymbolAddress((void**)&pWudl, g_Wud_lo);

    constexpr int SMEM_BN128 = 3 * (128 + 128) * 72 * 2;  // 110592
    constexpr int SMEM_BN64  = 3 * (128 + 64) * 72 * 2;   // 82944
    cudaFuncSetAttribute(mma_gemm<128,0,1>, cudaFuncAttributeMaxDynamicSharedMemorySize, SMEM_BN128);
    cudaFuncSetAttribute(mma_gemm<128,1,3>, cudaFuncAttributeMaxDynamicSharedMemorySize, SMEM_BN128);
    cudaFuncSetAttribute(mma_gemm<64,2,3>,  cudaFuncAttributeMaxDynamicSharedMemorySize, SMEM_BN64);

    // ---- setup; launch index 3 (0-based) == diffusion GEMM for ncu
    k_zero_h<<<(int)(((size_t)XTC * Nn + 255) / 256), 256>>>(pX, (size_t)XTC * Nn);     // 0
    k_zero_h<<<(int)((size_t)ROWS * FPK / 256), 256>>>(pFh, (size_t)ROWS * FPK);        // 1
    k_zero_h<<<(int)((size_t)ROWS * FPK / 256), 256>>>(pFl, (size_t)ROWS * FPK);        // 2
    // ncu target: real-shape diffusion (inputs deterministic; output overwritten)
    mma_gemm<128,0,1><<<dim3(33, 16), 256, SMEM_BN128>>>(pSeh, pSeh, pSeh, pX, pX, pX,
                                                         Nn, Nn, 1024, nullptr);        // 3
    k_zero_f32<<<ROWS * 64 / 256, 256>>>(ph, (size_t)ROWS * 64);
    k_pad_emb<<<64, 256>>>(emb);
    k_transpose<<<64, 256>>>(pEp, pEpT, Nn, 16);
    sgemm32<<<dim3(16, 8), 256>>>(pEp, pEpT, pSe, Nn, Nn, 16);
    k_relu_softmax<<<Nn, 256>>>(pSe);
    sgemm32<<<dim3(16, 8), 256>>>(pSe, pSe, pSe + NN2, Nn, Nn, Nn);
    k_cheb<<<NN2 / 256, 256>>>(pSe + NN2);
    k_tohalf<<<2 * NN2 / 256, 256>>>(pSe, pSeh, (size_t)2 * NN2);
    k_pad_w_t<true><<<(128 * FPK + 255) / 256, 256>>>(egw, pWgeh, pWgel, 128);
    k_pad_w_t<true><<<(64 * FPK + 255) / 256, 256>>>(euw, pWueh, pWuel, 64);
    k_pad_w_t<false><<<(128 * FPK + 255) / 256, 256>>>(dgw, pWgdh, pWgdl, 128);
    k_pad_w_t<false><<<(64 * FPK + 255) / 256, 256>>>(duw, pWudh, pWudl, 64);

    // ---- encoder (diffusion: single-segment fp16 S_hi, segK = 1024)
    for (int t = 0; t < Tt; t++) {
        k_set_x_enc<<<256, 256>>>(x, t);
        mma_gemm<128,0,1><<<dim3(33, 16), 256, SMEM_BN128>>>(pSeh, pSeh, pSeh, pX, pX, pX,
                                                             Nn, Nn, 1024, nullptr);
        mma_gemm<128,1,3><<<dim3(1, 512), 256, SMEM_BN128>>>(pFh, pFl, pFh, pWgeh, pWgeh, pWgel,
                                                             FPK, FPK, 256, egb);
        mma_gemm<128,0,1><<<dim3(33, 16), 256, SMEM_BN128>>>(pSeh, pSeh, pSeh, pX, pX, pX,
                                                             Nn, Nn, 1024, nullptr);
        mma_gemm<64,2,3><<<dim3(1, 512), 256, SMEM_BN64>>>(pFh, pFl, pFh, pWueh, pWueh, pWuel,
                                                           FPK, FPK, 256, eub);
    }

    // ---- decoder supports
    k_demb<<<ROWS * Ee / 256, 256>>>(fce);
    k_transpose<<<ROWS * Ee / 256, 256>>>(pDemb, pDembT, Nn, Bb * Ee);
    sgemm32<<<dim3(16, 8), 256>>>(pDemb, pDembT, pSd, Nn, Nn, Bb * Ee);
    k_relu_softmax<<<Nn, 256>>>(pSd);
    sgemm32<<<dim3(16, 8), 256>>>(pSd, pSd, pSd + NN2, Nn, Nn, Nn);
    k_cheb<<<NN2 / 256, 256>>>(pSd + NN2);
    k_tohalf<<<2 * NN2 / 256, 256>>>(pSd, pSdh, (size_t)2 * NN2);
    k_init_go<<<256, 256>>>(x);

    // ---- decoder
    for (int t = 0; t < Hor; t++) {
        k_set_xy_dec<<<256, 256>>>(ycov, t);
        mma_gemm<128,0,1><<<dim3(33, 16), 256, SMEM_BN128>>>(pSdh, pSdh, pSdh, pX, pX, pX,
                                                             Nn, Nn, 1024, nullptr);
        mma_gemm<128,1,3><<<dim3(1, 512), 256, SMEM_BN128>>>(pFh, pFl, pFh, pWgdh, pWgdh, pWgdl,
                                                             FPK, FPK, 256, dgb);
        mma_gemm<128,0,1><<<dim3(33, 16), 256, SMEM_BN128>>>(pSdh, pSdh, pSdh, pX, pX, pX,
                                                             Nn, Nn, 1024, nullptr);
        mma_gemm<64,2,3><<<dim3(1, 512), 256, SMEM_BN64>>>(pFh, pFl, pFh, pWudh, pWudh, pWudl,
                                                           FPK, FPK, 256, dub);
        k_proj_out<<<256, 256>>>(pw, pb, out, t);
    }
}

// round 10
// speedup vs baseline: 3.1400x; 1.2665x over previous
#include <cuda_runtime.h>
#include <cuda_fp16.h>
#include <cstdint>
#include <math.h>

constexpr int Bb=64, Tt=12, Nn=1024, Ee=10, Hor=12;
constexpr int ROWS = Nn*Bb;          // 65536
constexpr int NN2  = Nn*Nn;
constexpr int FPK  = 256;            // padded K width of F (3*66=198 -> 256)
constexpr int XTC  = 66*Bb;          // 4224 = Xin^T row count (cols of Xin)

// ---------------- device-global scratch ----------------
__device__ __align__(1024) float g_S_enc[2*NN2];
__device__ __align__(1024) float g_S_dec[2*NN2];
__device__ __align__(1024) float g_R [(size_t)ROWS*64];
__device__ __align__(1024) float g_h [(size_t)ROWS*64];
__device__ __align__(1024) float g_go[ROWS];
__device__ __align__(1024) float g_demb [Nn*Bb*Ee];
__device__ __align__(1024) float g_dembT[Bb*Ee*Nn];
__device__ __align__(1024) float g_embpad [Nn*16];
__device__ __align__(1024) float g_embpadT[16*Nn];

__device__ __align__(1024) __half g_Se_hi[2*NN2];
__device__ __align__(1024) __half g_Sd_hi[2*NN2];
__device__ __align__(1024) __half g_XT[(size_t)XTC*Nn];          // single fp16
__device__ __align__(1024) __half g_F[(size_t)ROWS*FPK];         // single fp16
__device__ __align__(1024) __half g_Wge_hi[128*FPK], g_Wge_lo[128*FPK];
__device__ __align__(1024) __half g_Wue_hi[64*FPK],  g_Wue_lo[64*FPK];
__device__ __align__(1024) __half g_Wgd_hi[128*FPK], g_Wgd_lo[128*FPK];
__device__ __align__(1024) __half g_Wud_hi[64*FPK],  g_Wud_lo[64*FPK];

__device__ __forceinline__ float sigmoidf_(float x){ return 1.0f/(1.0f+expf(-x)); }
__device__ __forceinline__ void split_h(float v, __half& hi, __half& lo){
    hi = __float2half_rn(v);
    lo = __float2half_rn(v - __half2float(hi));
}

__device__ __forceinline__ uint32_t smem_u32(const void* p){
    uint32_t a;
    asm("{ .reg .u64 t; cvta.to.shared.u64 t, %1; cvt.u32.u64 %0, t; }" : "=r"(a) : "l"(p));
    return a;
}
__device__ __forceinline__ void cp_async16(uint32_t dst, const void* src){
    asm volatile("cp.async.cg.shared.global [%0], [%1], 16;" :: "r"(dst), "l"(src));
}
__device__ __forceinline__ void cp_commit(){ asm volatile("cp.async.commit_group;"); }
template <int N>
__device__ __forceinline__ void cp_wait(){ asm volatile("cp.async.wait_group %0;" :: "n"(N)); }

__device__ __forceinline__ void ldsm_x4(uint32_t* r, uint32_t addr){
    asm volatile("ldmatrix.sync.aligned.m8n8.x4.shared.b16 {%0,%1,%2,%3}, [%4];"
        : "=r"(r[0]), "=r"(r[1]), "=r"(r[2]), "=r"(r[3]) : "r"(addr));
}
__device__ __forceinline__ void mma16816(float* c, const uint32_t* a, const uint32_t* b){
    asm volatile("mma.sync.aligned.m16n8k16.row.col.f32.f16.f16.f32 "
        "{%0,%1,%2,%3}, {%4,%5,%6,%7}, {%8,%9}, {%0,%1,%2,%3};"
        : "+f"(c[0]), "+f"(c[1]), "+f"(c[2]), "+f"(c[3])
        : "r"(a[0]), "r"(a[1]), "r"(a[2]), "r"(a[3]), "r"(b[0]), "r"(b[1]));
}

// ---------------- fp16 split-K HMMA GEMM (3-stage, 2 CTAs/SM) ---------------
// D[M rows, N=BN per block] = sum over NSEG segments Aseg(M x segK) @ Bseg^T,
// fp32 accumulate. A rows = output rows (lda elems); B rows = output COLUMNS,
// K-major (ldb elems). BM=128, BK=64, 256 threads (8 warps, 4m x 2n).
// EPI 0: diffusion -> fp16 scatter into g_F
// EPI 1: gate: z=sig(+bias), c<64 -> z*h into g_XT + g_F; c>=64 -> g_R
// EPI 2: update: hc=tanh(+bias); hn = r*h + (1-r)*hc -> g_h, g_XT, g_F
template <int BN, int EPI, int NSEG>
__global__ void __launch_bounds__(256, 2) mma_gemm(
    const __half* __restrict__ A0, const __half* __restrict__ A1,
    const __half* __restrict__ A2,
    const __half* __restrict__ B0, const __half* __restrict__ B1,
    const __half* __restrict__ B2,
    int lda, int ldb, int segK, const float* __restrict__ bias)
{
    constexpr int BM = 128, LDS = 72;      // 64 + 8 pad (half elems)
    constexpr int NT = BN / 16;            // n8-tiles per warp (8 or 4)
    constexpr uint32_t STG_BYTES = (uint32_t)(BM + BN) * LDS * 2u;
    extern __shared__ __align__(16) char sm[];
    const uint32_t sm0 = smem_u32(sm);

    const int tid = threadIdx.x, lane = tid & 31, wid = tid >> 5;
    const int wm = wid >> 1, wn = wid & 1;
    const int m0 = blockIdx.y * BM, n0 = blockIdx.x * BN;

    const __half* Asg[3] = {A0, A1, A2};
    const __half* Bsg[3] = {B0, B1, B2};
    const int nt_seg = segK >> 6;
    const int KT = NSEG * nt_seg;

    float acc[2][NT][4];
#pragma unroll
    for (int i = 0; i < 2; i++)
#pragma unroll
        for (int j = 0; j < NT; j++)
#pragma unroll
            for (int e = 0; e < 4; e++) acc[i][j][e] = 0.0f;

    const uint32_t aOff = (((uint32_t)(wm*32 + (lane & 15))) * LDS + ((lane >> 4) << 3)) * 2u;
    const uint32_t bOff = (uint32_t)BM * LDS * 2u
        + (((uint32_t)(wn*(BN/2) + (lane & 7) + ((lane >> 4) << 3))) * LDS
           + (((lane >> 3) & 1) << 3)) * 2u;

    auto load_tile = [&](int kt, int stg) {
        const uint32_t sA = sm0 + (uint32_t)stg * STG_BYTES;
        const uint32_t sB = sA + (uint32_t)BM * LDS * 2u;
        int seg = kt / nt_seg;
        int j = kt - seg * nt_seg;
        const char* Ag = (const char*)(Asg[seg] + (size_t)m0 * lda + j * 64);
        const char* Bg = (const char*)(Bsg[seg] + (size_t)n0 * ldb + j * 64);
#pragma unroll
        for (int it = 0; it < 4; it++) {
            int id = (it << 8) + tid;
            int r = id >> 3, c = id & 7;
            cp_async16(sA + (uint32_t)r*144u + (uint32_t)c*16u,
                       Ag + (size_t)r * ((size_t)lda*2) + c*16);
        }
#pragma unroll
        for (int it = 0; it < BN/32; it++) {
            int id = (it << 8) + tid;
            int r = id >> 3, c = id & 7;
            cp_async16(sB + (uint32_t)r*144u + (uint32_t)c*16u,
                       Bg + (size_t)r * ((size_t)ldb*2) + c*16);
        }
        cp_commit();
    };

    load_tile(0, 0);
    if (KT > 1) load_tile(1, 1);

    int stg = 0;
    for (int kt = 0; kt < KT; kt++) {
        if (kt + 1 < KT) cp_wait<1>(); else cp_wait<0>();
        __syncthreads();
        if (kt + 2 < KT) load_tile(kt + 2, (kt + 2) % 3);

        const uint32_t sbase = sm0 + (uint32_t)stg * STG_BYTES;
        const uint32_t aBase = sbase + aOff;
        const uint32_t bBase = sbase + bOff;
#pragma unroll
        for (int ks = 0; ks < 4; ks++) {
            uint32_t a[2][4];
            ldsm_x4(a[0], aBase + (uint32_t)ks*32u);
            ldsm_x4(a[1], aBase + 16u*LDS*2u + (uint32_t)ks*32u);
            uint32_t b[NT/2][4];
#pragma unroll
            for (int p = 0; p < NT/2; p++)
                ldsm_x4(b[p], bBase + (uint32_t)p*16u*LDS*2u + (uint32_t)ks*32u);
#pragma unroll
            for (int mt = 0; mt < 2; mt++)
#pragma unroll
                for (int nt = 0; nt < NT; nt++)
                    mma16816(acc[mt][nt], a[mt], &b[nt >> 1][(nt & 1) * 2]);
        }
        if (++stg == 3) stg = 0;
    }

    // ---------------- epilogue ----------------
    const int rbase = m0 + wm*32 + (lane >> 2);
    const int cbase = n0 + wn*(BN/2) + ((lane & 3) << 1);
#pragma unroll
    for (int mt = 0; mt < 2; mt++) {
#pragma unroll
        for (int nt = 0; nt < NT; nt++) {
#pragma unroll
            for (int e = 0; e < 4; e++) {
                const int row = rbase + mt*16 + ((e >> 1) << 3);
                const int col = cbase + nt*8 + (e & 1);
                const float v = acc[mt][nt][e];
                if (EPI == 0) {
                    const int kk = row >> 10, n = row & 1023;
                    const int b = col / 66, c = col - b * 66;
                    const size_t off = (size_t)((n << 6) + b) * FPK + (kk + 1) * 66 + c;
                    g_F[off] = __float2half_rn(v);
                } else if (EPI == 1) {
                    const int id = row, n = row >> 6, b = row & 63;
                    const float s = sigmoidf_(v + bias[col]);
                    if (col < 64) {
                        const float zh = s * g_h[(size_t)id * 64 + col];
                        const __half hv = __float2half_rn(zh);
                        g_XT[((size_t)(b * 66 + 2 + col) << 10) + n] = hv;
                        g_F[((size_t)id << 8) + 2 + col] = hv;
                    } else {
                        g_R[(size_t)id * 64 + (col - 64)] = s;
                    }
                } else {
                    const int id = row, n = row >> 6, b = row & 63;
                    const float hc = tanhf(v + bias[col]);
                    const size_t o = (size_t)id * 64 + col;
                    const float r = g_R[o], h = g_h[o];
                    const float hn = r * h + (1.0f - r) * hc;
                    g_h[o] = hn;
                    const __half hv = __float2half_rn(hn);
                    g_XT[((size_t)(b * 66 + 2 + col) << 10) + n] = hv;
                    g_F[((size_t)id << 8) + 2 + col] = hv;
                }
            }
        }
    }
}

// ---------------- fp32 SGEMM (setup only) ----------------
__global__ void __launch_bounds__(256) sgemm32(
    const float* __restrict__ A, const float* __restrict__ B,
    float* __restrict__ C, int M, int N, int K)
{
    constexpr int BM = 128, BN = 64, BK = 16;
    __shared__ __align__(16) float As_[BK][BM];
    __shared__ __align__(16) float Bs_[BK][BN];
    const int tid = threadIdx.x;
    const int tx = tid & 15, ty = tid >> 4;
    const int m0 = blockIdx.y * BM, n0 = blockIdx.x * BN;
    float acc[8][4];
#pragma unroll
    for (int i = 0; i < 8; i++)
#pragma unroll
        for (int jj = 0; jj < 4; jj++) acc[i][jj] = 0.0f;
    const int arow0 = tid >> 2, acol0 = (tid & 3) * 4;
    const int brow = tid >> 4, bcol = (tid & 15) * 4;
    for (int kt = 0; kt < K; kt += BK) {
#pragma unroll
        for (int i = 0; i < 2; i++) {
            int r = arow0 + i * 64;
            float4 v = *reinterpret_cast<const float4*>(A + (size_t)(m0 + r) * K + kt + acol0);
            As_[acol0+0][r]=v.x; As_[acol0+1][r]=v.y; As_[acol0+2][r]=v.z; As_[acol0+3][r]=v.w;
        }
        float4 bv = *reinterpret_cast<const float4*>(B + (size_t)(kt + brow) * N + n0 + bcol);
        *reinterpret_cast<float4*>(&Bs_[brow][bcol]) = bv;
        __syncthreads();
#pragma unroll
        for (int k = 0; k < BK; k++) {
            float4 a0 = *reinterpret_cast<const float4*>(&As_[k][ty*8]);
            float4 a1 = *reinterpret_cast<const float4*>(&As_[k][ty*8+4]);
            float4 b0 = *reinterpret_cast<const float4*>(&Bs_[k][tx*4]);
            float am[8]={a0.x,a0.y,a0.z,a0.w,a1.x,a1.y,a1.z,a1.w};
            float bn[4]={b0.x,b0.y,b0.z,b0.w};
#pragma unroll
            for (int i = 0; i < 8; i++)
#pragma unroll
                for (int jj = 0; jj < 4; jj++) acc[i][jj] = fmaf(am[i], bn[jj], acc[i][jj]);
        }
        __syncthreads();
    }
#pragma unroll
    for (int i = 0; i < 8; i++) {
        float4 v = make_float4(acc[i][0], acc[i][1], acc[i][2], acc[i][3]);
        *reinterpret_cast<float4*>(C + (size_t)(m0 + ty*8 + i) * N + n0 + tx*4) = v;
    }
}

// ---------------- elementwise helpers ----------------
__global__ void k_zero_f32(float* p, size_t n) {
    size_t i = (size_t)blockIdx.x * blockDim.x + threadIdx.x;
    if (i < n) p[i] = 0.0f;
}
__global__ void k_zero_h(__half* p, size_t n) {
    size_t i = (size_t)blockIdx.x * blockDim.x + threadIdx.x;
    if (i < n) p[i] = __float2half_rn(0.0f);
}
__global__ void k_tohalf(const float* __restrict__ s, __half* __restrict__ hi, size_t n) {
    size_t i = (size_t)blockIdx.x * blockDim.x + threadIdx.x;
    if (i >= n) return;
    hi[i] = __float2half_rn(s[i]);
}
__global__ void k_pad_emb(const float* __restrict__ emb) {
    int idx = blockIdx.x * blockDim.x + threadIdx.x;
    if (idx >= Nn * 16) return;
    int n = idx >> 4, j = idx & 15;
    g_embpad[idx] = (j < Ee) ? emb[n * Ee + j] : 0.0f;
}
__global__ void k_transpose(const float* __restrict__ in, float* __restrict__ out,
                            int R, int C) {
    int idx = blockIdx.x * blockDim.x + threadIdx.x;
    if (idx >= R * C) return;
    int r = idx / C, c = idx - r * C;
    out[c * R + r] = in[idx];
}
template <bool ENC>
__global__ void k_pad_w_t(const float* __restrict__ src, __half* __restrict__ hi,
                          __half* __restrict__ lo, int nout) {
    int idx = blockIdx.x * blockDim.x + threadIdx.x;
    if (idx >= nout * FPK) return;
    int n = idx >> 8, f = idx & 255;
    float v = 0.0f;
    if (f < 198) {
        int k = f / 66, c = f - k * 66;
        if (ENC) {
            if (c == 0) v = src[(k * 65) * nout + n];
            else if (c >= 2) v = src[(k * 65 + c - 1) * nout + n];
        } else {
            v = src[f * nout + n];
        }
    }
    __half h, l; split_h(v, h, l);
    hi[idx] = h; lo[idx] = l;
}
__global__ void k_relu_softmax(float* __restrict__ S) {
    int row = blockIdx.x;
    float* p = S + (size_t)row * Nn;
    int t = threadIdx.x;
    float v[4];
#pragma unroll
    for (int i = 0; i < 4; i++) { float x = p[t + i*256]; v[i] = x > 0.0f ? x : 0.0f; }
    __shared__ float red[256];
    float m = fmaxf(fmaxf(v[0], v[1]), fmaxf(v[2], v[3]));
    red[t] = m; __syncthreads();
    for (int s = 128; s > 0; s >>= 1) { if (t < s) red[t] = fmaxf(red[t], red[t+s]); __syncthreads(); }
    m = red[0]; __syncthreads();
    float e[4], sum = 0.0f;
#pragma unroll
    for (int i = 0; i < 4; i++) { e[i] = expf(v[i] - m); sum += e[i]; }
    red[t] = sum; __syncthreads();
    for (int s = 128; s > 0; s >>= 1) { if (t < s) red[t] += red[t+s]; __syncthreads(); }
    float inv = 1.0f / red[0];
#pragma unroll
    for (int i = 0; i < 4; i++) p[t + i*256] = e[i] * inv;
}
__global__ void k_cheb(float* __restrict__ P) {
    int idx = blockIdx.x * blockDim.x + threadIdx.x;
    if (idx >= NN2) return;
    int r = idx >> 10, c = idx & 1023;
    P[idx] = 2.0f * P[idx] - (r == c ? 1.0f : 0.0f);
}
__global__ void k_set_x_enc(const float* __restrict__ x, int t) {
    int id = blockIdx.x * blockDim.x + threadIdx.x;
    if (id >= ROWS) return;
    int n = id >> 6, b = id & 63;
    float xv = x[((size_t)b * Tt + t) * Nn + n];
    __half xh = __float2half_rn(xv);
    g_XT[((size_t)(b * 66) << 10) + n] = xh;
    g_F[(size_t)id << 8] = xh;
}
__global__ void k_set_xy_dec(const float* __restrict__ ycov, int t) {
    int id = blockIdx.x * blockDim.x + threadIdx.x;
    if (id >= ROWS) return;
    int n = id >> 6, b = id & 63;
    float gv = g_go[id];
    float yv = ycov[((size_t)b * Hor + t) * Nn + n];
    __half gh = __float2half_rn(gv);
    __half yh = __float2half_rn(yv);
    g_XT[((size_t)(b * 66) << 10) + n] = gh;
    g_XT[((size_t)(b * 66 + 1) << 10) + n] = yh;
    size_t fo = (size_t)id << 8;
    g_F[fo] = gh;
    g_F[fo + 1] = yh;
}
__global__ void k_demb(const float* __restrict__ fce) {
    int idx = blockIdx.x * blockDim.x + threadIdx.x;
    if (idx >= ROWS * Ee) return;
    int id = idx / Ee, e = idx - id * Ee;
    const float* hr = g_h + (size_t)id * 64;
    float s = 0.0f;
#pragma unroll
    for (int h = 0; h < 64; h++) s = fmaf(hr[h], fce[h * Ee + e], s);
    g_demb[idx] = s;
}
__global__ void k_init_go(const float* __restrict__ x) {
    int id = blockIdx.x * blockDim.x + threadIdx.x;
    if (id >= ROWS) return;
    int n = id >> 6, b = id & 63;
    g_go[id] = x[((size_t)b * Tt + (Tt - 1)) * Nn + n];
}
__global__ void k_proj_out(const float* __restrict__ pw, const float* __restrict__ pb,
                           float* __restrict__ out, int t) {
    int id = blockIdx.x * blockDim.x + threadIdx.x;
    if (id >= ROWS) return;
    int n = id >> 6, b = id & 63;
    const float* hr = g_h + (size_t)id * 64;
    float s = pb[0];
#pragma unroll
    for (int i = 0; i < 64; i++) s = fmaf(hr[i], pw[i], s);
    g_go[id] = s;
    out[((size_t)b * Hor + t) * Nn + n] = s;
}

// ---------------- orchestration ----------------
extern "C" void kernel_launch(void* const* d_in, const int* in_sizes, int n_in,
                              void* d_out, int out_size) {
    const float* x    = (const float*)d_in[0];
    const float* ycov = (const float*)d_in[1];
    const float* emb  = (const float*)d_in[2];
    const float* fce  = (const float*)d_in[3];
    const float* egw  = (const float*)d_in[4];
    const float* egb  = (const float*)d_in[5];
    const float* euw  = (const float*)d_in[6];
    const float* eub  = (const float*)d_in[7];
    const float* dgw  = (const float*)d_in[8];
    const float* dgb  = (const float*)d_in[9];
    const float* duw  = (const float*)d_in[10];
    const float* dub  = (const float*)d_in[11];
    const float* pw   = (const float*)d_in[12];
    const float* pb   = (const float*)d_in[13];
    float* out = (float*)d_out;

    float *pSe, *pSd, *ph, *pDemb, *pDembT, *pEp, *pEpT;
    __half *pSeh, *pSdh, *pX, *pF;
    __half *pWgeh, *pWgel, *pWueh, *pWuel, *pWgdh, *pWgdl, *pWudh, *pWudl;
    cudaGetSymbolAddress((void**)&pSe, g_S_enc);
    cudaGetSymbolAddress((void**)&pSd, g_S_dec);
    cudaGetSymbolAddress((void**)&ph, g_h);
    cudaGetSymbolAddress((void**)&pDemb, g_demb);
    cudaGetSymbolAddress((void**)&pDembT, g_dembT);
    cudaGetSymbolAddress((void**)&pEp, g_embpad);
    cudaGetSymbolAddress((void**)&pEpT, g_embpadT);
    cudaGetSymbolAddress((void**)&pSeh, g_Se_hi);
    cudaGetSymbolAddress((void**)&pSdh, g_Sd_hi);
    cudaGetSymbolAddress((void**)&pX, g_XT);
    cudaGetSymbolAddress((void**)&pF, g_F);
    cudaGetSymbolAddress((void**)&pWgeh, g_Wge_hi); cudaGetSymbolAddress((void**)&pWgel, g_Wge_lo);
    cudaGetSymbolAddress((void**)&pWueh, g_Wue_hi); cudaGetSymbolAddress((void**)&pWuel, g_Wue_lo);
    cudaGetSymbolAddress((void**)&pWgdh, g_Wgd_hi); cudaGetSymbolAddress((void**)&pWgdl, g_Wgd_lo);
    cudaGetSymbolAddress((void**)&pWudh, g_Wud_hi); cudaGetSymbolAddress((void**)&pWudl, g_Wud_lo);

    constexpr int SMEM_BN128 = 3 * (128 + 128) * 72 * 2;  // 110592
    constexpr int SMEM_BN64  = 3 * (128 + 64) * 72 * 2;   // 82944
    cudaFuncSetAttribute(mma_gemm<128,0,1>, cudaFuncAttributeMaxDynamicSharedMemorySize, SMEM_BN128);
    cudaFuncSetAttribute(mma_gemm<128,1,2>, cudaFuncAttributeMaxDynamicSharedMemorySize, SMEM_BN128);
    cudaFuncSetAttribute(mma_gemm<64,2,2>,  cudaFuncAttributeMaxDynamicSharedMemorySize, SMEM_BN64);

    // ---- setup; launch index 3 (0-based) == diffusion GEMM for ncu
    k_zero_h<<<(int)(((size_t)XTC * Nn + 255) / 256), 256>>>(pX, (size_t)XTC * Nn);     // 0
    k_zero_h<<<(int)((size_t)ROWS * FPK / 256), 256>>>(pF, (size_t)ROWS * FPK);         // 1
    k_zero_f32<<<ROWS * 64 / 256, 256>>>(ph, (size_t)ROWS * 64);                        // 2
    // ncu target: real-shape diffusion (inputs deterministic; output overwritten)
    mma_gemm<128,0,1><<<dim3(33, 16), 256, SMEM_BN128>>>(pSeh, pSeh, pSeh, pX, pX, pX,
                                                         Nn, Nn, 1024, nullptr);        // 3
    k_pad_emb<<<64, 256>>>(emb);
    k_transpose<<<64, 256>>>(pEp, pEpT, Nn, 16);
    sgemm32<<<dim3(16, 8), 256>>>(pEp, pEpT, pSe, Nn, Nn, 16);
    k_relu_softmax<<<Nn, 256>>>(pSe);
    sgemm32<<<dim3(16, 8), 256>>>(pSe, pSe, pSe + NN2, Nn, Nn, Nn);
    k_cheb<<<NN2 / 256, 256>>>(pSe + NN2);
    k_tohalf<<<2 * NN2 / 256, 256>>>(pSe, pSeh, (size_t)2 * NN2);
    k_pad_w_t<true><<<(128 * FPK + 255) / 256, 256>>>(egw, pWgeh, pWgel, 128);
    k_pad_w_t<true><<<(64 * FPK + 255) / 256, 256>>>(euw, pWueh, pWuel, 64);
    k_pad_w_t<false><<<(128 * FPK + 255) / 256, 256>>>(dgw, pWgdh, pWgdl, 128);
    k_pad_w_t<false><<<(64 * FPK + 255) / 256, 256>>>(duw, pWudh, pWudl, 64);

    // ---- encoder (diffusion: fp16 S_hi, segK=1024; MLP: F fp16, W hi/lo 2-seg)
    for (int t = 0; t < Tt; t++) {
        k_set_x_enc<<<256, 256>>>(x, t);
        mma_gemm<128,0,1><<<dim3(33, 16), 256, SMEM_BN128>>>(pSeh, pSeh, pSeh, pX, pX, pX,
                                                             Nn, Nn, 1024, nullptr);
        mma_gemm<128,1,2><<<dim3(1, 512), 256, SMEM_BN128>>>(pF, pF, pF, pWgeh, pWgel, pWgel,
                                                             FPK, FPK, 256, egb);
        mma_gemm<128,0,1><<<dim3(33, 16), 256, SMEM_BN128>>>(pSeh, pSeh, pSeh, pX, pX, pX,
                                                             Nn, Nn, 1024, nullptr);
        mma_gemm<64,2,2><<<dim3(1, 512), 256, SMEM_BN64>>>(pF, pF, pF, pWueh, pWuel, pWuel,
                                                           FPK, FPK, 256, eub);
    }

    // ---- decoder supports
    k_demb<<<ROWS * Ee / 256, 256>>>(fce);
    k_transpose<<<ROWS * Ee / 256, 256>>>(pDemb, pDembT, Nn, Bb * Ee);
    sgemm32<<<dim3(16, 8), 256>>>(pDemb, pDembT, pSd, Nn, Nn, Bb * Ee);
    k_relu_softmax<<<Nn, 256>>>(pSd);
    sgemm32<<<dim3(16, 8), 256>>>(pSd, pSd, pSd + NN2, Nn, Nn, Nn);
    k_cheb<<<NN2 / 256, 256>>>(pSd + NN2);
    k_tohalf<<<2 * NN2 / 256, 256>>>(pSd, pSdh, (size_t)2 * NN2);
    k_init_go<<<256, 256>>>(x);

    // ---- decoder
    for (int t = 0; t < Hor; t++) {
        k_set_xy_dec<<<256, 256>>>(ycov, t);
        mma_gemm<128,0,1><<<dim3(33, 16), 256, SMEM_BN128>>>(pSdh, pSdh, pSdh, pX, pX, pX,
                                                             Nn, Nn, 1024, nullptr);
        mma_gemm<128,1,2><<<dim3(1, 512), 256, SMEM_BN128>>>(pF, pF, pF, pWgdh, pWgdl, pWgdl,
                                                             FPK, FPK, 256, dgb);
        mma_gemm<128,0,1><<<dim3(33, 16), 256, SMEM_BN128>>>(pSdh, pSdh, pSdh, pX, pX, pX,
                                                             Nn, Nn, 1024, nullptr);
        mma_gemm<64,2,2><<<dim3(1, 512), 256, SMEM_BN64>>>(pF, pF, pF, pWudh, pWudl, pWudl,
                                                           FPK, FPK, 256, dub);
        k_proj_out<<<256, 256>>>(pw, pb, out, t);
    }
}

// round 11
// speedup vs baseline: 3.3227x; 1.0582x over previous
#include <cuda_runtime.h>
#include <cuda_fp16.h>
#include <cstdint>
#include <math.h>

constexpr int Bb=64, Tt=12, Nn=1024, Ee=10, Hor=12;
constexpr int ROWS = Nn*Bb;          // 65536
constexpr int NN2  = Nn*Nn;
constexpr int FPK  = 256;            // padded K width of F (3*66=198 -> 256)
constexpr int XTC  = 66*Bb;          // 4224 = Xin^T row count (cols of Xin)

// ---------------- device-global scratch ----------------
__device__ __align__(1024) float g_S_enc[2*NN2];
__device__ __align__(1024) float g_S_dec[2*NN2];
__device__ __align__(1024) float g_R [(size_t)ROWS*64];
__device__ __align__(1024) float g_h [(size_t)ROWS*64];
__device__ __align__(1024) float g_go[ROWS];
__device__ __align__(1024) float g_demb [Nn*Bb*Ee];
__device__ __align__(1024) float g_dembT[Bb*Ee*Nn];
__device__ __align__(1024) float g_embpad [Nn*16];
__device__ __align__(1024) float g_embpadT[16*Nn];

__device__ __align__(1024) __half g_Se_hi[2*NN2];
__device__ __align__(1024) __half g_Sd_hi[2*NN2];
__device__ __align__(1024) __half g_XT[(size_t)XTC*Nn];          // single fp16
__device__ __align__(1024) __half g_F[(size_t)ROWS*FPK];         // single fp16
__device__ __align__(1024) __half g_Wge[128*FPK];
__device__ __align__(1024) __half g_Wue[64*FPK];
__device__ __align__(1024) __half g_Wgd[128*FPK];
__device__ __align__(1024) __half g_Wud[64*FPK];

__device__ __forceinline__ float sigmoidf_(float x){ return 1.0f/(1.0f+expf(-x)); }

__device__ __forceinline__ uint32_t smem_u32(const void* p){
    uint32_t a;
    asm("{ .reg .u64 t; cvta.to.shared.u64 t, %1; cvt.u32.u64 %0, t; }" : "=r"(a) : "l"(p));
    return a;
}
__device__ __forceinline__ void cp_async16(uint32_t dst, const void* src){
    asm volatile("cp.async.cg.shared.global [%0], [%1], 16;" :: "r"(dst), "l"(src));
}
__device__ __forceinline__ void cp_commit(){ asm volatile("cp.async.commit_group;"); }
template <int N>
__device__ __forceinline__ void cp_wait(){ asm volatile("cp.async.wait_group %0;" :: "n"(N)); }

__device__ __forceinline__ void ldsm_x4(uint32_t* r, uint32_t addr){
    asm volatile("ldmatrix.sync.aligned.m8n8.x4.shared.b16 {%0,%1,%2,%3}, [%4];"
        : "=r"(r[0]), "=r"(r[1]), "=r"(r[2]), "=r"(r[3]) : "r"(addr));
}
__device__ __forceinline__ void mma16816(float* c, const uint32_t* a, const uint32_t* b){
    asm volatile("mma.sync.aligned.m16n8k16.row.col.f32.f16.f16.f32 "
        "{%0,%1,%2,%3}, {%4,%5,%6,%7}, {%8,%9}, {%0,%1,%2,%3};"
        : "+f"(c[0]), "+f"(c[1]), "+f"(c[2]), "+f"(c[3])
        : "r"(a[0]), "r"(a[1]), "r"(a[2]), "r"(a[3]), "r"(b[0]), "r"(b[1]));
}

// ---------------- fp16 HMMA GEMM (3-stage, 2 CTAs/SM) -----------------------
// D[M rows, N=BN per block] = sum over NSEG segments Aseg(M x segK) @ Bseg^T,
// fp32 accumulate. A rows = output rows (lda elems); B rows = output COLUMNS,
// K-major (ldb elems). BM=128, BK=64, 256 threads (8 warps, 4m x 2n).
// EPI 0: diffusion -> fp16 scatter into g_F
// EPI 1: gate: z=sig(+bias), c<64 -> z*h into g_XT + g_F; c>=64 -> g_R
// EPI 2: update: hc=tanh(+bias); hn = r*h + (1-r)*hc -> g_h, g_XT, g_F
template <int BN, int EPI, int NSEG>
__global__ void __launch_bounds__(256, 2) mma_gemm(
    const __half* __restrict__ A0, const __half* __restrict__ A1,
    const __half* __restrict__ A2,
    const __half* __restrict__ B0, const __half* __restrict__ B1,
    const __half* __restrict__ B2,
    int lda, int ldb, int segK, const float* __restrict__ bias)
{
    constexpr int BM = 128, LDS = 72;      // 64 + 8 pad (half elems)
    constexpr int NT = BN / 16;            // n8-tiles per warp (8 or 4)
    constexpr uint32_t STG_BYTES = (uint32_t)(BM + BN) * LDS * 2u;
    extern __shared__ __align__(16) char sm[];
    const uint32_t sm0 = smem_u32(sm);

    const int tid = threadIdx.x, lane = tid & 31, wid = tid >> 5;
    const int wm = wid >> 1, wn = wid & 1;
    const int m0 = blockIdx.y * BM, n0 = blockIdx.x * BN;

    const __half* Asg[3] = {A0, A1, A2};
    const __half* Bsg[3] = {B0, B1, B2};
    const int nt_seg = segK >> 6;
    const int KT = NSEG * nt_seg;

    float acc[2][NT][4];
#pragma unroll
    for (int i = 0; i < 2; i++)
#pragma unroll
        for (int j = 0; j < NT; j++)
#pragma unroll
            for (int e = 0; e < 4; e++) acc[i][j][e] = 0.0f;

    const uint32_t aOff = (((uint32_t)(wm*32 + (lane & 15))) * LDS + ((lane >> 4) << 3)) * 2u;
    const uint32_t bOff = (uint32_t)BM * LDS * 2u
        + (((uint32_t)(wn*(BN/2) + (lane & 7) + ((lane >> 4) << 3))) * LDS
           + (((lane >> 3) & 1) << 3)) * 2u;

    auto load_tile = [&](int kt, int stg) {
        const uint32_t sA = sm0 + (uint32_t)stg * STG_BYTES;
        const uint32_t sB = sA + (uint32_t)BM * LDS * 2u;
        int seg = kt / nt_seg;
        int j = kt - seg * nt_seg;
        const char* Ag = (const char*)(Asg[seg] + (size_t)m0 * lda + j * 64);
        const char* Bg = (const char*)(Bsg[seg] + (size_t)n0 * ldb + j * 64);
#pragma unroll
        for (int it = 0; it < 4; it++) {
            int id = (it << 8) + tid;
            int r = id >> 3, c = id & 7;
            cp_async16(sA + (uint32_t)r*144u + (uint32_t)c*16u,
                       Ag + (size_t)r * ((size_t)lda*2) + c*16);
        }
#pragma unroll
        for (int it = 0; it < BN/32; it++) {
            int id = (it << 8) + tid;
            int r = id >> 3, c = id & 7;
            cp_async16(sB + (uint32_t)r*144u + (uint32_t)c*16u,
                       Bg + (size_t)r * ((size_t)ldb*2) + c*16);
        }
        cp_commit();
    };

    load_tile(0, 0);
    if (KT > 1) load_tile(1, 1);

    int stg = 0;
    for (int kt = 0; kt < KT; kt++) {
        if (kt + 1 < KT) cp_wait<1>(); else cp_wait<0>();
        __syncthreads();
        if (kt + 2 < KT) load_tile(kt + 2, (kt + 2) % 3);

        const uint32_t sbase = sm0 + (uint32_t)stg * STG_BYTES;
        const uint32_t aBase = sbase + aOff;
        const uint32_t bBase = sbase + bOff;
#pragma unroll
        for (int ks = 0; ks < 4; ks++) {
            uint32_t a[2][4];
            ldsm_x4(a[0], aBase + (uint32_t)ks*32u);
            ldsm_x4(a[1], aBase + 16u*LDS*2u + (uint32_t)ks*32u);
            uint32_t b[NT/2][4];
#pragma unroll
            for (int p = 0; p < NT/2; p++)
                ldsm_x4(b[p], bBase + (uint32_t)p*16u*LDS*2u + (uint32_t)ks*32u);
#pragma unroll
            for (int mt = 0; mt < 2; mt++)
#pragma unroll
                for (int nt = 0; nt < NT; nt++)
                    mma16816(acc[mt][nt], a[mt], &b[nt >> 1][(nt & 1) * 2]);
        }
        if (++stg == 3) stg = 0;
    }

    // ---------------- epilogue ----------------
    const int rbase = m0 + wm*32 + (lane >> 2);
    const int cbase = n0 + wn*(BN/2) + ((lane & 3) << 1);
#pragma unroll
    for (int mt = 0; mt < 2; mt++) {
#pragma unroll
        for (int nt = 0; nt < NT; nt++) {
#pragma unroll
            for (int e = 0; e < 4; e++) {
                const int row = rbase + mt*16 + ((e >> 1) << 3);
                const int col = cbase + nt*8 + (e & 1);
                const float v = acc[mt][nt][e];
                if (EPI == 0) {
                    const int kk = row >> 10, n = row & 1023;
                    const int b = col / 66, c = col - b * 66;
                    const size_t off = (size_t)((n << 6) + b) * FPK + (kk + 1) * 66 + c;
                    g_F[off] = __float2half_rn(v);
                } else if (EPI == 1) {
                    const int id = row, n = row >> 6, b = row & 63;
                    const float s = sigmoidf_(v + bias[col]);
                    if (col < 64) {
                        const float zh = s * g_h[(size_t)id * 64 + col];
                        const __half hv = __float2half_rn(zh);
                        g_XT[((size_t)(b * 66 + 2 + col) << 10) + n] = hv;
                        g_F[((size_t)id << 8) + 2 + col] = hv;
                    } else {
                        g_R[(size_t)id * 64 + (col - 64)] = s;
                    }
                } else {
                    const int id = row, n = row >> 6, b = row & 63;
                    const float hc = tanhf(v + bias[col]);
                    const size_t o = (size_t)id * 64 + col;
                    const float r = g_R[o], h = g_h[o];
                    const float hn = r * h + (1.0f - r) * hc;
                    g_h[o] = hn;
                    const __half hv = __float2half_rn(hn);
                    g_XT[((size_t)(b * 66 + 2 + col) << 10) + n] = hv;
                    g_F[((size_t)id << 8) + 2 + col] = hv;
                }
            }
        }
    }
}

// ---------------- fp32 SGEMM (setup only) ----------------
__global__ void __launch_bounds__(256) sgemm32(
    const float* __restrict__ A, const float* __restrict__ B,
    float* __restrict__ C, int M, int N, int K)
{
    constexpr int BM = 128, BN = 64, BK = 16;
    __shared__ __align__(16) float As_[BK][BM];
    __shared__ __align__(16) float Bs_[BK][BN];
    const int tid = threadIdx.x;
    const int tx = tid & 15, ty = tid >> 4;
    const int m0 = blockIdx.y * BM, n0 = blockIdx.x * BN;
    float acc[8][4];
#pragma unroll
    for (int i = 0; i < 8; i++)
#pragma unroll
        for (int jj = 0; jj < 4; jj++) acc[i][jj] = 0.0f;
    const int arow0 = tid >> 2, acol0 = (tid & 3) * 4;
    const int brow = tid >> 4, bcol = (tid & 15) * 4;
    for (int kt = 0; kt < K; kt += BK) {
#pragma unroll
        for (int i = 0; i < 2; i++) {
            int r = arow0 + i * 64;
            float4 v = *reinterpret_cast<const float4*>(A + (size_t)(m0 + r) * K + kt + acol0);
            As_[acol0+0][r]=v.x; As_[acol0+1][r]=v.y; As_[acol0+2][r]=v.z; As_[acol0+3][r]=v.w;
        }
        float4 bv = *reinterpret_cast<const float4*>(B + (size_t)(kt + brow) * N + n0 + bcol);
        *reinterpret_cast<float4*>(&Bs_[brow][bcol]) = bv;
        __syncthreads();
#pragma unroll
        for (int k = 0; k < BK; k++) {
            float4 a0 = *reinterpret_cast<const float4*>(&As_[k][ty*8]);
            float4 a1 = *reinterpret_cast<const float4*>(&As_[k][ty*8+4]);
            float4 b0 = *reinterpret_cast<const float4*>(&Bs_[k][tx*4]);
            float am[8]={a0.x,a0.y,a0.z,a0.w,a1.x,a1.y,a1.z,a1.w};
            float bn[4]={b0.x,b0.y,b0.z,b0.w};
#pragma unroll
            for (int i = 0; i < 8; i++)
#pragma unroll
                for (int jj = 0; jj < 4; jj++) acc[i][jj] = fmaf(am[i], bn[jj], acc[i][jj]);
        }
        __syncthreads();
    }
#pragma unroll
    for (int i = 0; i < 8; i++) {
        float4 v = make_float4(acc[i][0], acc[i][1], acc[i][2], acc[i][3]);
        *reinterpret_cast<float4*>(C + (size_t)(m0 + ty*8 + i) * N + n0 + tx*4) = v;
    }
}

// ---------------- elementwise helpers ----------------
__global__ void k_zero_f32(float* p, size_t n) {
    size_t i = (size_t)blockIdx.x * blockDim.x + threadIdx.x;
    if (i < n) p[i] = 0.0f;
}
__global__ void k_zero_h(__half* p, size_t n) {
    size_t i = (size_t)blockIdx.x * blockDim.x + threadIdx.x;
    if (i < n) p[i] = __float2half_rn(0.0f);
}
__global__ void k_tohalf(const float* __restrict__ s, __half* __restrict__ hi, size_t n) {
    size_t i = (size_t)blockIdx.x * blockDim.x + threadIdx.x;
    if (i >= n) return;
    hi[i] = __float2half_rn(s[i]);
}
__global__ void k_pad_emb(const float* __restrict__ emb) {
    int idx = blockIdx.x * blockDim.x + threadIdx.x;
    if (idx >= Nn * 16) return;
    int n = idx >> 4, j = idx & 15;
    g_embpad[idx] = (j < Ee) ? emb[n * Ee + j] : 0.0f;
}
__global__ void k_transpose(const float* __restrict__ in, float* __restrict__ out,
                            int R, int C) {
    int idx = blockIdx.x * blockDim.x + threadIdx.x;
    if (idx >= R * C) return;
    int r = idx / C, c = idx - r * C;
    out[c * R + r] = in[idx];
}
template <bool ENC>
__global__ void k_pad_w_t(const float* __restrict__ src, __half* __restrict__ dst,
                          int nout) {
    int idx = blockIdx.x * blockDim.x + threadIdx.x;
    if (idx >= nout * FPK) return;
    int n = idx >> 8, f = idx & 255;
    float v = 0.0f;
    if (f < 198) {
        int k = f / 66, c = f - k * 66;
        if (ENC) {
            if (c == 0) v = src[(k * 65) * nout + n];
            else if (c >= 2) v = src[(k * 65 + c - 1) * nout + n];
        } else {
            v = src[f * nout + n];
        }
    }
    dst[idx] = __float2half_rn(v);
}
__global__ void k_relu_softmax(float* __restrict__ S) {
    int row = blockIdx.x;
    float* p = S + (size_t)row * Nn;
    int t = threadIdx.x;
    float v[4];
#pragma unroll
    for (int i = 0; i < 4; i++) { float x = p[t + i*256]; v[i] = x > 0.0f ? x : 0.0f; }
    __shared__ float red[256];
    float m = fmaxf(fmaxf(v[0], v[1]), fmaxf(v[2], v[3]));
    red[t] = m; __syncthreads();
    for (int s = 128; s > 0; s >>= 1) { if (t < s) red[t] = fmaxf(red[t], red[t+s]); __syncthreads(); }
    m = red[0]; __syncthreads();
    float e[4], sum = 0.0f;
#pragma unroll
    for (int i = 0; i < 4; i++) { e[i] = expf(v[i] - m); sum += e[i]; }
    red[t] = sum; __syncthreads();
    for (int s = 128; s > 0; s >>= 1) { if (t < s) red[t] += red[t+s]; __syncthreads(); }
    float inv = 1.0f / red[0];
#pragma unroll
    for (int i = 0; i < 4; i++) p[t + i*256] = e[i] * inv;
}
__global__ void k_cheb(float* __restrict__ P) {
    int idx = blockIdx.x * blockDim.x + threadIdx.x;
    if (idx >= NN2) return;
    int r = idx >> 10, c = idx & 1023;
    P[idx] = 2.0f * P[idx] - (r == c ? 1.0f : 0.0f);
}
__global__ void k_set_x_enc(const float* __restrict__ x, int t) {
    int id = blockIdx.x * blockDim.x + threadIdx.x;
    if (id >= ROWS) return;
    int n = id >> 6, b = id & 63;
    float xv = x[((size_t)b * Tt + t) * Nn + n];
    __half xh = __float2half_rn(xv);
    g_XT[((size_t)(b * 66) << 10) + n] = xh;
    g_F[(size_t)id << 8] = xh;
}
__global__ void k_set_xy_dec(const float* __restrict__ ycov, int t) {
    int id = blockIdx.x * blockDim.x + threadIdx.x;
    if (id >= ROWS) return;
    int n = id >> 6, b = id & 63;
    float gv = g_go[id];
    float yv = ycov[((size_t)b * Hor + t) * Nn + n];
    __half gh = __float2half_rn(gv);
    __half yh = __float2half_rn(yv);
    g_XT[((size_t)(b * 66) << 10) + n] = gh;
    g_XT[((size_t)(b * 66 + 1) << 10) + n] = yh;
    size_t fo = (size_t)id << 8;
    g_F[fo] = gh;
    g_F[fo + 1] = yh;
}
__global__ void k_demb(const float* __restrict__ fce) {
    int idx = blockIdx.x * blockDim.x + threadIdx.x;
    if (idx >= ROWS * Ee) return;
    int id = idx / Ee, e = idx - id * Ee;
    const float* hr = g_h + (size_t)id * 64;
    float s = 0.0f;
#pragma unroll
    for (int h = 0; h < 64; h++) s = fmaf(hr[h], fce[h * Ee + e], s);
    g_demb[idx] = s;
}
__global__ void k_init_go(const float* __restrict__ x) {
    int id = blockIdx.x * blockDim.x + threadIdx.x;
    if (id >= ROWS) return;
    int n = id >> 6, b = id & 63;
    g_go[id] = x[((size_t)b * Tt + (Tt - 1)) * Nn + n];
}
__global__ void k_proj_out(const float* __restrict__ pw, const float* __restrict__ pb,
                           float* __restrict__ out, int t) {
    int id = blockIdx.x * blockDim.x + threadIdx.x;
    if (id >= ROWS) return;
    int n = id >> 6, b = id & 63;
    const float* hr = g_h + (size_t)id * 64;
    float s = pb[0];
#pragma unroll
    for (int i = 0; i < 64; i++) s = fmaf(hr[i], pw[i], s);
    g_go[id] = s;
    out[((size_t)b * Hor + t) * Nn + n] = s;
}

// ---------------- orchestration ----------------
extern "C" void kernel_launch(void* const* d_in, const int* in_sizes, int n_in,
                              void* d_out, int out_size) {
    const float* x    = (const float*)d_in[0];
    const float* ycov = (const float*)d_in[1];
    const float* emb  = (const float*)d_in[2];
    const float* fce  = (const float*)d_in[3];
    const float* egw  = (const float*)d_in[4];
    const float* egb  = (const float*)d_in[5];
    const float* euw  = (const float*)d_in[6];
    const float* eub  = (const float*)d_in[7];
    const float* dgw  = (const float*)d_in[8];
    const float* dgb  = (const float*)d_in[9];
    const float* duw  = (const float*)d_in[10];
    const float* dub  = (const float*)d_in[11];
    const float* pw   = (const float*)d_in[12];
    const float* pb   = (const float*)d_in[13];
    float* out = (float*)d_out;

    float *pSe, *pSd, *ph, *pDemb, *pDembT, *pEp, *pEpT;
    __half *pSeh, *pSdh, *pX, *pF, *pWge, *pWue, *pWgd, *pWud;
    cudaGetSymbolAddress((void**)&pSe, g_S_enc);
    cudaGetSymbolAddress((void**)&pSd, g_S_dec);
    cudaGetSymbolAddress((void**)&ph, g_h);
    cudaGetSymbolAddress((void**)&pDemb, g_demb);
    cudaGetSymbolAddress((void**)&pDembT, g_dembT);
    cudaGetSymbolAddress((void**)&pEp, g_embpad);
    cudaGetSymbolAddress((void**)&pEpT, g_embpadT);
    cudaGetSymbolAddress((void**)&pSeh, g_Se_hi);
    cudaGetSymbolAddress((void**)&pSdh, g_Sd_hi);
    cudaGetSymbolAddress((void**)&pX, g_XT);
    cudaGetSymbolAddress((void**)&pF, g_F);
    cudaGetSymbolAddress((void**)&pWge, g_Wge);
    cudaGetSymbolAddress((void**)&pWue, g_Wue);
    cudaGetSymbolAddress((void**)&pWgd, g_Wgd);
    cudaGetSymbolAddress((void**)&pWud, g_Wud);

    constexpr int SMEM_BN128 = 3 * (128 + 128) * 72 * 2;  // 110592
    constexpr int SMEM_BN64  = 3 * (128 + 64) * 72 * 2;   // 82944
    cudaFuncSetAttribute(mma_gemm<128,0,1>, cudaFuncAttributeMaxDynamicSharedMemorySize, SMEM_BN128);
    cudaFuncSetAttribute(mma_gemm<128,1,1>, cudaFuncAttributeMaxDynamicSharedMemorySize, SMEM_BN128);
    cudaFuncSetAttribute(mma_gemm<64,2,1>,  cudaFuncAttributeMaxDynamicSharedMemorySize, SMEM_BN64);

    // ---- setup; launch index 3 (0-based) == diffusion GEMM for ncu
    k_zero_h<<<(int)(((size_t)XTC * Nn + 255) / 256), 256>>>(pX, (size_t)XTC * Nn);     // 0
    k_zero_h<<<(int)((size_t)ROWS * FPK / 256), 256>>>(pF, (size_t)ROWS * FPK);         // 1
    k_zero_f32<<<ROWS * 64 / 256, 256>>>(ph, (size_t)ROWS * 64);                        // 2
    // ncu target: real-shape diffusion (inputs deterministic; output overwritten)
    mma_gemm<128,0,1><<<dim3(33, 16), 256, SMEM_BN128>>>(pSeh, pSeh, pSeh, pX, pX, pX,
                                                         Nn, Nn, 1024, nullptr);        // 3
    k_pad_emb<<<64, 256>>>(emb);
    k_transpose<<<64, 256>>>(pEp, pEpT, Nn, 16);
    sgemm32<<<dim3(16, 8), 256>>>(pEp, pEpT, pSe, Nn, Nn, 16);
    k_relu_softmax<<<Nn, 256>>>(pSe);
    sgemm32<<<dim3(16, 8), 256>>>(pSe, pSe, pSe + NN2, Nn, Nn, Nn);
    k_cheb<<<NN2 / 256, 256>>>(pSe + NN2);
    k_tohalf<<<2 * NN2 / 256, 256>>>(pSe, pSeh, (size_t)2 * NN2);
    k_pad_w_t<true><<<(128 * FPK + 255) / 256, 256>>>(egw, pWge, 128);
    k_pad_w_t<true><<<(64 * FPK + 255) / 256, 256>>>(euw, pWue, 64);
    k_pad_w_t<false><<<(128 * FPK + 255) / 256, 256>>>(dgw, pWgd, 128);
    k_pad_w_t<false><<<(64 * FPK + 255) / 256, 256>>>(duw, pWud, 64);

    // ---- encoder (all operands single fp16; diffusion segK=1024, MLP segK=256)
    for (int t = 0; t < Tt; t++) {
        k_set_x_enc<<<256, 256>>>(x, t);
        mma_gemm<128,0,1><<<dim3(33, 16), 256, SMEM_BN128>>>(pSeh, pSeh, pSeh, pX, pX, pX,
                                                             Nn, Nn, 1024, nullptr);
        mma_gemm<128,1,1><<<dim3(1, 512), 256, SMEM_BN128>>>(pF, pF, pF, pWge, pWge, pWge,
                                                             FPK, FPK, 256, egb);
        mma_gemm<128,0,1><<<dim3(33, 16), 256, SMEM_BN128>>>(pSeh, pSeh, pSeh, pX, pX, pX,
                                                             Nn, Nn, 1024, nullptr);
        mma_gemm<64,2,1><<<dim3(1, 512), 256, SMEM_BN64>>>(pF, pF, pF, pWue, pWue, pWue,
                                                           FPK, FPK, 256, eub);
    }

    // ---- decoder supports
    k_demb<<<ROWS * Ee / 256, 256>>>(fce);
    k_transpose<<<ROWS * Ee / 256, 256>>>(pDemb, pDembT, Nn, Bb * Ee);
    sgemm32<<<dim3(16, 8), 256>>>(pDemb, pDembT, pSd, Nn, Nn, Bb * Ee);
    k_relu_softmax<<<Nn, 256>>>(pSd);
    sgemm32<<<dim3(16, 8), 256>>>(pSd, pSd, pSd + NN2, Nn, Nn, Nn);
    k_cheb<<<NN2 / 256, 256>>>(pSd + NN2);
    k_tohalf<<<2 * NN2 / 256, 256>>>(pSd, pSdh, (size_t)2 * NN2);
    k_init_go<<<256, 256>>>(x);

    // ---- decoder
    for (int t = 0; t < Hor; t++) {
        k_set_xy_dec<<<256, 256>>>(ycov, t);
        mma_gemm<128,0,1><<<dim3(33, 16), 256, SMEM_BN128>>>(pSdh, pSdh, pSdh, pX, pX, pX,
                                                             Nn, Nn, 1024, nullptr);
        mma_gemm<128,1,1><<<dim3(1, 512), 256, SMEM_BN128>>>(pF, pF, pF, pWgd, pWgd, pWgd,
                                                             FPK, FPK, 256, dgb);
        mma_gemm<128,0,1><<<dim3(33, 16), 256, SMEM_BN128>>>(pSdh, pSdh, pSdh, pX, pX, pX,
                                                             Nn, Nn, 1024, nullptr);
        mma_gemm<64,2,1><<<dim3(1, 512), 256, SMEM_BN64>>>(pF, pF, pF, pWud, pWud, pWud,
                                                           FPK, FPK, 256, dub);
        k_proj_out<<<256, 256>>>(pw, pb, out, t);
    }
}

// round 12
// speedup vs baseline: 4.0323x; 1.2136x over previous
#include <cuda_runtime.h>
#include <cuda_fp16.h>
#include <cstdint>
#include <math.h>

constexpr int Bb=64, Tt=12, Nn=1024, Ee=10, Hor=12;
constexpr int ROWS = Nn*Bb;          // 65536
constexpr int NN2  = Nn*Nn;
constexpr int FPK  = 256;            // padded K width of F (3*66=198 -> 256)
constexpr int XTC  = 66*Bb;          // 4224 = Xin^T row count (cols of Xin)

// ---------------- device-global scratch ----------------
__device__ __align__(1024) float g_S_enc[2*NN2];
__device__ __align__(1024) float g_S_dec[2*NN2];
__device__ __align__(1024) float g_R [(size_t)ROWS*64];
__device__ __align__(1024) float g_h [(size_t)ROWS*64];
__device__ __align__(1024) float g_go[ROWS];
__device__ __align__(1024) float g_demb [Nn*Bb*Ee];
__device__ __align__(1024) float g_dembT[Bb*Ee*Nn];
__device__ __align__(1024) float g_embpad [Nn*16];
__device__ __align__(1024) float g_embpadT[16*Nn];

__device__ __align__(1024) __half g_Se_hi[2*NN2];
__device__ __align__(1024) __half g_Sd_hi[2*NN2];
__device__ __align__(1024) __half g_XT[(size_t)XTC*Nn];          // single fp16
__device__ __align__(1024) __half g_F[(size_t)ROWS*FPK];         // single fp16
__device__ __align__(1024) __half g_Wge[128*FPK];
__device__ __align__(1024) __half g_Wue[64*FPK];
__device__ __align__(1024) __half g_Wgd[128*FPK];
__device__ __align__(1024) __half g_Wud[64*FPK];

__device__ __forceinline__ float sigmoidf_(float x){ return 1.0f/(1.0f+expf(-x)); }

__device__ __forceinline__ uint32_t smem_u32(const void* p){
    uint32_t a;
    asm("{ .reg .u64 t; cvta.to.shared.u64 t, %1; cvt.u32.u64 %0, t; }" : "=r"(a) : "l"(p));
    return a;
}
__device__ __forceinline__ void cp_async16(uint32_t dst, const void* src){
    asm volatile("cp.async.cg.shared.global [%0], [%1], 16;" :: "r"(dst), "l"(src));
}
__device__ __forceinline__ void cp_commit(){ asm volatile("cp.async.commit_group;"); }
template <int N>
__device__ __forceinline__ void cp_wait(){ asm volatile("cp.async.wait_group %0;" :: "n"(N)); }

__device__ __forceinline__ void ldsm_x4(uint32_t* r, uint32_t addr){
    asm volatile("ldmatrix.sync.aligned.m8n8.x4.shared.b16 {%0,%1,%2,%3}, [%4];"
        : "=r"(r[0]), "=r"(r[1]), "=r"(r[2]), "=r"(r[3]) : "r"(addr));
}
__device__ __forceinline__ void mma16816(float* c, const uint32_t* a, const uint32_t* b){
    asm volatile("mma.sync.aligned.m16n8k16.row.col.f32.f16.f16.f32 "
        "{%0,%1,%2,%3}, {%4,%5,%6,%7}, {%8,%9}, {%0,%1,%2,%3};"
        : "+f"(c[0]), "+f"(c[1]), "+f"(c[2]), "+f"(c[3])
        : "r"(a[0]), "r"(a[1]), "r"(a[2]), "r"(a[3]), "r"(b[0]), "r"(b[1]));
}

// ---------------- fp16 HMMA GEMM (3-stage, 2 CTAs/SM) -----------------------
// D[M rows, N=BN per block] = sum over NSEG segments Aseg(M x segK) @ Bseg^T,
// fp32 accumulate. A rows = output rows (lda elems); B rows = output COLUMNS,
// K-major (ldb elems). BM=128, BK=64, 256 threads (8 warps, 4m x 2n).
// Epilogues use half2/float2 paired accesses (acc e=0,1 / 2,3 are col-adjacent).
// EPI 0: diffusion -> fp16 scatter into g_F
// EPI 1: gate: z=sig(+bias), c<64 -> z*h into g_XT + g_F; c>=64 -> g_R
// EPI 2: update: hc=tanh(+bias); hn = r*h + (1-r)*hc -> g_h, g_XT, g_F
template <int BN, int EPI, int NSEG>
__global__ void __launch_bounds__(256, 2) mma_gemm(
    const __half* __restrict__ A0, const __half* __restrict__ A1,
    const __half* __restrict__ A2,
    const __half* __restrict__ B0, const __half* __restrict__ B1,
    const __half* __restrict__ B2,
    int lda, int ldb, int segK, const float* __restrict__ bias)
{
    constexpr int BM = 128, LDS = 72;      // 64 + 8 pad (half elems)
    constexpr int NT = BN / 16;            // n8-tiles per warp (8 or 4)
    constexpr uint32_t STG_BYTES = (uint32_t)(BM + BN) * LDS * 2u;
    extern __shared__ __align__(16) char sm[];
    const uint32_t sm0 = smem_u32(sm);

    const int tid = threadIdx.x, lane = tid & 31, wid = tid >> 5;
    const int wm = wid >> 1, wn = wid & 1;
    const int m0 = blockIdx.y * BM, n0 = blockIdx.x * BN;

    const __half* Asg[3] = {A0, A1, A2};
    const __half* Bsg[3] = {B0, B1, B2};
    const int nt_seg = segK >> 6;
    const int KT = NSEG * nt_seg;

    float acc[2][NT][4];
#pragma unroll
    for (int i = 0; i < 2; i++)
#pragma unroll
        for (int j = 0; j < NT; j++)
#pragma unroll
            for (int e = 0; e < 4; e++) acc[i][j][e] = 0.0f;

    const uint32_t aOff = (((uint32_t)(wm*32 + (lane & 15))) * LDS + ((lane >> 4) << 3)) * 2u;
    const uint32_t bOff = (uint32_t)BM * LDS * 2u
        + (((uint32_t)(wn*(BN/2) + (lane & 7) + ((lane >> 4) << 3))) * LDS
           + (((lane >> 3) & 1) << 3)) * 2u;

    auto load_tile = [&](int kt, int stg) {
        const uint32_t sA = sm0 + (uint32_t)stg * STG_BYTES;
        const uint32_t sB = sA + (uint32_t)BM * LDS * 2u;
        int seg = kt / nt_seg;
        int j = kt - seg * nt_seg;
        const char* Ag = (const char*)(Asg[seg] + (size_t)m0 * lda + j * 64);
        const char* Bg = (const char*)(Bsg[seg] + (size_t)n0 * ldb + j * 64);
#pragma unroll
        for (int it = 0; it < 4; it++) {
            int id = (it << 8) + tid;
            int r = id >> 3, c = id & 7;
            cp_async16(sA + (uint32_t)r*144u + (uint32_t)c*16u,
                       Ag + (size_t)r * ((size_t)lda*2) + c*16);
        }
#pragma unroll
        for (int it = 0; it < BN/32; it++) {
            int id = (it << 8) + tid;
            int r = id >> 3, c = id & 7;
            cp_async16(sB + (uint32_t)r*144u + (uint32_t)c*16u,
                       Bg + (size_t)r * ((size_t)ldb*2) + c*16);
        }
        cp_commit();
    };

    load_tile(0, 0);
    if (KT > 1) load_tile(1, 1);

    int stg = 0;
    for (int kt = 0; kt < KT; kt++) {
        if (kt + 1 < KT) cp_wait<1>(); else cp_wait<0>();
        __syncthreads();
        if (kt + 2 < KT) load_tile(kt + 2, (kt + 2) % 3);

        const uint32_t sbase = sm0 + (uint32_t)stg * STG_BYTES;
        const uint32_t aBase = sbase + aOff;
        const uint32_t bBase = sbase + bOff;
#pragma unroll
        for (int ks = 0; ks < 4; ks++) {
            uint32_t a[2][4];
            ldsm_x4(a[0], aBase + (uint32_t)ks*32u);
            ldsm_x4(a[1], aBase + 16u*LDS*2u + (uint32_t)ks*32u);
            uint32_t b[NT/2][4];
#pragma unroll
            for (int p = 0; p < NT/2; p++)
                ldsm_x4(b[p], bBase + (uint32_t)p*16u*LDS*2u + (uint32_t)ks*32u);
#pragma unroll
            for (int mt = 0; mt < 2; mt++)
#pragma unroll
                for (int nt = 0; nt < NT; nt++)
                    mma16816(acc[mt][nt], a[mt], &b[nt >> 1][(nt & 1) * 2]);
        }
        if (++stg == 3) stg = 0;
    }

    // ---------------- epilogue (paired half2/float2) ----------------
    const int rbase = m0 + wm*32 + (lane >> 2);
    const int cb = n0 + wn*(BN/2) + ((lane & 3) << 1);   // even
#pragma unroll
    for (int mt = 0; mt < 2; mt++) {
#pragma unroll
        for (int nt = 0; nt < NT; nt++) {
#pragma unroll
            for (int ep = 0; ep < 2; ep++) {
                const int row = rbase + mt*16 + ep*8;
                const int col0 = cb + nt*8;              // even; pair never straddles 66-block
                const float v0 = acc[mt][nt][ep*2 + 0];
                const float v1 = acc[mt][nt][ep*2 + 1];
                if (EPI == 0) {
                    const int kk = row >> 10, n = row & 1023;
                    const int b = col0 / 66, c = col0 - b * 66;
                    const size_t off = (size_t)((n << 6) + b) * FPK + (kk + 1) * 66 + c;
                    *reinterpret_cast<__half2*>(&g_F[off]) = __floats2half2_rn(v0, v1);
                } else if (EPI == 1) {
                    const int id = row, n = row >> 6, b = row & 63;
                    if (col0 < 64) {                      // warp-uniform (wn==0)
                        const float2 hp = *reinterpret_cast<const float2*>(
                            &g_h[(size_t)id * 64 + col0]);
                        const float zh0 = sigmoidf_(v0 + bias[col0])     * hp.x;
                        const float zh1 = sigmoidf_(v1 + bias[col0 + 1]) * hp.y;
                        const __half h0 = __float2half_rn(zh0);
                        const __half h1 = __float2half_rn(zh1);
                        g_XT[((size_t)(b * 66 + 2 + col0)     << 10) + n] = h0;
                        g_XT[((size_t)(b * 66 + 3 + col0)     << 10) + n] = h1;
                        *reinterpret_cast<__half2*>(&g_F[((size_t)id << 8) + 2 + col0]) =
                            __halves2half2(h0, h1);
                    } else {                              // warp-uniform (wn==1)
                        float2 rv;
                        rv.x = sigmoidf_(v0 + bias[col0]);
                        rv.y = sigmoidf_(v1 + bias[col0 + 1]);
                        *reinterpret_cast<float2*>(&g_R[(size_t)id * 64 + (col0 - 64)]) = rv;
                    }
                } else {
                    const int id = row, n = row >> 6, b = row & 63;
                    const size_t o = (size_t)id * 64 + col0;
                    const float2 rp = *reinterpret_cast<const float2*>(&g_R[o]);
                    const float2 hp = *reinterpret_cast<const float2*>(&g_h[o]);
                    const float hc0 = tanhf(v0 + bias[col0]);
                    const float hc1 = tanhf(v1 + bias[col0 + 1]);
                    const float hn0 = rp.x * hp.x + (1.0f - rp.x) * hc0;
                    const float hn1 = rp.y * hp.y + (1.0f - rp.y) * hc1;
                    *reinterpret_cast<float2*>(&g_h[o]) = make_float2(hn0, hn1);
                    const __half h0 = __float2half_rn(hn0);
                    const __half h1 = __float2half_rn(hn1);
                    g_XT[((size_t)(b * 66 + 2 + col0) << 10) + n] = h0;
                    g_XT[((size_t)(b * 66 + 3 + col0) << 10) + n] = h1;
                    *reinterpret_cast<__half2*>(&g_F[((size_t)id << 8) + 2 + col0]) =
                        __halves2half2(h0, h1);
                }
            }
        }
    }
}

// ---------------- fp32 SGEMM (setup only) ----------------
__global__ void __launch_bounds__(256) sgemm32(
    const float* __restrict__ A, const float* __restrict__ B,
    float* __restrict__ C, int M, int N, int K)
{
    constexpr int BM = 128, BN = 64, BK = 16;
    __shared__ __align__(16) float As_[BK][BM];
    __shared__ __align__(16) float Bs_[BK][BN];
    const int tid = threadIdx.x;
    const int tx = tid & 15, ty = tid >> 4;
    const int m0 = blockIdx.y * BM, n0 = blockIdx.x * BN;
    float acc[8][4];
#pragma unroll
    for (int i = 0; i < 8; i++)
#pragma unroll
        for (int jj = 0; jj < 4; jj++) acc[i][jj] = 0.0f;
    const int arow0 = tid >> 2, acol0 = (tid & 3) * 4;
    const int brow = tid >> 4, bcol = (tid & 15) * 4;
    for (int kt = 0; kt < K; kt += BK) {
#pragma unroll
        for (int i = 0; i < 2; i++) {
            int r = arow0 + i * 64;
            float4 v = *reinterpret_cast<const float4*>(A + (size_t)(m0 + r) * K + kt + acol0);
            As_[acol0+0][r]=v.x; As_[acol0+1][r]=v.y; As_[acol0+2][r]=v.z; As_[acol0+3][r]=v.w;
        }
        float4 bv = *reinterpret_cast<const float4*>(B + (size_t)(kt + brow) * N + n0 + bcol);
        *reinterpret_cast<float4*>(&Bs_[brow][bcol]) = bv;
        __syncthreads();
#pragma unroll
        for (int k = 0; k < BK; k++) {
            float4 a0 = *reinterpret_cast<const float4*>(&As_[k][ty*8]);
            float4 a1 = *reinterpret_cast<const float4*>(&As_[k][ty*8+4]);
            float4 b0 = *reinterpret_cast<const float4*>(&Bs_[k][tx*4]);
            float am[8]={a0.x,a0.y,a0.z,a0.w,a1.x,a1.y,a1.z,a1.w};
            float bn[4]={b0.x,b0.y,b0.z,b0.w};
#pragma unroll
            for (int i = 0; i < 8; i++)
#pragma unroll
                for (int jj = 0; jj < 4; jj++) acc[i][jj] = fmaf(am[i], bn[jj], acc[i][jj]);
        }
        __syncthreads();
    }
#pragma unroll
    for (int i = 0; i < 8; i++) {
        float4 v = make_float4(acc[i][0], acc[i][1], acc[i][2], acc[i][3]);
        *reinterpret_cast<float4*>(C + (size_t)(m0 + ty*8 + i) * N + n0 + tx*4) = v;
    }
}

// ---------------- elementwise helpers ----------------
// one kernel zeroing all recurrent state: g_h, XT h-slots, F h-slots
__global__ void k_zero_state() {
    int idx = blockIdx.x * blockDim.x + threadIdx.x;
    if (idx >= ROWS * 64) return;
    int id = idx >> 6, i = idx & 63;
    int n = id >> 6, b = id & 63;
    g_h[idx] = 0.0f;
    g_XT[((size_t)(b * 66 + 2 + i) << 10) + n] = __float2half_rn(0.0f);
    g_F[((size_t)id << 8) + 2 + i] = __float2half_rn(0.0f);
}
__global__ void k_tohalf(const float* __restrict__ s, __half* __restrict__ hi, size_t n) {
    size_t i = (size_t)blockIdx.x * blockDim.x + threadIdx.x;
    if (i >= n) return;
    hi[i] = __float2half_rn(s[i]);
}
__global__ void k_pad_emb(const float* __restrict__ emb) {
    int idx = blockIdx.x * blockDim.x + threadIdx.x;
    if (idx >= Nn * 16) return;
    int n = idx >> 4, j = idx & 15;
    g_embpad[idx] = (j < Ee) ? emb[n * Ee + j] : 0.0f;
}
__global__ void k_transpose(const float* __restrict__ in, float* __restrict__ out,
                            int R, int C) {
    int idx = blockIdx.x * blockDim.x + threadIdx.x;
    if (idx >= R * C) return;
    int r = idx / C, c = idx - r * C;
    out[c * R + r] = in[idx];
}
template <bool ENC>
__global__ void k_pad_w_t(const float* __restrict__ src, __half* __restrict__ dst,
                          int nout) {
    int idx = blockIdx.x * blockDim.x + threadIdx.x;
    if (idx >= nout * FPK) return;
    int n = idx >> 8, f = idx & 255;
    float v = 0.0f;
    if (f < 198) {
        int k = f / 66, c = f - k * 66;
        if (ENC) {
            if (c == 0) v = src[(k * 65) * nout + n];
            else if (c >= 2) v = src[(k * 65 + c - 1) * nout + n];
        } else {
            v = src[f * nout + n];
        }
    }
    dst[idx] = __float2half_rn(v);
}
__global__ void k_relu_softmax(float* __restrict__ S) {
    int row = blockIdx.x;
    float* p = S + (size_t)row * Nn;
    int t = threadIdx.x;
    float v[4];
#pragma unroll
    for (int i = 0; i < 4; i++) { float x = p[t + i*256]; v[i] = x > 0.0f ? x : 0.0f; }
    __shared__ float red[256];
    float m = fmaxf(fmaxf(v[0], v[1]), fmaxf(v[2], v[3]));
    red[t] = m; __syncthreads();
    for (int s = 128; s > 0; s >>= 1) { if (t < s) red[t] = fmaxf(red[t], red[t+s]); __syncthreads(); }
    m = red[0]; __syncthreads();
    float e[4], sum = 0.0f;
#pragma unroll
    for (int i = 0; i < 4; i++) { e[i] = expf(v[i] - m); sum += e[i]; }
    red[t] = sum; __syncthreads();
    for (int s = 128; s > 0; s >>= 1) { if (t < s) red[t] += red[t+s]; __syncthreads(); }
    float inv = 1.0f / red[0];
#pragma unroll
    for (int i = 0; i < 4; i++) p[t + i*256] = e[i] * inv;
}
__global__ void k_cheb(float* __restrict__ P) {
    int idx = blockIdx.x * blockDim.x + threadIdx.x;
    if (idx >= NN2) return;
    int r = idx >> 10, c = idx & 1023;
    P[idx] = 2.0f * P[idx] - (r == c ? 1.0f : 0.0f);
}
__global__ void k_set_x_enc(const float* __restrict__ x, int t) {
    int id = blockIdx.x * blockDim.x + threadIdx.x;
    if (id >= ROWS) return;
    int n = id >> 6, b = id & 63;
    float xv = x[((size_t)b * Tt + t) * Nn + n];
    __half xh = __float2half_rn(xv);
    g_XT[((size_t)(b * 66) << 10) + n] = xh;
    g_F[(size_t)id << 8] = xh;
}
__global__ void k_set_xy_dec(const float* __restrict__ ycov, int t) {
    int id = blockIdx.x * blockDim.x + threadIdx.x;
    if (id >= ROWS) return;
    int n = id >> 6, b = id & 63;
    float gv = g_go[id];
    float yv = ycov[((size_t)b * Hor + t) * Nn + n];
    __half gh = __float2half_rn(gv);
    __half yh = __float2half_rn(yv);
    g_XT[((size_t)(b * 66) << 10) + n] = gh;
    g_XT[((size_t)(b * 66 + 1) << 10) + n] = yh;
    size_t fo = (size_t)id << 8;
    g_F[fo] = gh;
    g_F[fo + 1] = yh;
}
__global__ void k_demb(const float* __restrict__ fce) {
    int idx = blockIdx.x * blockDim.x + threadIdx.x;
    if (idx >= ROWS * Ee) return;
    int id = idx / Ee, e = idx - id * Ee;
    const float* hr = g_h + (size_t)id * 64;
    float s = 0.0f;
#pragma unroll
    for (int h = 0; h < 64; h++) s = fmaf(hr[h], fce[h * Ee + e], s);
    g_demb[idx] = s;
}
__global__ void k_init_go(const float* __restrict__ x) {
    int id = blockIdx.x * blockDim.x + threadIdx.x;
    if (id >= ROWS) return;
    int n = id >> 6, b = id & 63;
    g_go[id] = x[((size_t)b * Tt + (Tt - 1)) * Nn + n];
}
__global__ void k_proj_out(const float* __restrict__ pw, const float* __restrict__ pb,
                           float* __restrict__ out, int t) {
    int id = blockIdx.x * blockDim.x + threadIdx.x;
    if (id >= ROWS) return;
    int n = id >> 6, b = id & 63;
    const float* hr = g_h + (size_t)id * 64;
    float s = pb[0];
#pragma unroll
    for (int i = 0; i < 64; i++) s = fmaf(hr[i], pw[i], s);
    g_go[id] = s;
    out[((size_t)b * Hor + t) * Nn + n] = s;
}

// ---------------- orchestration ----------------
extern "C" void kernel_launch(void* const* d_in, const int* in_sizes, int n_in,
                              void* d_out, int out_size) {
    const float* x    = (const float*)d_in[0];
    const float* ycov = (const float*)d_in[1];
    const float* emb  = (const float*)d_in[2];
    const float* fce  = (const float*)d_in[3];
    const float* egw  = (const float*)d_in[4];
    const float* egb  = (const float*)d_in[5];
    const float* euw  = (const float*)d_in[6];
    const float* eub  = (const float*)d_in[7];
    const float* dgw  = (const float*)d_in[8];
    const float* dgb  = (const float*)d_in[9];
    const float* duw  = (const float*)d_in[10];
    const float* dub  = (const float*)d_in[11];
    const float* pw   = (const float*)d_in[12];
    const float* pb   = (const float*)d_in[13];
    float* out = (float*)d_out;

    float *pSe, *pSd, *pDemb, *pDembT, *pEp, *pEpT;
    __half *pSeh, *pSdh, *pX, *pF, *pWge, *pWue, *pWgd, *pWud;
    cudaGetSymbolAddress((void**)&pSe, g_S_enc);
    cudaGetSymbolAddress((void**)&pSd, g_S_dec);
    cudaGetSymbolAddress((void**)&pDemb, g_demb);
    cudaGetSymbolAddress((void**)&pDembT, g_dembT);
    cudaGetSymbolAddress((void**)&pEp, g_embpad);
    cudaGetSymbolAddress((void**)&pEpT, g_embpadT);
    cudaGetSymbolAddress((void**)&pSeh, g_Se_hi);
    cudaGetSymbolAddress((void**)&pSdh, g_Sd_hi);
    cudaGetSymbolAddress((void**)&pX, g_XT);
    cudaGetSymbolAddress((void**)&pF, g_F);
    cudaGetSymbolAddress((void**)&pWge, g_Wge);
    cudaGetSymbolAddress((void**)&pWue, g_Wue);
    cudaGetSymbolAddress((void**)&pWgd, g_Wgd);
    cudaGetSymbolAddress((void**)&pWud, g_Wud);

    constexpr int SMEM_BN128 = 3 * (128 + 128) * 72 * 2;  // 110592
    constexpr int SMEM_BN64  = 3 * (128 + 64) * 72 * 2;   // 82944
    cudaFuncSetAttribute(mma_gemm<128,0,1>, cudaFuncAttributeMaxDynamicSharedMemorySize, SMEM_BN128);
    cudaFuncSetAttribute(mma_gemm<128,1,1>, cudaFuncAttributeMaxDynamicSharedMemorySize, SMEM_BN128);
    cudaFuncSetAttribute(mma_gemm<64,2,1>,  cudaFuncAttributeMaxDynamicSharedMemorySize, SMEM_BN64);

    // ---- setup; launch index 3 (0-based) == gate MLP GEMM for ncu
    k_zero_state<<<16384, 256>>>();                                                     // 0
    k_pad_w_t<true><<<(128 * FPK + 255) / 256, 256>>>(egw, pWge, 128);                  // 1
    k_pad_w_t<true><<<(64 * FPK + 255) / 256, 256>>>(euw, pWue, 64);                    // 2
    // ncu target: real-shape gate MLP. Safe as dummy: h==0 here, so all its
    // XT/F writes are zeros (already zero); g_R is overwritten by the real gate
    // before any consumer. Deterministic output regardless of stale F content.
    mma_gemm<128,1,1><<<dim3(1, 512), 256, SMEM_BN128>>>(pF, pF, pF, pWge, pWge, pWge,
                                                         FPK, FPK, 256, egb);           // 3
    k_pad_emb<<<64, 256>>>(emb);
    k_transpose<<<64, 256>>>(pEp, pEpT, Nn, 16);
    sgemm32<<<dim3(16, 8), 256>>>(pEp, pEpT, pSe, Nn, Nn, 16);
    k_relu_softmax<<<Nn, 256>>>(pSe);
    sgemm32<<<dim3(16, 8), 256>>>(pSe, pSe, pSe + NN2, Nn, Nn, Nn);
    k_cheb<<<NN2 / 256, 256>>>(pSe + NN2);
    k_tohalf<<<2 * NN2 / 256, 256>>>(pSe, pSeh, (size_t)2 * NN2);
    k_pad_w_t<false><<<(128 * FPK + 255) / 256, 256>>>(dgw, pWgd, 128);
    k_pad_w_t<false><<<(64 * FPK + 255) / 256, 256>>>(duw, pWud, 64);

    // ---- encoder (all operands single fp16; diffusion segK=1024, MLP segK=256)
    for (int t = 0; t < Tt; t++) {
        k_set_x_enc<<<256, 256>>>(x, t);
        mma_gemm<128,0,1><<<dim3(33, 16), 256, SMEM_BN128>>>(pSeh, pSeh, pSeh, pX, pX, pX,
                                                             Nn, Nn, 1024, nullptr);
        mma_gemm<128,1,1><<<dim3(1, 512), 256, SMEM_BN128>>>(pF, pF, pF, pWge, pWge, pWge,
                                                             FPK, FPK, 256, egb);
        mma_gemm<128,0,1><<<dim3(33, 16), 256, SMEM_BN128>>>(pSeh, pSeh, pSeh, pX, pX, pX,
                                                             Nn, Nn, 1024, nullptr);
        mma_gemm<64,2,1><<<dim3(1, 512), 256, SMEM_BN64>>>(pF, pF, pF, pWue, pWue, pWue,
                                                           FPK, FPK, 256, eub);
    }

    // ---- decoder supports
    k_demb<<<ROWS * Ee / 256, 256>>>(fce);
    k_transpose<<<ROWS * Ee / 256, 256>>>(pDemb, pDembT, Nn, Bb * Ee);
    sgemm32<<<dim3(16, 8), 256>>>(pDemb, pDembT, pSd, Nn, Nn, Bb * Ee);
    k_relu_softmax<<<Nn, 256>>>(pSd);
    sgemm32<<<dim3(16, 8), 256>>>(pSd, pSd, pSd + NN2, Nn, Nn, Nn);
    k_cheb<<<NN2 / 256, 256>>>(pSd + NN2);
    k_tohalf<<<2 * NN2 / 256, 256>>>(pSd, pSdh, (size_t)2 * NN2);
    k_init_go<<<256, 256>>>(x);

    // ---- decoder
    for (int t = 0; t < Hor; t++) {
        k_set_xy_dec<<<256, 256>>>(ycov, t);
        mma_gemm<128,0,1><<<dim3(33, 16), 256, SMEM_BN128>>>(pSdh, pSdh, pSdh, pX, pX, pX,
                                                             Nn, Nn, 1024, nullptr);
        mma_gemm<128,1,1><<<dim3(1, 512), 256, SMEM_BN128>>>(pF, pF, pF, pWgd, pWgd, pWgd,
                                                             FPK, FPK, 256, dgb);
        mma_gemm<128,0,1><<<dim3(33, 16), 256, SMEM_BN128>>>(pSdh, pSdh, pSdh, pX, pX, pX,
                                                             Nn, Nn, 1024, nullptr);
        mma_gemm<64,2,1><<<dim3(1, 512), 256, SMEM_BN64>>>(pF, pF, pF, pWud, pWud, pWud,
                                                           FPK, FPK, 256, dub);
        k_proj_out<<<256, 256>>>(pw, pb, out, t);
    }
}

// round 13
// speedup vs baseline: 5.3192x; 1.3191x over previous
#include <cuda_runtime.h>
#include <cuda_fp16.h>
#include <cstdint>
#include <math.h>

constexpr int Bb=64, Tt=12, Nn=1024, Ee=10, Hor=12;
constexpr int ROWS = Nn*Bb;          // 65536
constexpr int NN2  = Nn*Nn;
constexpr int FPK  = 256;            // padded K width of F (3*66=198 -> 256)
constexpr int XTC  = 66*Bb;          // 4224 = Xin^T row count (cols of Xin)
// ROW ORDER: id = b*1024 + n  (batch-major; coalesces XT/x/out accesses)

// ---------------- device-global scratch ----------------
__device__ __align__(1024) float g_S_enc[2*NN2];
__device__ __align__(1024) float g_S_dec[2*NN2];
__device__ __align__(1024) float g_R [(size_t)ROWS*64];
__device__ __align__(1024) float g_h [(size_t)ROWS*64];
__device__ __align__(1024) float g_go[ROWS];
__device__ __align__(1024) float g_demb [Nn*Bb*Ee];
__device__ __align__(1024) float g_dembT[Bb*Ee*Nn];
__device__ __align__(1024) float g_embpad [Nn*16];
__device__ __align__(1024) float g_embpadT[16*Nn];

__device__ __align__(1024) __half g_Se_hi[2*NN2];
__device__ __align__(1024) __half g_Sd_hi[2*NN2];
__device__ __align__(1024) __half g_XT[(size_t)XTC*Nn];          // [b*66+c][n]
__device__ __align__(1024) __half g_F[(size_t)ROWS*FPK];         // [b*1024+n][256]
__device__ __align__(1024) __half g_Wge[128*FPK];
__device__ __align__(1024) __half g_Wue[64*FPK];
__device__ __align__(1024) __half g_Wgd[128*FPK];
__device__ __align__(1024) __half g_Wud[64*FPK];

__device__ __forceinline__ float sigmoidf_(float x){ return 1.0f/(1.0f+expf(-x)); }

__device__ __forceinline__ uint32_t smem_u32(const void* p){
    uint32_t a;
    asm("{ .reg .u64 t; cvta.to.shared.u64 t, %1; cvt.u32.u64 %0, t; }" : "=r"(a) : "l"(p));
    return a;
}
__device__ __forceinline__ void cp_async16(uint32_t dst, const void* src){
    asm volatile("cp.async.cg.shared.global [%0], [%1], 16;" :: "r"(dst), "l"(src));
}
__device__ __forceinline__ void cp_commit(){ asm volatile("cp.async.commit_group;"); }
template <int N>
__device__ __forceinline__ void cp_wait(){ asm volatile("cp.async.wait_group %0;" :: "n"(N)); }

__device__ __forceinline__ void ldsm_x4(uint32_t* r, uint32_t addr){
    asm volatile("ldmatrix.sync.aligned.m8n8.x4.shared.b16 {%0,%1,%2,%3}, [%4];"
        : "=r"(r[0]), "=r"(r[1]), "=r"(r[2]), "=r"(r[3]) : "r"(addr));
}
__device__ __forceinline__ void mma16816(float* c, const uint32_t* a, const uint32_t* b){
    asm volatile("mma.sync.aligned.m16n8k16.row.col.f32.f16.f16.f32 "
        "{%0,%1,%2,%3}, {%4,%5,%6,%7}, {%8,%9}, {%0,%1,%2,%3};"
        : "+f"(c[0]), "+f"(c[1]), "+f"(c[2]), "+f"(c[3])
        : "r"(a[0]), "r"(a[1]), "r"(a[2]), "r"(a[3]), "r"(b[0]), "r"(b[1]));
}

// ---------------- fp16 HMMA GEMM (3-stage, 2 CTAs/SM) -----------------------
// D[M rows, N=BN per block] = sum over NSEG segments Aseg(M x segK) @ Bseg^T,
// fp32 accumulate. A rows = output rows (lda elems); B rows = output COLUMNS,
// K-major (ldb elems). BM=128, BK=64, 256 threads (8 warps, 4m x 2n).
// Row convention for EPI!=0: row index id = b*1024 + n.
// EPI 0: diffusion (row m = kk*1024+n; col = b*66+c) -> g_F[(b*1024+n)][...]
// EPI 1: gate: z=sig(+bias), c<64 -> z*h into g_XT + g_F; c>=64 -> g_R
// EPI 2: update: hc=tanh(+bias); hn = r*h + (1-r)*hc -> g_h, g_XT, g_F
template <int BN, int EPI, int NSEG>
__global__ void __launch_bounds__(256, 2) mma_gemm(
    const __half* __restrict__ A0, const __half* __restrict__ A1,
    const __half* __restrict__ A2,
    const __half* __restrict__ B0, const __half* __restrict__ B1,
    const __half* __restrict__ B2,
    int lda, int ldb, int segK, const float* __restrict__ bias)
{
    constexpr int BM = 128, LDS = 72;      // 64 + 8 pad (half elems)
    constexpr int NT = BN / 16;            // n8-tiles per warp (8 or 4)
    constexpr uint32_t STG_BYTES = (uint32_t)(BM + BN) * LDS * 2u;
    extern __shared__ __align__(16) char sm[];
    const uint32_t sm0 = smem_u32(sm);

    const int tid = threadIdx.x, lane = tid & 31, wid = tid >> 5;
    const int wm = wid >> 1, wn = wid & 1;
    const int m0 = blockIdx.y * BM, n0 = blockIdx.x * BN;

    const __half* Asg[3] = {A0, A1, A2};
    const __half* Bsg[3] = {B0, B1, B2};
    const int nt_seg = segK >> 6;
    const int KT = NSEG * nt_seg;

    float acc[2][NT][4];
#pragma unroll
    for (int i = 0; i < 2; i++)
#pragma unroll
        for (int j = 0; j < NT; j++)
#pragma unroll
            for (int e = 0; e < 4; e++) acc[i][j][e] = 0.0f;

    const uint32_t aOff = (((uint32_t)(wm*32 + (lane & 15))) * LDS + ((lane >> 4) << 3)) * 2u;
    const uint32_t bOff = (uint32_t)BM * LDS * 2u
        + (((uint32_t)(wn*(BN/2) + (lane & 7) + ((lane >> 4) << 3))) * LDS
           + (((lane >> 3) & 1) << 3)) * 2u;

    auto load_tile = [&](int kt, int stg) {
        const uint32_t sA = sm0 + (uint32_t)stg * STG_BYTES;
        const uint32_t sB = sA + (uint32_t)BM * LDS * 2u;
        int seg = kt / nt_seg;
        int j = kt - seg * nt_seg;
        const char* Ag = (const char*)(Asg[seg] + (size_t)m0 * lda + j * 64);
        const char* Bg = (const char*)(Bsg[seg] + (size_t)n0 * ldb + j * 64);
#pragma unroll
        for (int it = 0; it < 4; it++) {
            int id = (it << 8) + tid;
            int r = id >> 3, c = id & 7;
            cp_async16(sA + (uint32_t)r*144u + (uint32_t)c*16u,
                       Ag + (size_t)r * ((size_t)lda*2) + c*16);
        }
#pragma unroll
        for (int it = 0; it < BN/32; it++) {
            int id = (it << 8) + tid;
            int r = id >> 3, c = id & 7;
            cp_async16(sB + (uint32_t)r*144u + (uint32_t)c*16u,
                       Bg + (size_t)r * ((size_t)ldb*2) + c*16);
        }
        cp_commit();
    };

    load_tile(0, 0);
    if (KT > 1) load_tile(1, 1);

    int stg = 0;
    for (int kt = 0; kt < KT; kt++) {
        if (kt + 1 < KT) cp_wait<1>(); else cp_wait<0>();
        __syncthreads();
        if (kt + 2 < KT) load_tile(kt + 2, (kt + 2) % 3);

        const uint32_t sbase = sm0 + (uint32_t)stg * STG_BYTES;
        const uint32_t aBase = sbase + aOff;
        const uint32_t bBase = sbase + bOff;
#pragma unroll
        for (int ks = 0; ks < 4; ks++) {
            uint32_t a[2][4];
            ldsm_x4(a[0], aBase + (uint32_t)ks*32u);
            ldsm_x4(a[1], aBase + 16u*LDS*2u + (uint32_t)ks*32u);
            uint32_t b[NT/2][4];
#pragma unroll
            for (int p = 0; p < NT/2; p++)
                ldsm_x4(b[p], bBase + (uint32_t)p*16u*LDS*2u + (uint32_t)ks*32u);
#pragma unroll
            for (int mt = 0; mt < 2; mt++)
#pragma unroll
                for (int nt = 0; nt < NT; nt++)
                    mma16816(acc[mt][nt], a[mt], &b[nt >> 1][(nt & 1) * 2]);
        }
        if (++stg == 3) stg = 0;
    }

    // ---------------- epilogue (paired half2/float2; batch-major rows) -------
    const int rbase = m0 + wm*32 + (lane >> 2);
    const int cb = n0 + wn*(BN/2) + ((lane & 3) << 1);   // even
#pragma unroll
    for (int mt = 0; mt < 2; mt++) {
#pragma unroll
        for (int nt = 0; nt < NT; nt++) {
#pragma unroll
            for (int ep = 0; ep < 2; ep++) {
                const int row = rbase + mt*16 + ep*8;
                const int col0 = cb + nt*8;              // even; pair never straddles 66-block
                const float v0 = acc[mt][nt][ep*2 + 0];
                const float v1 = acc[mt][nt][ep*2 + 1];
                if (EPI == 0) {
                    const int kk = row >> 10, n = row & 1023;
                    const int b = col0 / 66, c = col0 - b * 66;
                    const size_t off = (size_t)((b << 10) + n) * FPK + (kk + 1) * 66 + c;
                    *reinterpret_cast<__half2*>(&g_F[off]) = __floats2half2_rn(v0, v1);
                } else if (EPI == 1) {
                    const int id = row, b = row >> 10, n = row & 1023;
                    if (col0 < 64) {                      // warp-uniform (wn==0)
                        const float2 hp = *reinterpret_cast<const float2*>(
                            &g_h[(size_t)id * 64 + col0]);
                        const float zh0 = sigmoidf_(v0 + bias[col0])     * hp.x;
                        const float zh1 = sigmoidf_(v1 + bias[col0 + 1]) * hp.y;
                        const __half h0 = __float2half_rn(zh0);
                        const __half h1 = __float2half_rn(zh1);
                        g_XT[((size_t)(b * 66 + 2 + col0) << 10) + n] = h0;
                        g_XT[((size_t)(b * 66 + 3 + col0) << 10) + n] = h1;
                        *reinterpret_cast<__half2*>(&g_F[((size_t)id << 8) + 2 + col0]) =
                            __halves2half2(h0, h1);
                    } else {                              // warp-uniform (wn==1)
                        float2 rv;
                        rv.x = sigmoidf_(v0 + bias[col0]);
                        rv.y = sigmoidf_(v1 + bias[col0 + 1]);
                        *reinterpret_cast<float2*>(&g_R[(size_t)id * 64 + (col0 - 64)]) = rv;
                    }
                } else {
                    const int id = row, b = row >> 10, n = row & 1023;
                    const size_t o = (size_t)id * 64 + col0;
                    const float2 rp = *reinterpret_cast<const float2*>(&g_R[o]);
                    const float2 hp = *reinterpret_cast<const float2*>(&g_h[o]);
                    const float hc0 = tanhf(v0 + bias[col0]);
                    const float hc1 = tanhf(v1 + bias[col0 + 1]);
                    const float hn0 = rp.x * hp.x + (1.0f - rp.x) * hc0;
                    const float hn1 = rp.y * hp.y + (1.0f - rp.y) * hc1;
                    *reinterpret_cast<float2*>(&g_h[o]) = make_float2(hn0, hn1);
                    const __half h0 = __float2half_rn(hn0);
                    const __half h1 = __float2half_rn(hn1);
                    g_XT[((size_t)(b * 66 + 2 + col0) << 10) + n] = h0;
                    g_XT[((size_t)(b * 66 + 3 + col0) << 10) + n] = h1;
                    *reinterpret_cast<__half2*>(&g_F[((size_t)id << 8) + 2 + col0]) =
                        __halves2half2(h0, h1);
                }
            }
        }
    }
}

// ---------------- fp32 SGEMM (setup only) ----------------
__global__ void __launch_bounds__(256) sgemm32(
    const float* __restrict__ A, const float* __restrict__ B,
    float* __restrict__ C, int M, int N, int K)
{
    constexpr int BM = 128, BN = 64, BK = 16;
    __shared__ __align__(16) float As_[BK][BM];
    __shared__ __align__(16) float Bs_[BK][BN];
    const int tid = threadIdx.x;
    const int tx = tid & 15, ty = tid >> 4;
    const int m0 = blockIdx.y * BM, n0 = blockIdx.x * BN;
    float acc[8][4];
#pragma unroll
    for (int i = 0; i < 8; i++)
#pragma unroll
        for (int jj = 0; jj < 4; jj++) acc[i][jj] = 0.0f;
    const int arow0 = tid >> 2, acol0 = (tid & 3) * 4;
    const int brow = tid >> 4, bcol = (tid & 15) * 4;
    for (int kt = 0; kt < K; kt += BK) {
#pragma unroll
        for (int i = 0; i < 2; i++) {
            int r = arow0 + i * 64;
            float4 v = *reinterpret_cast<const float4*>(A + (size_t)(m0 + r) * K + kt + acol0);
            As_[acol0+0][r]=v.x; As_[acol0+1][r]=v.y; As_[acol0+2][r]=v.z; As_[acol0+3][r]=v.w;
        }
        float4 bv = *reinterpret_cast<const float4*>(B + (size_t)(kt + brow) * N + n0 + bcol);
        *reinterpret_cast<float4*>(&Bs_[brow][bcol]) = bv;
        __syncthreads();
#pragma unroll
        for (int k = 0; k < BK; k++) {
            float4 a0 = *reinterpret_cast<const float4*>(&As_[k][ty*8]);
            float4 a1 = *reinterpret_cast<const float4*>(&As_[k][ty*8+4]);
            float4 b0 = *reinterpret_cast<const float4*>(&Bs_[k][tx*4]);
            float am[8]={a0.x,a0.y,a0.z,a0.w,a1.x,a1.y,a1.z,a1.w};
            float bn[4]={b0.x,b0.y,b0.z,b0.w};
#pragma unroll
            for (int i = 0; i < 8; i++)
#pragma unroll
                for (int jj = 0; jj < 4; jj++) acc[i][jj] = fmaf(am[i], bn[jj], acc[i][jj]);
        }
        __syncthreads();
    }
#pragma unroll
    for (int i = 0; i < 8; i++) {
        float4 v = make_float4(acc[i][0], acc[i][1], acc[i][2], acc[i][3]);
        *reinterpret_cast<float4*>(C + (size_t)(m0 + ty*8 + i) * N + n0 + tx*4) = v;
    }
}

// ---------------- elementwise helpers (id = b*1024 + n) ----------------
__global__ void k_zero_state() {
    int idx = blockIdx.x * blockDim.x + threadIdx.x;
    if (idx >= ROWS * 64) return;
    int id = idx >> 6, i = idx & 63;
    int b = id >> 10, n = id & 1023;
    g_h[idx] = 0.0f;
    g_XT[((size_t)(b * 66 + 2 + i) << 10) + n] = __float2half_rn(0.0f);
    g_F[((size_t)id << 8) + 2 + i] = __float2half_rn(0.0f);
}
__global__ void k_tohalf(const float* __restrict__ s, __half* __restrict__ hi, size_t n) {
    size_t i = (size_t)blockIdx.x * blockDim.x + threadIdx.x;
    if (i >= n) return;
    hi[i] = __float2half_rn(s[i]);
}
__global__ void k_pad_emb(const float* __restrict__ emb) {
    int idx = blockIdx.x * blockDim.x + threadIdx.x;
    if (idx >= Nn * 16) return;
    int n = idx >> 4, j = idx & 15;
    g_embpad[idx] = (j < Ee) ? emb[n * Ee + j] : 0.0f;
}
__global__ void k_transpose(const float* __restrict__ in, float* __restrict__ out,
                            int R, int C) {
    int idx = blockIdx.x * blockDim.x + threadIdx.x;
    if (idx >= R * C) return;
    int r = idx / C, c = idx - r * C;
    out[c * R + r] = in[idx];
}
template <bool ENC>
__global__ void k_pad_w_t(const float* __restrict__ src, __half* __restrict__ dst,
                          int nout) {
    int idx = blockIdx.x * blockDim.x + threadIdx.x;
    if (idx >= nout * FPK) return;
    int n = idx >> 8, f = idx & 255;
    float v = 0.0f;
    if (f < 198) {
        int k = f / 66, c = f - k * 66;
        if (ENC) {
            if (c == 0) v = src[(k * 65) * nout + n];
            else if (c >= 2) v = src[(k * 65 + c - 1) * nout + n];
        } else {
            v = src[f * nout + n];
        }
    }
    dst[idx] = __float2half_rn(v);
}
__global__ void k_relu_softmax(float* __restrict__ S) {
    int row = blockIdx.x;
    float* p = S + (size_t)row * Nn;
    int t = threadIdx.x;
    float v[4];
#pragma unroll
    for (int i = 0; i < 4; i++) { float x = p[t + i*256]; v[i] = x > 0.0f ? x : 0.0f; }
    __shared__ float red[256];
    float m = fmaxf(fmaxf(v[0], v[1]), fmaxf(v[2], v[3]));
    red[t] = m; __syncthreads();
    for (int s = 128; s > 0; s >>= 1) { if (t < s) red[t] = fmaxf(red[t], red[t+s]); __syncthreads(); }
    m = red[0]; __syncthreads();
    float e[4], sum = 0.0f;
#pragma unroll
    for (int i = 0; i < 4; i++) { e[i] = expf(v[i] - m); sum += e[i]; }
    red[t] = sum; __syncthreads();
    for (int s = 128; s > 0; s >>= 1) { if (t < s) red[t] += red[t+s]; __syncthreads(); }
    float inv = 1.0f / red[0];
#pragma unroll
    for (int i = 0; i < 4; i++) p[t + i*256] = e[i] * inv;
}
__global__ void k_cheb(float* __restrict__ P) {
    int idx = blockIdx.x * blockDim.x + threadIdx.x;
    if (idx >= NN2) return;
    int r = idx >> 10, c = idx & 1023;
    P[idx] = 2.0f * P[idx] - (r == c ? 1.0f : 0.0f);
}
__global__ void k_set_x_enc(const float* __restrict__ x, int t) {
    int id = blockIdx.x * blockDim.x + threadIdx.x;
    if (id >= ROWS) return;
    int b = id >> 10, n = id & 1023;
    float xv = x[((size_t)b * Tt + t) * Nn + n];
    __half xh = __float2half_rn(xv);
    g_XT[((size_t)(b * 66) << 10) + n] = xh;
    g_F[(size_t)id << 8] = xh;
}
__global__ void k_set_xy_dec(const float* __restrict__ ycov, int t) {
    int id = blockIdx.x * blockDim.x + threadIdx.x;
    if (id >= ROWS) return;
    int b = id >> 10, n = id & 1023;
    float gv = g_go[id];
    float yv = ycov[((size_t)b * Hor + t) * Nn + n];
    __half gh = __float2half_rn(gv);
    __half yh = __float2half_rn(yv);
    g_XT[((size_t)(b * 66) << 10) + n] = gh;
    g_XT[((size_t)(b * 66 + 1) << 10) + n] = yh;
    size_t fo = (size_t)id << 8;
    g_F[fo] = gh;
    g_F[fo + 1] = yh;
}
// dec_emb must be [n, b*Ee+e] for the gram; decode id accordingly
__global__ void k_demb(const float* __restrict__ fce) {
    int idx = blockIdx.x * blockDim.x + threadIdx.x;
    if (idx >= ROWS * Ee) return;
    int id = idx / Ee, e = idx - id * Ee;
    int b = id >> 10, n = id & 1023;
    const float* hr = g_h + (size_t)id * 64;
    float s = 0.0f;
#pragma unroll
    for (int h = 0; h < 64; h++) s = fmaf(hr[h], fce[h * Ee + e], s);
    g_demb[(size_t)n * (Bb * Ee) + b * Ee + e] = s;
}
__global__ void k_init_go(const float* __restrict__ x) {
    int id = blockIdx.x * blockDim.x + threadIdx.x;
    if (id >= ROWS) return;
    int b = id >> 10, n = id & 1023;
    g_go[id] = x[((size_t)b * Tt + (Tt - 1)) * Nn + n];
}
__global__ void k_proj_out(const float* __restrict__ pw, const float* __restrict__ pb,
                           float* __restrict__ out, int t) {
    int id = blockIdx.x * blockDim.x + threadIdx.x;
    if (id >= ROWS) return;
    int b = id >> 10, n = id & 1023;
    const float* hr = g_h + (size_t)id * 64;
    float s = pb[0];
#pragma unroll
    for (int i = 0; i < 64; i++) s = fmaf(hr[i], pw[i], s);
    g_go[id] = s;
    out[((size_t)b * Hor + t) * Nn + n] = s;
}

// ---------------- orchestration ----------------
extern "C" void kernel_launch(void* const* d_in, const int* in_sizes, int n_in,
                              void* d_out, int out_size) {
    const float* x    = (const float*)d_in[0];
    const float* ycov = (const float*)d_in[1];
    const float* emb  = (const float*)d_in[2];
    const float* fce  = (const float*)d_in[3];
    const float* egw  = (const float*)d_in[4];
    const float* egb  = (const float*)d_in[5];
    const float* euw  = (const float*)d_in[6];
    const float* eub  = (const float*)d_in[7];
    const float* dgw  = (const float*)d_in[8];
    const float* dgb  = (const float*)d_in[9];
    const float* duw  = (const float*)d_in[10];
    const float* dub  = (const float*)d_in[11];
    const float* pw   = (const float*)d_in[12];
    const float* pb   = (const float*)d_in[13];
    float* out = (float*)d_out;

    float *pSe, *pSd, *pDemb, *pDembT, *pEp, *pEpT;
    __half *pSeh, *pSdh, *pX, *pF, *pWge, *pWue, *pWgd, *pWud;
    cudaGetSymbolAddress((void**)&pSe, g_S_enc);
    cudaGetSymbolAddress((void**)&pSd, g_S_dec);
    cudaGetSymbolAddress((void**)&pDemb, g_demb);
    cudaGetSymbolAddress((void**)&pDembT, g_dembT);
    cudaGetSymbolAddress((void**)&pEp, g_embpad);
    cudaGetSymbolAddress((void**)&pEpT, g_embpadT);
    cudaGetSymbolAddress((void**)&pSeh, g_Se_hi);
    cudaGetSymbolAddress((void**)&pSdh, g_Sd_hi);
    cudaGetSymbolAddress((void**)&pX, g_XT);
    cudaGetSymbolAddress((void**)&pF, g_F);
    cudaGetSymbolAddress((void**)&pWge, g_Wge);
    cudaGetSymbolAddress((void**)&pWue, g_Wue);
    cudaGetSymbolAddress((void**)&pWgd, g_Wgd);
    cudaGetSymbolAddress((void**)&pWud, g_Wud);

    constexpr int SMEM_BN128 = 3 * (128 + 128) * 72 * 2;  // 110592
    constexpr int SMEM_BN64  = 3 * (128 + 64) * 72 * 2;   // 82944
    cudaFuncSetAttribute(mma_gemm<128,0,1>, cudaFuncAttributeMaxDynamicSharedMemorySize, SMEM_BN128);
    cudaFuncSetAttribute(mma_gemm<128,1,1>, cudaFuncAttributeMaxDynamicSharedMemorySize, SMEM_BN128);
    cudaFuncSetAttribute(mma_gemm<64,2,1>,  cudaFuncAttributeMaxDynamicSharedMemorySize, SMEM_BN64);

    // ---- setup; launch index 3 (0-based) == gate MLP GEMM for ncu
    k_zero_state<<<16384, 256>>>();                                                     // 0
    k_pad_w_t<true><<<(128 * FPK + 255) / 256, 256>>>(egw, pWge, 128);                  // 1
    k_pad_w_t<true><<<(64 * FPK + 255) / 256, 256>>>(euw, pWue, 64);                    // 2
    // ncu target: real-shape gate MLP (h==0 here; writes zeros / overwritten R)
    mma_gemm<128,1,1><<<dim3(1, 512), 256, SMEM_BN128>>>(pF, pF, pF, pWge, pWge, pWge,
                                                         FPK, FPK, 256, egb);           // 3
    k_pad_emb<<<64, 256>>>(emb);
    k_transpose<<<64, 256>>>(pEp, pEpT, Nn, 16);
    sgemm32<<<dim3(16, 8), 256>>>(pEp, pEpT, pSe, Nn, Nn, 16);
    k_relu_softmax<<<Nn, 256>>>(pSe);
    sgemm32<<<dim3(16, 8), 256>>>(pSe, pSe, pSe + NN2, Nn, Nn, Nn);
    k_cheb<<<NN2 / 256, 256>>>(pSe + NN2);
    k_tohalf<<<2 * NN2 / 256, 256>>>(pSe, pSeh, (size_t)2 * NN2);
    k_pad_w_t<false><<<(128 * FPK + 255) / 256, 256>>>(dgw, pWgd, 128);
    k_pad_w_t<false><<<(64 * FPK + 255) / 256, 256>>>(duw, pWud, 64);

    // ---- encoder (all operands single fp16; diffusion segK=1024, MLP segK=256)
    for (int t = 0; t < Tt; t++) {
        k_set_x_enc<<<256, 256>>>(x, t);
        mma_gemm<128,0,1><<<dim3(33, 16), 256, SMEM_BN128>>>(pSeh, pSeh, pSeh, pX, pX, pX,
                                                             Nn, Nn, 1024, nullptr);
        mma_gemm<128,1,1><<<dim3(1, 512), 256, SMEM_BN128>>>(pF, pF, pF, pWge, pWge, pWge,
                                                             FPK, FPK, 256, egb);
        mma_gemm<128,0,1><<<dim3(33, 16), 256, SMEM_BN128>>>(pSeh, pSeh, pSeh, pX, pX, pX,
                                                             Nn, Nn, 1024, nullptr);
        mma_gemm<64,2,1><<<dim3(1, 512), 256, SMEM_BN64>>>(pF, pF, pF, pWue, pWue, pWue,
                                                           FPK, FPK, 256, eub);
    }

    // ---- decoder supports
    k_demb<<<ROWS * Ee / 256, 256>>>(fce);
    k_transpose<<<(ROWS * Ee + 255) / 256, 256>>>(pDemb, pDembT, Nn, Bb * Ee);
    sgemm32<<<dim3(16, 8), 256>>>(pDemb, pDembT, pSd, Nn, Nn, Bb * Ee);
    k_relu_softmax<<<Nn, 256>>>(pSd);
    sgemm32<<<dim3(16, 8), 256>>>(pSd, pSd, pSd + NN2, Nn, Nn, Nn);
    k_cheb<<<NN2 / 256, 256>>>(pSd + NN2);
    k_tohalf<<<2 * NN2 / 256, 256>>>(pSd, pSdh, (size_t)2 * NN2);
    k_init_go<<<256, 256>>>(x);

    // ---- decoder
    for (int t = 0; t < Hor; t++) {
        k_set_xy_dec<<<256, 256>>>(ycov, t);
        mma_gemm<128,0,1><<<dim3(33, 16), 256, SMEM_BN128>>>(pSdh, pSdh, pSdh, pX, pX, pX,
                                                             Nn, Nn, 1024, nullptr);
        mma_gemm<128,1,1><<<dim3(1, 512), 256, SMEM_BN128>>>(pF, pF, pF, pWgd, pWgd, pWgd,
                                                             FPK, FPK, 256, dgb);
        mma_gemm<128,0,1><<<dim3(33, 16), 256, SMEM_BN128>>>(pSdh, pSdh, pSdh, pX, pX, pX,
                                                             Nn, Nn, 1024, nullptr);
        mma_gemm<64,2,1><<<dim3(1, 512), 256, SMEM_BN64>>>(pF, pF, pF, pWud, pWud, pWud,
                                                           FPK, FPK, 256, dub);
        k_proj_out<<<256, 256>>>(pw, pb, out, t);
    }
}

// round 14
// speedup vs baseline: 5.4556x; 1.0256x over previous
#include <cuda_runtime.h>
#include <cuda_fp16.h>
#include <cstdint>
#include <math.h>

constexpr int Bb=64, Tt=12, Nn=1024, Ee=10, Hor=12;
constexpr int ROWS = Nn*Bb;          // 65536
constexpr int NN2  = Nn*Nn;
constexpr int FPK  = 256;            // padded K width of F (3*66=198 -> 256)
constexpr int XTC  = 66*Bb;          // 4224 = Xin^T row count (cols of Xin)
// ROW ORDER: id = b*1024 + n  (batch-major; coalesces XT/x/out accesses)

// ---------------- device-global scratch ----------------
__device__ __align__(1024) float g_S_enc[2*NN2];
__device__ __align__(1024) float g_S_dec[2*NN2];
__device__ __align__(1024) float g_R [(size_t)ROWS*64];
__device__ __align__(1024) float g_h [(size_t)ROWS*64];
__device__ __align__(1024) float g_go[ROWS];
__device__ __align__(1024) float g_demb [Nn*Bb*Ee];
__device__ __align__(1024) float g_dembT[Bb*Ee*Nn];
__device__ __align__(1024) float g_embpad [Nn*16];
__device__ __align__(1024) float g_embpadT[16*Nn];

__device__ __align__(1024) __half g_Se_hi[2*NN2];
__device__ __align__(1024) __half g_Sd_hi[2*NN2];
__device__ __align__(1024) __half g_XT[(size_t)XTC*Nn];          // [b*66+c][n]
__device__ __align__(1024) __half g_F[(size_t)ROWS*FPK];         // [b*1024+n][256]
__device__ __align__(1024) __half g_Wge[128*FPK];
__device__ __align__(1024) __half g_Wue[64*FPK];
__device__ __align__(1024) __half g_Wgd[128*FPK];
__device__ __align__(1024) __half g_Wud[64*FPK];

__device__ __forceinline__ float sigmoidf_(float x){ return 1.0f/(1.0f+expf(-x)); }
// HW MUFU.TANH (sm_75+): max rel err ~2^-11, same order as fp16 state rounding
__device__ __forceinline__ float tanh_fast(float x){
    float y; asm("tanh.approx.f32 %0, %1;" : "=f"(y) : "f"(x)); return y;
}
__device__ __forceinline__ float sigmoid_fast(float x){
    return fmaf(0.5f, tanh_fast(0.5f * x), 0.5f);
}

__device__ __forceinline__ uint32_t smem_u32(const void* p){
    uint32_t a;
    asm("{ .reg .u64 t; cvta.to.shared.u64 t, %1; cvt.u32.u64 %0, t; }" : "=r"(a) : "l"(p));
    return a;
}
__device__ __forceinline__ void cp_async16(uint32_t dst, const void* src){
    asm volatile("cp.async.cg.shared.global [%0], [%1], 16;" :: "r"(dst), "l"(src));
}
__device__ __forceinline__ void cp_commit(){ asm volatile("cp.async.commit_group;"); }
template <int N>
__device__ __forceinline__ void cp_wait(){ asm volatile("cp.async.wait_group %0;" :: "n"(N)); }

__device__ __forceinline__ void ldsm_x4(uint32_t* r, uint32_t addr){
    asm volatile("ldmatrix.sync.aligned.m8n8.x4.shared.b16 {%0,%1,%2,%3}, [%4];"
        : "=r"(r[0]), "=r"(r[1]), "=r"(r[2]), "=r"(r[3]) : "r"(addr));
}
__device__ __forceinline__ void mma16816(float* c, const uint32_t* a, const uint32_t* b){
    asm volatile("mma.sync.aligned.m16n8k16.row.col.f32.f16.f16.f32 "
        "{%0,%1,%2,%3}, {%4,%5,%6,%7}, {%8,%9}, {%0,%1,%2,%3};"
        : "+f"(c[0]), "+f"(c[1]), "+f"(c[2]), "+f"(c[3])
        : "r"(a[0]), "r"(a[1]), "r"(a[2]), "r"(a[3]), "r"(b[0]), "r"(b[1]));
}

// ---------------- fp16 HMMA GEMM (3-stage, 2 CTAs/SM) -----------------------
// D[M rows, N=BN per block] = sum over NSEG segments Aseg(M x segK) @ Bseg^T,
// fp32 accumulate. A rows = output rows (lda elems); B rows = output COLUMNS,
// K-major (ldb elems). BM=128, BK=64, 256 threads (8 warps, 4m x 2n).
// Row convention for EPI!=0: row index id = b*1024 + n.
// EPI 0: diffusion (row m = kk*1024+n; col = b*66+c) -> g_F[(b*1024+n)][...]
// EPI 1: gate: z=sig(+bias), c<64 -> z*h into g_XT + g_F; c>=64 -> g_R
// EPI 2: update: hc=tanh(+bias); hn = r*h + (1-r)*hc -> g_h, g_XT, g_F
template <int BN, int EPI, int NSEG>
__global__ void __launch_bounds__(256, 2) mma_gemm(
    const __half* __restrict__ A0, const __half* __restrict__ A1,
    const __half* __restrict__ A2,
    const __half* __restrict__ B0, const __half* __restrict__ B1,
    const __half* __restrict__ B2,
    int lda, int ldb, int segK, const float* __restrict__ bias)
{
    constexpr int BM = 128, LDS = 72;      // 64 + 8 pad (half elems)
    constexpr int NT = BN / 16;            // n8-tiles per warp (8 or 4)
    constexpr uint32_t STG_BYTES = (uint32_t)(BM + BN) * LDS * 2u;
    extern __shared__ __align__(16) char sm[];
    const uint32_t sm0 = smem_u32(sm);

    const int tid = threadIdx.x, lane = tid & 31, wid = tid >> 5;
    const int wm = wid >> 1, wn = wid & 1;
    const int m0 = blockIdx.y * BM, n0 = blockIdx.x * BN;

    const __half* Asg[3] = {A0, A1, A2};
    const __half* Bsg[3] = {B0, B1, B2};
    const int nt_seg = segK >> 6;
    const int KT = NSEG * nt_seg;

    float acc[2][NT][4];
#pragma unroll
    for (int i = 0; i < 2; i++)
#pragma unroll
        for (int j = 0; j < NT; j++)
#pragma unroll
            for (int e = 0; e < 4; e++) acc[i][j][e] = 0.0f;

    const uint32_t aOff = (((uint32_t)(wm*32 + (lane & 15))) * LDS + ((lane >> 4) << 3)) * 2u;
    const uint32_t bOff = (uint32_t)BM * LDS * 2u
        + (((uint32_t)(wn*(BN/2) + (lane & 7) + ((lane >> 4) << 3))) * LDS
           + (((lane >> 3) & 1) << 3)) * 2u;

    auto load_tile = [&](int kt, int stg) {
        const uint32_t sA = sm0 + (uint32_t)stg * STG_BYTES;
        const uint32_t sB = sA + (uint32_t)BM * LDS * 2u;
        int seg = kt / nt_seg;
        int j = kt - seg * nt_seg;
        const char* Ag = (const char*)(Asg[seg] + (size_t)m0 * lda + j * 64);
        const char* Bg = (const char*)(Bsg[seg] + (size_t)n0 * ldb + j * 64);
#pragma unroll
        for (int it = 0; it < 4; it++) {
            int id = (it << 8) + tid;
            int r = id >> 3, c = id & 7;
            cp_async16(sA + (uint32_t)r*144u + (uint32_t)c*16u,
                       Ag + (size_t)r * ((size_t)lda*2) + c*16);
        }
#pragma unroll
        for (int it = 0; it < BN/32; it++) {
            int id = (it << 8) + tid;
            int r = id >> 3, c = id & 7;
            cp_async16(sB + (uint32_t)r*144u + (uint32_t)c*16u,
                       Bg + (size_t)r * ((size_t)ldb*2) + c*16);
        }
        cp_commit();
    };

    load_tile(0, 0);
    if (KT > 1) load_tile(1, 1);

    int stg = 0;
    for (int kt = 0; kt < KT; kt++) {
        if (kt + 1 < KT) cp_wait<1>(); else cp_wait<0>();
        __syncthreads();
        if (kt + 2 < KT) load_tile(kt + 2, (kt + 2) % 3);

        const uint32_t sbase = sm0 + (uint32_t)stg * STG_BYTES;
        const uint32_t aBase = sbase + aOff;
        const uint32_t bBase = sbase + bOff;
#pragma unroll
        for (int ks = 0; ks < 4; ks++) {
            uint32_t a[2][4];
            ldsm_x4(a[0], aBase + (uint32_t)ks*32u);
            ldsm_x4(a[1], aBase + 16u*LDS*2u + (uint32_t)ks*32u);
            uint32_t b[NT/2][4];
#pragma unroll
            for (int p = 0; p < NT/2; p++)
                ldsm_x4(b[p], bBase + (uint32_t)p*16u*LDS*2u + (uint32_t)ks*32u);
#pragma unroll
            for (int mt = 0; mt < 2; mt++)
#pragma unroll
                for (int nt = 0; nt < NT; nt++)
                    mma16816(acc[mt][nt], a[mt], &b[nt >> 1][(nt & 1) * 2]);
        }
        if (++stg == 3) stg = 0;
    }

    // ---------------- epilogue (paired half2/float2; batch-major rows) -------
    const int rbase = m0 + wm*32 + (lane >> 2);
    const int cb = n0 + wn*(BN/2) + ((lane & 3) << 1);   // even
#pragma unroll
    for (int mt = 0; mt < 2; mt++) {
#pragma unroll
        for (int nt = 0; nt < NT; nt++) {
#pragma unroll
            for (int ep = 0; ep < 2; ep++) {
                const int row = rbase + mt*16 + ep*8;
                const int col0 = cb + nt*8;              // even; pair never straddles 66-block
                const float v0 = acc[mt][nt][ep*2 + 0];
                const float v1 = acc[mt][nt][ep*2 + 1];
                if (EPI == 0) {
                    const int kk = row >> 10, n = row & 1023;
                    const int b = col0 / 66, c = col0 - b * 66;
                    const size_t off = (size_t)((b << 10) + n) * FPK + (kk + 1) * 66 + c;
                    *reinterpret_cast<__half2*>(&g_F[off]) = __floats2half2_rn(v0, v1);
                } else if (EPI == 1) {
                    const int id = row, b = row >> 10, n = row & 1023;
                    if (col0 < 64) {                      // warp-uniform (wn==0)
                        const float2 hp = *reinterpret_cast<const float2*>(
                            &g_h[(size_t)id * 64 + col0]);
                        const float zh0 = sigmoid_fast(v0 + bias[col0])     * hp.x;
                        const float zh1 = sigmoid_fast(v1 + bias[col0 + 1]) * hp.y;
                        const __half h0 = __float2half_rn(zh0);
                        const __half h1 = __float2half_rn(zh1);
                        g_XT[((size_t)(b * 66 + 2 + col0) << 10) + n] = h0;
                        g_XT[((size_t)(b * 66 + 3 + col0) << 10) + n] = h1;
                        *reinterpret_cast<__half2*>(&g_F[((size_t)id << 8) + 2 + col0]) =
                            __halves2half2(h0, h1);
                    } else {                              // warp-uniform (wn==1)
                        float2 rv;
                        rv.x = sigmoid_fast(v0 + bias[col0]);
                        rv.y = sigmoid_fast(v1 + bias[col0 + 1]);
                        *reinterpret_cast<float2*>(&g_R[(size_t)id * 64 + (col0 - 64)]) = rv;
                    }
                } else {
                    const int id = row, b = row >> 10, n = row & 1023;
                    const size_t o = (size_t)id * 64 + col0;
                    const float2 rp = *reinterpret_cast<const float2*>(&g_R[o]);
                    const float2 hp = *reinterpret_cast<const float2*>(&g_h[o]);
                    const float hc0 = tanh_fast(v0 + bias[col0]);
                    const float hc1 = tanh_fast(v1 + bias[col0 + 1]);
                    const float hn0 = rp.x * hp.x + (1.0f - rp.x) * hc0;
                    const float hn1 = rp.y * hp.y + (1.0f - rp.y) * hc1;
                    *reinterpret_cast<float2*>(&g_h[o]) = make_float2(hn0, hn1);
                    const __half h0 = __float2half_rn(hn0);
                    const __half h1 = __float2half_rn(hn1);
                    g_XT[((size_t)(b * 66 + 2 + col0) << 10) + n] = h0;
                    g_XT[((size_t)(b * 66 + 3 + col0) << 10) + n] = h1;
                    *reinterpret_cast<__half2*>(&g_F[((size_t)id << 8) + 2 + col0]) =
                        __halves2half2(h0, h1);
                }
            }
        }
    }
}

// ---------------- fp32 SGEMM (setup only) ----------------
__global__ void __launch_bounds__(256) sgemm32(
    const float* __restrict__ A, const float* __restrict__ B,
    float* __restrict__ C, int M, int N, int K)
{
    constexpr int BM = 128, BN = 64, BK = 16;
    __shared__ __align__(16) float As_[BK][BM];
    __shared__ __align__(16) float Bs_[BK][BN];
    const int tid = threadIdx.x;
    const int tx = tid & 15, ty = tid >> 4;
    const int m0 = blockIdx.y * BM, n0 = blockIdx.x * BN;
    float acc[8][4];
#pragma unroll
    for (int i = 0; i < 8; i++)
#pragma unroll
        for (int jj = 0; jj < 4; jj++) acc[i][jj] = 0.0f;
    const int arow0 = tid >> 2, acol0 = (tid & 3) * 4;
    const int brow = tid >> 4, bcol = (tid & 15) * 4;
    for (int kt = 0; kt < K; kt += BK) {
#pragma unroll
        for (int i = 0; i < 2; i++) {
            int r = arow0 + i * 64;
            float4 v = *reinterpret_cast<const float4*>(A + (size_t)(m0 + r) * K + kt + acol0);
            As_[acol0+0][r]=v.x; As_[acol0+1][r]=v.y; As_[acol0+2][r]=v.z; As_[acol0+3][r]=v.w;
        }
        float4 bv = *reinterpret_cast<const float4*>(B + (size_t)(kt + brow) * N + n0 + bcol);
        *reinterpret_cast<float4*>(&Bs_[brow][bcol]) = bv;
        __syncthreads();
#pragma unroll
        for (int k = 0; k < BK; k++) {
            float4 a0 = *reinterpret_cast<const float4*>(&As_[k][ty*8]);
            float4 a1 = *reinterpret_cast<const float4*>(&As_[k][ty*8+4]);
            float4 b0 = *reinterpret_cast<const float4*>(&Bs_[k][tx*4]);
            float am[8]={a0.x,a0.y,a0.z,a0.w,a1.x,a1.y,a1.z,a1.w};
            float bn[4]={b0.x,b0.y,b0.z,b0.w};
#pragma unroll
            for (int i = 0; i < 8; i++)
#pragma unroll
                for (int jj = 0; jj < 4; jj++) acc[i][jj] = fmaf(am[i], bn[jj], acc[i][jj]);
        }
        __syncthreads();
    }
#pragma unroll
    for (int i = 0; i < 8; i++) {
        float4 v = make_float4(acc[i][0], acc[i][1], acc[i][2], acc[i][3]);
        *reinterpret_cast<float4*>(C + (size_t)(m0 + ty*8 + i) * N + n0 + tx*4) = v;
    }
}

// ---------------- elementwise helpers (id = b*1024 + n) ----------------
__global__ void k_zero_state() {
    int idx = blockIdx.x * blockDim.x + threadIdx.x;
    if (idx >= ROWS * 64) return;
    int id = idx >> 6, i = idx & 63;
    int b = id >> 10, n = id & 1023;
    g_h[idx] = 0.0f;
    g_XT[((size_t)(b * 66 + 2 + i) << 10) + n] = __float2half_rn(0.0f);
    g_F[((size_t)id << 8) + 2 + i] = __float2half_rn(0.0f);
}
__global__ void k_tohalf(const float* __restrict__ s, __half* __restrict__ hi, size_t n) {
    size_t i = (size_t)blockIdx.x * blockDim.x + threadIdx.x;
    if (i >= n) return;
    hi[i] = __float2half_rn(s[i]);
}
__global__ void k_pad_emb(const float* __restrict__ emb) {
    int idx = blockIdx.x * blockDim.x + threadIdx.x;
    if (idx >= Nn * 16) return;
    int n = idx >> 4, j = idx & 15;
    g_embpad[idx] = (j < Ee) ? emb[n * Ee + j] : 0.0f;
}
__global__ void k_transpose(const float* __restrict__ in, float* __restrict__ out,
                            int R, int C) {
    int idx = blockIdx.x * blockDim.x + threadIdx.x;
    if (idx >= R * C) return;
    int r = idx / C, c = idx - r * C;
    out[c * R + r] = in[idx];
}
template <bool ENC>
__global__ void k_pad_w_t(const float* __restrict__ src, __half* __restrict__ dst,
                          int nout) {
    int idx = blockIdx.x * blockDim.x + threadIdx.x;
    if (idx >= nout * FPK) return;
    int n = idx >> 8, f = idx & 255;
    float v = 0.0f;
    if (f < 198) {
        int k = f / 66, c = f - k * 66;
        if (ENC) {
            if (c == 0) v = src[(k * 65) * nout + n];
            else if (c >= 2) v = src[(k * 65 + c - 1) * nout + n];
        } else {
            v = src[f * nout + n];
        }
    }
    dst[idx] = __float2half_rn(v);
}
__global__ void k_relu_softmax(float* __restrict__ S) {
    int row = blockIdx.x;
    float* p = S + (size_t)row * Nn;
    int t = threadIdx.x;
    float v[4];
#pragma unroll
    for (int i = 0; i < 4; i++) { float x = p[t + i*256]; v[i] = x > 0.0f ? x : 0.0f; }
    __shared__ float red[256];
    float m = fmaxf(fmaxf(v[0], v[1]), fmaxf(v[2], v[3]));
    red[t] = m; __syncthreads();
    for (int s = 128; s > 0; s >>= 1) { if (t < s) red[t] = fmaxf(red[t], red[t+s]); __syncthreads(); }
    m = red[0]; __syncthreads();
    float e[4], sum = 0.0f;
#pragma unroll
    for (int i = 0; i < 4; i++) { e[i] = expf(v[i] - m); sum += e[i]; }
    red[t] = sum; __syncthreads();
    for (int s = 128; s > 0; s >>= 1) { if (t < s) red[t] += red[t+s]; __syncthreads(); }
    float inv = 1.0f / red[0];
#pragma unroll
    for (int i = 0; i < 4; i++) p[t + i*256] = e[i] * inv;
}
__global__ void k_cheb(float* __restrict__ P) {
    int idx = blockIdx.x * blockDim.x + threadIdx.x;
    if (idx >= NN2) return;
    int r = idx >> 10, c = idx & 1023;
    P[idx] = 2.0f * P[idx] - (r == c ? 1.0f : 0.0f);
}
__global__ void k_set_x_enc(const float* __restrict__ x, int t) {
    int id = blockIdx.x * blockDim.x + threadIdx.x;
    if (id >= ROWS) return;
    int b = id >> 10, n = id & 1023;
    float xv = x[((size_t)b * Tt + t) * Nn + n];
    __half xh = __float2half_rn(xv);
    g_XT[((size_t)(b * 66) << 10) + n] = xh;
    g_F[(size_t)id << 8] = xh;
}
__global__ void k_set_xy_dec(const float* __restrict__ ycov, int t) {
    int id = blockIdx.x * blockDim.x + threadIdx.x;
    if (id >= ROWS) return;
    int b = id >> 10, n = id & 1023;
    float gv = g_go[id];
    float yv = ycov[((size_t)b * Hor + t) * Nn + n];
    __half gh = __float2half_rn(gv);
    __half yh = __float2half_rn(yv);
    g_XT[((size_t)(b * 66) << 10) + n] = gh;
    g_XT[((size_t)(b * 66 + 1) << 10) + n] = yh;
    size_t fo = (size_t)id << 8;
    g_F[fo] = gh;
    g_F[fo + 1] = yh;
}
// dec_emb must be [n, b*Ee+e] for the gram; decode id accordingly
__global__ void k_demb(const float* __restrict__ fce) {
    int idx = blockIdx.x * blockDim.x + threadIdx.x;
    if (idx >= ROWS * Ee) return;
    int id = idx / Ee, e = idx - id * Ee;
    int b = id >> 10, n = id & 1023;
    const float* hr = g_h + (size_t)id * 64;
    float s = 0.0f;
#pragma unroll
    for (int h = 0; h < 64; h++) s = fmaf(hr[h], fce[h * Ee + e], s);
    g_demb[(size_t)n * (Bb * Ee) + b * Ee + e] = s;
}
__global__ void k_init_go(const float* __restrict__ x) {
    int id = blockIdx.x * blockDim.x + threadIdx.x;
    if (id >= ROWS) return;
    int b = id >> 10, n = id & 1023;
    g_go[id] = x[((size_t)b * Tt + (Tt - 1)) * Nn + n];
}
__global__ void k_proj_out(const float* __restrict__ pw, const float* __restrict__ pb,
                           float* __restrict__ out, int t) {
    int id = blockIdx.x * blockDim.x + threadIdx.x;
    if (id >= ROWS) return;
    int b = id >> 10, n = id & 1023;
    const float* hr = g_h + (size_t)id * 64;
    float s = pb[0];
#pragma unroll
    for (int i = 0; i < 64; i++) s = fmaf(hr[i], pw[i], s);
    g_go[id] = s;
    out[((size_t)b * Hor + t) * Nn + n] = s;
}

// ---------------- orchestration ----------------
extern "C" void kernel_launch(void* const* d_in, const int* in_sizes, int n_in,
                              void* d_out, int out_size) {
    const float* x    = (const float*)d_in[0];
    const float* ycov = (const float*)d_in[1];
    const float* emb  = (const float*)d_in[2];
    const float* fce  = (const float*)d_in[3];
    const float* egw  = (const float*)d_in[4];
    const float* egb  = (const float*)d_in[5];
    const float* euw  = (const float*)d_in[6];
    const float* eub  = (const float*)d_in[7];
    const float* dgw  = (const float*)d_in[8];
    const float* dgb  = (const float*)d_in[9];
    const float* duw  = (const float*)d_in[10];
    const float* dub  = (const float*)d_in[11];
    const float* pw   = (const float*)d_in[12];
    const float* pb   = (const float*)d_in[13];
    float* out = (float*)d_out;

    float *pSe, *pSd, *pDemb, *pDembT, *pEp, *pEpT;
    __half *pSeh, *pSdh, *pX, *pF, *pWge, *pWue, *pWgd, *pWud;
    cudaGetSymbolAddress((void**)&pSe, g_S_enc);
    cudaGetSymbolAddress((void**)&pSd, g_S_dec);
    cudaGetSymbolAddress((void**)&pDemb, g_demb);
    cudaGetSymbolAddress((void**)&pDembT, g_dembT);
    cudaGetSymbolAddress((void**)&pEp, g_embpad);
    cudaGetSymbolAddress((void**)&pEpT, g_embpadT);
    cudaGetSymbolAddress((void**)&pSeh, g_Se_hi);
    cudaGetSymbolAddress((void**)&pSdh, g_Sd_hi);
    cudaGetSymbolAddress((void**)&pX, g_XT);
    cudaGetSymbolAddress((void**)&pF, g_F);
    cudaGetSymbolAddress((void**)&pWge, g_Wge);
    cudaGetSymbolAddress((void**)&pWue, g_Wue);
    cudaGetSymbolAddress((void**)&pWgd, g_Wgd);
    cudaGetSymbolAddress((void**)&pWud, g_Wud);

    constexpr int SMEM_BN128 = 3 * (128 + 128) * 72 * 2;  // 110592
    constexpr int SMEM_BN64  = 3 * (128 + 64) * 72 * 2;   // 82944
    cudaFuncSetAttribute(mma_gemm<128,0,1>, cudaFuncAttributeMaxDynamicSharedMemorySize, SMEM_BN128);
    cudaFuncSetAttribute(mma_gemm<128,1,1>, cudaFuncAttributeMaxDynamicSharedMemorySize, SMEM_BN128);
    cudaFuncSetAttribute(mma_gemm<64,2,1>,  cudaFuncAttributeMaxDynamicSharedMemorySize, SMEM_BN64);

    // ---- setup; launch index 3 (0-based) == gate MLP GEMM for ncu
    k_zero_state<<<16384, 256>>>();                                                     // 0
    k_pad_w_t<true><<<(128 * FPK + 255) / 256, 256>>>(egw, pWge, 128);                  // 1
    k_pad_w_t<true><<<(64 * FPK + 255) / 256, 256>>>(euw, pWue, 64);                    // 2
    // ncu target: real-shape gate MLP (h==0 here; writes zeros / overwritten R)
    mma_gemm<128,1,1><<<dim3(1, 512), 256, SMEM_BN128>>>(pF, pF, pF, pWge, pWge, pWge,
                                                         FPK, FPK, 256, egb);           // 3
    k_pad_emb<<<64, 256>>>(emb);
    k_transpose<<<64, 256>>>(pEp, pEpT, Nn, 16);
    sgemm32<<<dim3(16, 8), 256>>>(pEp, pEpT, pSe, Nn, Nn, 16);
    k_relu_softmax<<<Nn, 256>>>(pSe);
    sgemm32<<<dim3(16, 8), 256>>>(pSe, pSe, pSe + NN2, Nn, Nn, Nn);
    k_cheb<<<NN2 / 256, 256>>>(pSe + NN2);
    k_tohalf<<<2 * NN2 / 256, 256>>>(pSe, pSeh, (size_t)2 * NN2);
    k_pad_w_t<false><<<(128 * FPK + 255) / 256, 256>>>(dgw, pWgd, 128);
    k_pad_w_t<false><<<(64 * FPK + 255) / 256, 256>>>(duw, pWud, 64);

    // ---- encoder (all operands single fp16; diffusion segK=1024, MLP segK=256)
    for (int t = 0; t < Tt; t++) {
        k_set_x_enc<<<256, 256>>>(x, t);
        mma_gemm<128,0,1><<<dim3(33, 16), 256, SMEM_BN128>>>(pSeh, pSeh, pSeh, pX, pX, pX,
                                                             Nn, Nn, 1024, nullptr);
        mma_gemm<128,1,1><<<dim3(1, 512), 256, SMEM_BN128>>>(pF, pF, pF, pWge, pWge, pWge,
                                                             FPK, FPK, 256, egb);
        mma_gemm<128,0,1><<<dim3(33, 16), 256, SMEM_BN128>>>(pSeh, pSeh, pSeh, pX, pX, pX,
                                                             Nn, Nn, 1024, nullptr);
        mma_gemm<64,2,1><<<dim3(1, 512), 256, SMEM_BN64>>>(pF, pF, pF, pWue, pWue, pWue,
                                                           FPK, FPK, 256, eub);
    }

    // ---- decoder supports
    k_demb<<<ROWS * Ee / 256, 256>>>(fce);
    k_transpose<<<(ROWS * Ee + 255) / 256, 256>>>(pDemb, pDembT, Nn, Bb * Ee);
    sgemm32<<<dim3(16, 8), 256>>>(pDemb, pDembT, pSd, Nn, Nn, Bb * Ee);
    k_relu_softmax<<<Nn, 256>>>(pSd);
    sgemm32<<<dim3(16, 8), 256>>>(pSd, pSd, pSd + NN2, Nn, Nn, Nn);
    k_cheb<<<NN2 / 256, 256>>>(pSd + NN2);
    k_tohalf<<<2 * NN2 / 256, 256>>>(pSd, pSdh, (size_t)2 * NN2);
    k_init_go<<<256, 256>>>(x);

    // ---- decoder
    for (int t = 0; t < Hor; t++) {
        k_set_xy_dec<<<256, 256>>>(ycov, t);
        mma_gemm<128,0,1><<<dim3(33, 16), 256, SMEM_BN128>>>(pSdh, pSdh, pSdh, pX, pX, pX,
                                                             Nn, Nn, 1024, nullptr);
        mma_gemm<128,1,1><<<dim3(1, 512), 256, SMEM_BN128>>>(pF, pF, pF, pWgd, pWgd, pWgd,
                                                             FPK, FPK, 256, dgb);
        mma_gemm<128,0,1><<<dim3(33, 16), 256, SMEM_BN128>>>(pSdh, pSdh, pSdh, pX, pX, pX,
                                                             Nn, Nn, 1024, nullptr);
        mma_gemm<64,2,1><<<dim3(1, 512), 256, SMEM_BN64>>>(pF, pF, pF, pWud, pWud, pWud,
                                                           FPK, FPK, 256, dub);
        k_proj_out<<<256, 256>>>(pw, pb, out, t);
    }
}

// round 15
// speedup vs baseline: 5.7496x; 1.0539x over previous
#include <cuda_runtime.h>
#include <cuda_fp16.h>
#include <cstdint>
#include <math.h>

constexpr int Bb=64, Tt=12, Nn=1024, Ee=10, Hor=12;
constexpr int ROWS = Nn*Bb;          // 65536
constexpr int NN2  = Nn*Nn;
constexpr int FPK  = 256;            // padded K width of F (3*66=198 -> 256)
constexpr int XTC  = 66*Bb;          // 4224 = Xin^T row count (cols of Xin)
// ROW ORDER: id = b*1024 + n  (batch-major)

// ---------------- device-global scratch ----------------
__device__ __align__(1024) float g_S_enc[2*NN2];
__device__ __align__(1024) float g_S_dec[2*NN2];
__device__ __align__(1024) __half g_Rh[(size_t)ROWS*64];   // r gate, fp16
__device__ __align__(1024) float g_h [(size_t)ROWS*64];
__device__ __align__(1024) float g_go[ROWS];
__device__ __align__(1024) float g_demb [Nn*Bb*Ee];
__device__ __align__(1024) float g_dembT[Bb*Ee*Nn];
__device__ __align__(1024) float g_embpad [Nn*16];
__device__ __align__(1024) float g_embpadT[16*Nn];

__device__ __align__(1024) __half g_Se_hi[2*NN2];
__device__ __align__(1024) __half g_Sd_hi[2*NN2];
__device__ __align__(1024) __half g_XT[(size_t)XTC*Nn];          // [b*66+c][n]
__device__ __align__(1024) __half g_F[(size_t)ROWS*FPK];         // [b*1024+n][256]
__device__ __align__(1024) __half g_Wge[128*FPK];
__device__ __align__(1024) __half g_Wue[64*FPK];
__device__ __align__(1024) __half g_Wgd[128*FPK];
__device__ __align__(1024) __half g_Wud[64*FPK];

// HW MUFU.TANH (sm_75+)
__device__ __forceinline__ float tanh_fast(float x){
    float y; asm("tanh.approx.f32 %0, %1;" : "=f"(y) : "f"(x)); return y;
}
__device__ __forceinline__ float sigmoid_fast(float x){
    return fmaf(0.5f, tanh_fast(0.5f * x), 0.5f);
}

__device__ __forceinline__ uint32_t smem_u32(const void* p){
    uint32_t a;
    asm("{ .reg .u64 t; cvta.to.shared.u64 t, %1; cvt.u32.u64 %0, t; }" : "=r"(a) : "l"(p));
    return a;
}
__device__ __forceinline__ void cp_async16(uint32_t dst, const void* src){
    asm volatile("cp.async.cg.shared.global [%0], [%1], 16;" :: "r"(dst), "l"(src));
}
__device__ __forceinline__ void cp_commit(){ asm volatile("cp.async.commit_group;"); }
template <int N>
__device__ __forceinline__ void cp_wait(){ asm volatile("cp.async.wait_group %0;" :: "n"(N)); }

__device__ __forceinline__ void ldsm_x4(uint32_t* r, uint32_t addr){
    asm volatile("ldmatrix.sync.aligned.m8n8.x4.shared.b16 {%0,%1,%2,%3}, [%4];"
        : "=r"(r[0]), "=r"(r[1]), "=r"(r[2]), "=r"(r[3]) : "r"(addr));
}
__device__ __forceinline__ void mma16816(float* c, const uint32_t* a, const uint32_t* b){
    asm volatile("mma.sync.aligned.m16n8k16.row.col.f32.f16.f16.f32 "
        "{%0,%1,%2,%3}, {%4,%5,%6,%7}, {%8,%9}, {%0,%1,%2,%3};"
        : "+f"(c[0]), "+f"(c[1]), "+f"(c[2]), "+f"(c[3])
        : "r"(a[0]), "r"(a[1]), "r"(a[2]), "r"(a[3]), "r"(b[0]), "r"(b[1]));
}

// ---------------- fp16 HMMA GEMM -----------------------
// D[M rows, N=BN per block] = A(M x segK) @ B^T, fp32 accumulate.
// A rows = output rows (lda elems); B rows = output COLUMNS, K-major (ldb).
// BM=128, BK=64, 256 threads (8 warps, 4m x 2n). Row id = b*1024 + n.
// NSTG=3: classic 3-stage pipeline (diffusion, KT=16).
// NSTG=2: 2-stage + cp.async PREFETCH of epilogue operands (h tile fp32 32KB,
//         R tile fp16 16KB) into smem, hidden under the mainloop (MLPs, KT=4).
// EPI 0: diffusion -> fp16 scatter into g_F
// EPI 1: gate: z=sig(+bias), c<64 -> z*h into g_XT + g_F; c>=64 -> g_Rh
// EPI 2: update: hc=tanh(+bias); hn = r*h + (1-r)*hc -> g_h, g_XT, g_F
template <int BN, int EPI, int NSTG>
__global__ void __launch_bounds__(256, 2) mma_gemm(
    const __half* __restrict__ A, const __half* __restrict__ B,
    int lda, int ldb, int segK, const float* __restrict__ bias)
{
    constexpr int BM = 128, LDS = 72;      // 64 + 8 pad (half elems)
    constexpr int NT = BN / 16;
    constexpr uint32_t STG_BYTES = (uint32_t)(BM + BN) * LDS * 2u;
    extern __shared__ __align__(16) char sm[];
    const uint32_t sm0 = smem_u32(sm);

    const int tid = threadIdx.x, lane = tid & 31, wid = tid >> 5;
    const int wm = wid >> 1, wn = wid & 1;
    const int m0 = blockIdx.y * BM, n0 = blockIdx.x * BN;
    const int KT = segK >> 6;

    float acc[2][NT][4];
#pragma unroll
    for (int i = 0; i < 2; i++)
#pragma unroll
        for (int j = 0; j < NT; j++)
#pragma unroll
            for (int e = 0; e < 4; e++) acc[i][j][e] = 0.0f;

    const uint32_t aOff = (((uint32_t)(wm*32 + (lane & 15))) * LDS + ((lane >> 4) << 3)) * 2u;
    const uint32_t bOff = (uint32_t)BM * LDS * 2u
        + (((uint32_t)(wn*(BN/2) + (lane & 7) + ((lane >> 4) << 3))) * LDS
           + (((lane >> 3) & 1) << 3)) * 2u;

    auto load_tile = [&](int kt, int stg) {
        const uint32_t sA = sm0 + (uint32_t)stg * STG_BYTES;
        const uint32_t sB = sA + (uint32_t)BM * LDS * 2u;
        const char* Ag = (const char*)(A + (size_t)m0 * lda + kt * 64);
        const char* Bg = (const char*)(B + (size_t)n0 * ldb + kt * 64);
#pragma unroll
        for (int it = 0; it < 4; it++) {
            int id = (it << 8) + tid;
            int r = id >> 3, c = id & 7;
            cp_async16(sA + (uint32_t)r*144u + (uint32_t)c*16u,
                       Ag + (size_t)r * ((size_t)lda*2) + c*16);
        }
#pragma unroll
        for (int it = 0; it < BN/32; it++) {
            int id = (it << 8) + tid;
            int r = id >> 3, c = id & 7;
            cp_async16(sB + (uint32_t)r*144u + (uint32_t)c*16u,
                       Bg + (size_t)r * ((size_t)ldb*2) + c*16);
        }
        cp_commit();
    };

    auto compute = [&](int stg) {
        const uint32_t sbase = sm0 + (uint32_t)stg * STG_BYTES;
        const uint32_t aBase = sbase + aOff;
        const uint32_t bBase = sbase + bOff;
#pragma unroll
        for (int ks = 0; ks < 4; ks++) {
            uint32_t a[2][4];
            ldsm_x4(a[0], aBase + (uint32_t)ks*32u);
            ldsm_x4(a[1], aBase + 16u*LDS*2u + (uint32_t)ks*32u);
            uint32_t b[NT/2][4];
#pragma unroll
            for (int p = 0; p < NT/2; p++)
                ldsm_x4(b[p], bBase + (uint32_t)p*16u*LDS*2u + (uint32_t)ks*32u);
#pragma unroll
            for (int mt = 0; mt < 2; mt++)
#pragma unroll
                for (int nt = 0; nt < NT; nt++)
                    mma16816(acc[mt][nt], a[mt], &b[nt >> 1][(nt & 1) * 2]);
        }
    };

    if (NSTG == 3) {
        load_tile(0, 0);
        if (KT > 1) load_tile(1, 1);
        int stg = 0;
        for (int kt = 0; kt < KT; kt++) {
            if (kt + 1 < KT) cp_wait<1>(); else cp_wait<0>();
            __syncthreads();
            if (kt + 2 < KT) load_tile(kt + 2, (kt + 2) % 3);
            compute(stg);
            if (++stg == 3) stg = 0;
        }
    } else {
        // prefetch epilogue operands under the mainloop
        if (EPI >= 1) {
#pragma unroll
            for (int it = 0; it < 8; it++) {
                int idx = (it << 8) + tid;
                cp_async16(sm0 + 2u*STG_BYTES + (uint32_t)idx*16u,
                           (const char*)g_h + (size_t)m0*256 + (size_t)idx*16);
            }
            if (EPI == 2) {
#pragma unroll
                for (int it = 0; it < 4; it++) {
                    int idx = (it << 8) + tid;
                    cp_async16(sm0 + 2u*STG_BYTES + 32768u + (uint32_t)idx*16u,
                               (const char*)g_Rh + (size_t)m0*128 + (size_t)idx*16);
                }
            }
            cp_commit();
        }
        load_tile(0, 0);
        for (int kt = 0; kt < KT; kt++) {
            cp_wait<0>();
            __syncthreads();
            if (kt + 1 < KT) load_tile(kt + 1, (kt + 1) & 1);
            compute(kt & 1);
        }
    }

    // ---------------- epilogue (paired half2/float2; batch-major rows) -------
    const float*  s_hf = reinterpret_cast<const float*>(sm + 2u*STG_BYTES);
    const __half* s_rh = reinterpret_cast<const __half*>(sm + 2u*STG_BYTES + 32768u);
    const int rbase = m0 + wm*32 + (lane >> 2);
    const int cb = n0 + wn*(BN/2) + ((lane & 3) << 1);   // even
#pragma unroll
    for (int mt = 0; mt < 2; mt++) {
#pragma unroll
        for (int nt = 0; nt < NT; nt++) {
#pragma unroll
            for (int ep = 0; ep < 2; ep++) {
                const int row = rbase + mt*16 + ep*8;
                const int lrow = row - m0;
                const int col0 = cb + nt*8;              // even
                const float v0 = acc[mt][nt][ep*2 + 0];
                const float v1 = acc[mt][nt][ep*2 + 1];
                if (EPI == 0) {
                    const int kk = row >> 10, n = row & 1023;
                    const int b = col0 / 66, c = col0 - b * 66;
                    const size_t off = (size_t)((b << 10) + n) * FPK + (kk + 1) * 66 + c;
                    *reinterpret_cast<__half2*>(&g_F[off]) = __floats2half2_rn(v0, v1);
                } else if (EPI == 1) {
                    const int id = row, b = row >> 10, n = row & 1023;
                    if (col0 < 64) {                      // warp-uniform (wn==0)
                        const float2 hp = *reinterpret_cast<const float2*>(
                            &s_hf[lrow * 64 + col0]);
                        const float zh0 = sigmoid_fast(v0 + bias[col0])     * hp.x;
                        const float zh1 = sigmoid_fast(v1 + bias[col0 + 1]) * hp.y;
                        const __half h0 = __float2half_rn(zh0);
                        const __half h1 = __float2half_rn(zh1);
                        g_XT[((size_t)(b * 66 + 2 + col0) << 10) + n] = h0;
                        g_XT[((size_t)(b * 66 + 3 + col0) << 10) + n] = h1;
                        *reinterpret_cast<__half2*>(&g_F[((size_t)id << 8) + 2 + col0]) =
                            __halves2half2(h0, h1);
                    } else {                              // warp-uniform (wn==1)
                        const float r0 = sigmoid_fast(v0 + bias[col0]);
                        const float r1 = sigmoid_fast(v1 + bias[col0 + 1]);
                        *reinterpret_cast<__half2*>(&g_Rh[(size_t)id * 64 + (col0 - 64)]) =
                            __floats2half2_rn(r0, r1);
                    }
                } else {
                    const int id = row, b = row >> 10, n = row & 1023;
                    const float2 hp = *reinterpret_cast<const float2*>(
                        &s_hf[lrow * 64 + col0]);
                    const __half2 rh = *reinterpret_cast<const __half2*>(
                        &s_rh[lrow * 64 + col0]);
                    const float2 rp = __half22float2(rh);
                    const float hc0 = tanh_fast(v0 + bias[col0]);
                    const float hc1 = tanh_fast(v1 + bias[col0 + 1]);
                    const float hn0 = rp.x * hp.x + (1.0f - rp.x) * hc0;
                    const float hn1 = rp.y * hp.y + (1.0f - rp.y) * hc1;
                    *reinterpret_cast<float2*>(&g_h[(size_t)id * 64 + col0]) =
                        make_float2(hn0, hn1);
                    const __half h0 = __float2half_rn(hn0);
                    const __half h1 = __float2half_rn(hn1);
                    g_XT[((size_t)(b * 66 + 2 + col0) << 10) + n] = h0;
                    g_XT[((size_t)(b * 66 + 3 + col0) << 10) + n] = h1;
                    *reinterpret_cast<__half2*>(&g_F[((size_t)id << 8) + 2 + col0]) =
                        __halves2half2(h0, h1);
                }
            }
        }
    }
}

// ---------------- fp32 SGEMM (setup only) ----------------
__global__ void __launch_bounds__(256) sgemm32(
    const float* __restrict__ A, const float* __restrict__ B,
    float* __restrict__ C, int M, int N, int K)
{
    constexpr int BM = 128, BN = 64, BK = 16;
    __shared__ __align__(16) float As_[BK][BM];
    __shared__ __align__(16) float Bs_[BK][BN];
    const int tid = threadIdx.x;
    const int tx = tid & 15, ty = tid >> 4;
    const int m0 = blockIdx.y * BM, n0 = blockIdx.x * BN;
    float acc[8][4];
#pragma unroll
    for (int i = 0; i < 8; i++)
#pragma unroll
        for (int jj = 0; jj < 4; jj++) acc[i][jj] = 0.0f;
    const int arow0 = tid >> 2, acol0 = (tid & 3) * 4;
    const int brow = tid >> 4, bcol = (tid & 15) * 4;
    for (int kt = 0; kt < K; kt += BK) {
#pragma unroll
        for (int i = 0; i < 2; i++) {
            int r = arow0 + i * 64;
            float4 v = *reinterpret_cast<const float4*>(A + (size_t)(m0 + r) * K + kt + acol0);
            As_[acol0+0][r]=v.x; As_[acol0+1][r]=v.y; As_[acol0+2][r]=v.z; As_[acol0+3][r]=v.w;
        }
        float4 bv = *reinterpret_cast<const float4*>(B + (size_t)(kt + brow) * N + n0 + bcol);
        *reinterpret_cast<float4*>(&Bs_[brow][bcol]) = bv;
        __syncthreads();
#pragma unroll
        for (int k = 0; k < BK; k++) {
            float4 a0 = *reinterpret_cast<const float4*>(&As_[k][ty*8]);
            float4 a1 = *reinterpret_cast<const float4*>(&As_[k][ty*8+4]);
            float4 b0 = *reinterpret_cast<const float4*>(&Bs_[k][tx*4]);
            float am[8]={a0.x,a0.y,a0.z,a0.w,a1.x,a1.y,a1.z,a1.w};
            float bn[4]={b0.x,b0.y,b0.z,b0.w};
#pragma unroll
            for (int i = 0; i < 8; i++)
#pragma unroll
                for (int jj = 0; jj < 4; jj++) acc[i][jj] = fmaf(am[i], bn[jj], acc[i][jj]);
        }
        __syncthreads();
    }
#pragma unroll
    for (int i = 0; i < 8; i++) {
        float4 v = make_float4(acc[i][0], acc[i][1], acc[i][2], acc[i][3]);
        *reinterpret_cast<float4*>(C + (size_t)(m0 + ty*8 + i) * N + n0 + tx*4) = v;
    }
}

// ---------------- elementwise helpers (id = b*1024 + n) ----------------
__global__ void k_zero_state() {
    int idx = blockIdx.x * blockDim.x + threadIdx.x;
    if (idx >= ROWS * 64) return;
    int id = idx >> 6, i = idx & 63;
    int b = id >> 10, n = id & 1023;
    g_h[idx] = 0.0f;
    g_XT[((size_t)(b * 66 + 2 + i) << 10) + n] = __float2half_rn(0.0f);
    g_F[((size_t)id << 8) + 2 + i] = __float2half_rn(0.0f);
}
__global__ void k_tohalf(const float* __restrict__ s, __half* __restrict__ hi, size_t n) {
    size_t i = (size_t)blockIdx.x * blockDim.x + threadIdx.x;
    if (i >= n) return;
    hi[i] = __float2half_rn(s[i]);
}
__global__ void k_pad_emb(const float* __restrict__ emb) {
    int idx = blockIdx.x * blockDim.x + threadIdx.x;
    if (idx >= Nn * 16) return;
    int n = idx >> 4, j = idx & 15;
    g_embpad[idx] = (j < Ee) ? emb[n * Ee + j] : 0.0f;
}
__global__ void k_transpose(const float* __restrict__ in, float* __restrict__ out,
                            int R, int C) {
    int idx = blockIdx.x * blockDim.x + threadIdx.x;
    if (idx >= R * C) return;
    int r = idx / C, c = idx - r * C;
    out[c * R + r] = in[idx];
}
template <bool ENC>
__global__ void k_pad_w_t(const float* __restrict__ src, __half* __restrict__ dst,
                          int nout) {
    int idx = blockIdx.x * blockDim.x + threadIdx.x;
    if (idx >= nout * FPK) return;
    int n = idx >> 8, f = idx & 255;
    float v = 0.0f;
    if (f < 198) {
        int k = f / 66, c = f - k * 66;
        if (ENC) {
            if (c == 0) v = src[(k * 65) * nout + n];
            else if (c >= 2) v = src[(k * 65 + c - 1) * nout + n];
        } else {
            v = src[f * nout + n];
        }
    }
    dst[idx] = __float2half_rn(v);
}
__global__ void k_relu_softmax(float* __restrict__ S) {
    int row = blockIdx.x;
    float* p = S + (size_t)row * Nn;
    int t = threadIdx.x;
    float v[4];
#pragma unroll
    for (int i = 0; i < 4; i++) { float x = p[t + i*256]; v[i] = x > 0.0f ? x : 0.0f; }
    __shared__ float red[256];
    float m = fmaxf(fmaxf(v[0], v[1]), fmaxf(v[2], v[3]));
    red[t] = m; __syncthreads();
    for (int s = 128; s > 0; s >>= 1) { if (t < s) red[t] = fmaxf(red[t], red[t+s]); __syncthreads(); }
    m = red[0]; __syncthreads();
    float e[4], sum = 0.0f;
#pragma unroll
    for (int i = 0; i < 4; i++) { e[i] = expf(v[i] - m); sum += e[i]; }
    red[t] = sum; __syncthreads();
    for (int s = 128; s > 0; s >>= 1) { if (t < s) red[t] += red[t+s]; __syncthreads(); }
    float inv = 1.0f / red[0];
#pragma unroll
    for (int i = 0; i < 4; i++) p[t + i*256] = e[i] * inv;
}
__global__ void k_cheb(float* __restrict__ P) {
    int idx = blockIdx.x * blockDim.x + threadIdx.x;
    if (idx >= NN2) return;
    int r = idx >> 10, c = idx & 1023;
    P[idx] = 2.0f * P[idx] - (r == c ? 1.0f : 0.0f);
}
__global__ void k_set_x_enc(const float* __restrict__ x, int t) {
    int id = blockIdx.x * blockDim.x + threadIdx.x;
    if (id >= ROWS) return;
    int b = id >> 10, n = id & 1023;
    float xv = x[((size_t)b * Tt + t) * Nn + n];
    __half xh = __float2half_rn(xv);
    g_XT[((size_t)(b * 66) << 10) + n] = xh;
    g_F[(size_t)id << 8] = xh;
}
__global__ void k_set_xy_dec(const float* __restrict__ ycov, int t) {
    int id = blockIdx.x * blockDim.x + threadIdx.x;
    if (id >= ROWS) return;
    int b = id >> 10, n = id & 1023;
    float gv = g_go[id];
    float yv = ycov[((size_t)b * Hor + t) * Nn + n];
    __half gh = __float2half_rn(gv);
    __half yh = __float2half_rn(yv);
    g_XT[((size_t)(b * 66) << 10) + n] = gh;
    g_XT[((size_t)(b * 66 + 1) << 10) + n] = yh;
    size_t fo = (size_t)id << 8;
    g_F[fo] = gh;
    g_F[fo + 1] = yh;
}
__global__ void k_demb(const float* __restrict__ fce) {
    int idx = blockIdx.x * blockDim.x + threadIdx.x;
    if (idx >= ROWS * Ee) return;
    int id = idx / Ee, e = idx - id * Ee;
    int b = id >> 10, n = id & 1023;
    const float* hr = g_h + (size_t)id * 64;
    float s = 0.0f;
#pragma unroll
    for (int h = 0; h < 64; h++) s = fmaf(hr[h], fce[h * Ee + e], s);
    g_demb[(size_t)n * (Bb * Ee) + b * Ee + e] = s;
}
__global__ void k_init_go(const float* __restrict__ x) {
    int id = blockIdx.x * blockDim.x + threadIdx.x;
    if (id >= ROWS) return;
    int b = id >> 10, n = id & 1023;
    g_go[id] = x[((size_t)b * Tt + (Tt - 1)) * Nn + n];
}
__global__ void k_proj_out(const float* __restrict__ pw, const float* __restrict__ pb,
                           float* __restrict__ out, int t) {
    int id = blockIdx.x * blockDim.x + threadIdx.x;
    if (id >= ROWS) return;
    int b = id >> 10, n = id & 1023;
    const float* hr = g_h + (size_t)id * 64;
    float s = pb[0];
#pragma unroll
    for (int i = 0; i < 64; i++) s = fmaf(hr[i], pw[i], s);
    g_go[id] = s;
    out[((size_t)b * Hor + t) * Nn + n] = s;
}

// ---------------- orchestration ----------------
extern "C" void kernel_launch(void* const* d_in, const int* in_sizes, int n_in,
                              void* d_out, int out_size) {
    const float* x    = (const float*)d_in[0];
    const float* ycov = (const float*)d_in[1];
    const float* emb  = (const float*)d_in[2];
    const float* fce  = (const float*)d_in[3];
    const float* egw  = (const float*)d_in[4];
    const float* egb  = (const float*)d_in[5];
    const float* euw  = (const float*)d_in[6];
    const float* eub  = (const float*)d_in[7];
    const float* dgw  = (const float*)d_in[8];
    const float* dgb  = (const float*)d_in[9];
    const float* duw  = (const float*)d_in[10];
    const float* dub  = (const float*)d_in[11];
    const float* pw   = (const float*)d_in[12];
    const float* pb   = (const float*)d_in[13];
    float* out = (float*)d_out;

    float *pSe, *pSd, *pDemb, *pDembT, *pEp, *pEpT;
    __half *pSeh, *pSdh, *pX, *pF, *pWge, *pWue, *pWgd, *pWud;
    cudaGetSymbolAddress((void**)&pSe, g_S_enc);
    cudaGetSymbolAddress((void**)&pSd, g_S_dec);
    cudaGetSymbolAddress((void**)&pDemb, g_demb);
    cudaGetSymbolAddress((void**)&pDembT, g_dembT);
    cudaGetSymbolAddress((void**)&pEp, g_embpad);
    cudaGetSymbolAddress((void**)&pEpT, g_embpadT);
    cudaGetSymbolAddress((void**)&pSeh, g_Se_hi);
    cudaGetSymbolAddress((void**)&pSdh, g_Sd_hi);
    cudaGetSymbolAddress((void**)&pX, g_XT);
    cudaGetSymbolAddress((void**)&pF, g_F);
    cudaGetSymbolAddress((void**)&pWge, g_Wge);
    cudaGetSymbolAddress((void**)&pWue, g_Wue);
    cudaGetSymbolAddress((void**)&pWgd, g_Wgd);
    cudaGetSymbolAddress((void**)&pWud, g_Wud);

    constexpr int SMEM_DIFF = 3 * (128 + 128) * 72 * 2;                 // 110592
    constexpr int SMEM_GATE = 2 * (128 + 128) * 72 * 2 + 32768;         // 106496
    constexpr int SMEM_UPD  = 2 * (128 + 64) * 72 * 2 + 32768 + 16384;  // 104448
    cudaFuncSetAttribute(mma_gemm<128,0,3>, cudaFuncAttributeMaxDynamicSharedMemorySize, SMEM_DIFF);
    cudaFuncSetAttribute(mma_gemm<128,1,2>, cudaFuncAttributeMaxDynamicSharedMemorySize, SMEM_GATE);
    cudaFuncSetAttribute(mma_gemm<64,2,2>,  cudaFuncAttributeMaxDynamicSharedMemorySize, SMEM_UPD);

    // ---- setup; launch index 3 (0-based) == gate MLP GEMM for ncu
    k_zero_state<<<16384, 256>>>();                                                     // 0
    k_pad_w_t<true><<<(128 * FPK + 255) / 256, 256>>>(egw, pWge, 128);                  // 1
    k_pad_w_t<true><<<(64 * FPK + 255) / 256, 256>>>(euw, pWue, 64);                    // 2
    // ncu target: real-shape gate MLP (h==0 here; writes zeros / overwritten Rh)
    mma_gemm<128,1,2><<<dim3(1, 512), 256, SMEM_GATE>>>(pF, pWge, FPK, FPK, 256, egb);  // 3
    k_pad_emb<<<64, 256>>>(emb);
    k_transpose<<<64, 256>>>(pEp, pEpT, Nn, 16);
    sgemm32<<<dim3(16, 8), 256>>>(pEp, pEpT, pSe, Nn, Nn, 16);
    k_relu_softmax<<<Nn, 256>>>(pSe);
    sgemm32<<<dim3(16, 8), 256>>>(pSe, pSe, pSe + NN2, Nn, Nn, Nn);
    k_cheb<<<NN2 / 256, 256>>>(pSe + NN2);
    k_tohalf<<<2 * NN2 / 256, 256>>>(pSe, pSeh, (size_t)2 * NN2);
    k_pad_w_t<false><<<(128 * FPK + 255) / 256, 256>>>(dgw, pWgd, 128);
    k_pad_w_t<false><<<(64 * FPK + 255) / 256, 256>>>(duw, pWud, 64);

    // ---- encoder
    for (int t = 0; t < Tt; t++) {
        k_set_x_enc<<<256, 256>>>(x, t);
        mma_gemm<128,0,3><<<dim3(33, 16), 256, SMEM_DIFF>>>(pSeh, pX, Nn, Nn, 1024, nullptr);
        mma_gemm<128,1,2><<<dim3(1, 512), 256, SMEM_GATE>>>(pF, pWge, FPK, FPK, 256, egb);
        mma_gemm<128,0,3><<<dim3(33, 16), 256, SMEM_DIFF>>>(pSeh, pX, Nn, Nn, 1024, nullptr);
        mma_gemm<64,2,2><<<dim3(1, 512), 256, SMEM_UPD>>>(pF, pWue, FPK, FPK, 256, eub);
    }

    // ---- decoder supports
    k_demb<<<ROWS * Ee / 256, 256>>>(fce);
    k_transpose<<<(ROWS * Ee + 255) / 256, 256>>>(pDemb, pDembT, Nn, Bb * Ee);
    sgemm32<<<dim3(16, 8), 256>>>(pDemb, pDembT, pSd, Nn, Nn, Bb * Ee);
    k_relu_softmax<<<Nn, 256>>>(pSd);
    sgemm32<<<dim3(16, 8), 256>>>(pSd, pSd, pSd + NN2, Nn, Nn, Nn);
    k_cheb<<<NN2 / 256, 256>>>(pSd + NN2);
    k_tohalf<<<2 * NN2 / 256, 256>>>(pSd, pSdh, (size_t)2 * NN2);
    k_init_go<<<256, 256>>>(x);

    // ---- decoder
    for (int t = 0; t < Hor; t++) {
        k_set_xy_dec<<<256, 256>>>(ycov, t);
        mma_gemm<128,0,3><<<dim3(33, 16), 256, SMEM_DIFF>>>(pSdh, pX, Nn, Nn, 1024, nullptr);
        mma_gemm<128,1,2><<<dim3(1, 512), 256, SMEM_GATE>>>(pF, pWgd, FPK, FPK, 256, dgb);
        mma_gemm<128,0,3><<<dim3(33, 16), 256, SMEM_DIFF>>>(pSdh, pX, Nn, Nn, 1024, nullptr);
        mma_gemm<64,2,2><<<dim3(1, 512), 256, SMEM_UPD>>>(pF, pWud, FPK, FPK, 256, dub);
        k_proj_out<<<256, 256>>>(pw, pb, out, t);
    }
}